// round 3
// baseline (speedup 1.0000x reference)
#include <cuda_runtime.h>

#define Bb   128
#define Ss   416
#define Nn   32
#define Mm   384
#define Dd   256
#define Hh   8
#define Ee   32
#define Oo   256
#define BSs  (Bb*Ss)          // 53248

typedef unsigned long long ull;

// -------- scratch (static device globals; no runtime allocation) ----------
__device__ float g_xln[BSs*Dd];
__device__ float g_q  [Bb*Hh*Ss*Ee];
__device__ float g_k  [Bb*Hh*Ss*Ee];
__device__ float g_v  [Bb*Hh*Ss*Ee];
__device__ float g_g  [Bb*Hh*Ss*Ee];
__device__ float g_ao [BSs*Oo];

// -------- packed fp32x2 helpers (FFMA2) -----------------------------------
__device__ __forceinline__ ull pk2(float lo, float hi) {
    ull r; asm("mov.b64 %0, {%1, %2};" : "=l"(r) : "f"(lo), "f"(hi)); return r;
}
__device__ __forceinline__ void upk2(ull v, float& lo, float& hi) {
    asm("mov.b64 {%0, %1}, %2;" : "=f"(lo), "=f"(hi) : "l"(v));
}
__device__ __forceinline__ void ffma2(ull& d, ull a, ull b) {
    asm("fma.rn.f32x2 %0, %1, %2, %0;" : "+l"(d) : "l"(a), "l"(b));
}

__device__ __forceinline__ float warpSum(float v) {
#pragma unroll
    for (int o = 16; o; o >>= 1) v += __shfl_xor_sync(0xffffffffu, v, o);
    return v;
}
__device__ __forceinline__ float warpMax(float v) {
#pragma unroll
    for (int o = 16; o; o >>= 1) v = fmaxf(v, __shfl_xor_sync(0xffffffffu, v, o));
    return v;
}

// =================== Kernel 1: LayerNorm over D=256 =======================
__global__ void k_ln1(const float* __restrict__ x,
                      const float* __restrict__ gam,
                      const float* __restrict__ bet) {
    int row = blockIdx.x;
    int t = threadIdx.x;
    int w = t >> 5, lane = t & 31;
    __shared__ float red[8];

    float v = x[(size_t)row * Dd + t];
    float s = warpSum(v);
    if (lane == 0) red[w] = s;
    __syncthreads();
    float mu = 0.f;
#pragma unroll
    for (int i = 0; i < 8; i++) mu += red[i];
    mu *= (1.f / 256.f);
    float d = v - mu;
    __syncthreads();
    s = warpSum(d * d);
    if (lane == 0) red[w] = s;
    __syncthreads();
    float var = 0.f;
#pragma unroll
    for (int i = 0; i < 8; i++) var += red[i];
    var *= (1.f / 256.f);
    g_xln[(size_t)row * Dd + t] = d * rsqrtf(var + 1e-6f) * gam[t] + bet[t];
}

// ============ Kernel 2: QKVG projections, 128x128 tile, FFMA2 =============
__global__ void __launch_bounds__(256, 2)
k_qkvg(const float* __restrict__ qp, const float* __restrict__ kp,
       const float* __restrict__ vp, const float* __restrict__ gp) {
    __shared__ float As[16 * 132];   // [k][m]
    __shared__ float Bs[16 * 132];   // [k][n]

    int tid  = threadIdx.x;
    int warp = tid >> 5, lane = tid & 31;
    int cx = (warp & 1) * 8 + (lane & 7);
    int cy = (warp >> 1) * 4 + (lane >> 3);

    int m0 = blockIdx.x * 128;
    int n0 = blockIdx.y * 128;
    int proj = n0 >> 8;
    const float* W = (proj == 0) ? qp : (proj == 1) ? kp : (proj == 2) ? vp : gp;
    float*      Og = (proj == 0) ? g_q : (proj == 1) ? g_k : (proj == 2) ? g_v : g_g;
    int nin = n0 & 255;

    ull acc[8][4];
#pragma unroll
    for (int i = 0; i < 8; i++)
#pragma unroll
        for (int j = 0; j < 4; j++) acc[i][j] = 0ull;

    for (int k0 = 0; k0 < 256; k0 += 16) {
#pragma unroll
        for (int it = 0; it < 2; it++) {
            int i = tid + it * 256;
            int m = i >> 2, kq = i & 3;
            float4 a4 = *(const float4*)&g_xln[(size_t)(m0 + m) * Dd + k0 + kq * 4];
            As[(kq * 4 + 0) * 132 + m] = a4.x;
            As[(kq * 4 + 1) * 132 + m] = a4.y;
            As[(kq * 4 + 2) * 132 + m] = a4.z;
            As[(kq * 4 + 3) * 132 + m] = a4.w;
        }
#pragma unroll
        for (int it = 0; it < 2; it++) {
            int i = tid + it * 256;
            int nq = i & 31, kk = i >> 5;
            int n = nin + nq * 4;
            int h = n >> 5, e = n & 31;
            float4 b4 = *(const float4*)&W[h * 8192 + (k0 + kk) * 32 + e];
            *(float4*)&Bs[kk * 132 + nq * 4] = b4;
        }
        __syncthreads();
#pragma unroll 4
        for (int kk = 0; kk < 16; kk++) {
            float a[8];
            *(float4*)&a[0] = *(const float4*)&As[kk * 132 + cy * 8];
            *(float4*)&a[4] = *(const float4*)&As[kk * 132 + cy * 8 + 4];
            ulonglong2 b01 = *(const ulonglong2*)&Bs[kk * 132 + cx * 8];
            ulonglong2 b23 = *(const ulonglong2*)&Bs[kk * 132 + cx * 8 + 4];
#pragma unroll
            for (int i = 0; i < 8; i++) {
                ull pa = pk2(a[i], a[i]);
                ffma2(acc[i][0], pa, b01.x);
                ffma2(acc[i][1], pa, b01.y);
                ffma2(acc[i][2], pa, b23.x);
                ffma2(acc[i][3], pa, b23.y);
            }
        }
        __syncthreads();
    }

#pragma unroll
    for (int i = 0; i < 8; i++) {
        int m = m0 + cy * 8 + i;
        int b = m / Ss;
        int s = m - b * Ss;
        float c0, c1, c2, c3, c4, c5, c6, c7;
        upk2(acc[i][0], c0, c1); upk2(acc[i][1], c2, c3);
        upk2(acc[i][2], c4, c5); upk2(acc[i][3], c6, c7);
        float v03[4] = {c0, c1, c2, c3};
        float v47[4] = {c4, c5, c6, c7};
#pragma unroll
        for (int jg = 0; jg < 2; jg++) {
            int n = nin + cx * 8 + jg * 4;
            int h = n >> 5, e = n & 31;
            const float* src = jg ? v47 : v03;
            float4 v4 = make_float4(src[0], src[1], src[2], src[3]);
            *(float4*)&Og[(((size_t)(b * Hh + h)) * Ss + s) * Ee + e] = v4;
        }
    }
}

// ============ Kernel 3: fused attention, one block per (b,h), FFMA2 ========
// smem: kT[32*420] | v[416*33] | att[32*416] | q2[2048] | c[416]
__global__ void k_attn(const float* __restrict__ pmask,
                       const float* __restrict__ mmask) {
    extern __shared__ float sm[];
    float* kT   = sm;                        // e-major: kT[e*420 + y]
    float* v_sh = kT + 32 * 420;             // v_sh[y*33 + e]
    float* att  = v_sh + 416 * 33;           // att[x*416 + y]
    float* q2   = att + 32 * 416;            // duplicated: q2[x*64 + 2e] = (q,q)
    float* c_sh = q2 + 2048;                 // 416

    int tid = threadIdx.x;
    int bh = blockIdx.x;
    int h = bh & 7, b = bh >> 3;
    size_t baseBH = (size_t)(b * Hh + h) * Ss;

    const float* kb = g_k + baseBH * Ee;
    for (int i = tid; i < Ss * Ee; i += 256) {
        int y = i >> 5, e = i & 31;
        kT[e * 420 + y] = kb[i];
    }
    const float* vb = g_v + baseBH * Ee;
    for (int i = tid; i < Ss * Ee; i += 256) {
        int y = i >> 5, e = i & 31;
        v_sh[y * 33 + e] = vb[i];
    }
    for (int i = tid; i < Ss; i += 256) {
        float val = (i < Nn) ? pmask[b * Nn + i] : mmask[b * Mm + (i - Nn)];
        c_sh[i] = (val == -2.0f) ? 0.f : 1.f;
    }
    __syncthreads();

    const float scale = 0.1767766952966369f;   // 1/sqrt(32)
    int w = tid >> 5;
    int lane = tid & 31;
    int xg = w;

    for (int tile = 0; tile < 13; tile++) {
        int x0 = tile * 32;
        const float* qb = g_q + (baseBH + x0) * Ee;
        for (int i = tid; i < 1024; i += 256) {
            float qv = qb[i];
            *(ull*)&q2[i * 2] = pk2(qv, qv);
        }
        __syncthreads();

        // ---- scores: y-pair accumulators ----
        bool xIsP = (tile == 0);
        for (int yq = lane; yq < 104; yq += 32) {
            int y0 = yq << 2;
            ull acc2[4][2];
#pragma unroll
            for (int i = 0; i < 4; i++) { acc2[i][0] = 0ull; acc2[i][1] = 0ull; }
#pragma unroll 8
            for (int e = 0; e < 32; e++) {
                ulonglong2 kv = *(const ulonglong2*)&kT[e * 420 + y0];
#pragma unroll
                for (int i = 0; i < 4; i++) {
                    ull pa = *(const ull*)&q2[(xg * 4 + i) * 64 + 2 * e];
                    ffma2(acc2[i][0], pa, kv.x);
                    ffma2(acc2[i][1], pa, kv.y);
                }
            }
            float4 cy = *(const float4*)&c_sh[y0];
            bool cross = (xIsP != (y0 < Nn));
#pragma unroll
            for (int i = 0; i < 4; i++) {
                float s0, s1, s2, s3;
                upk2(acc2[i][0], s0, s1);
                upk2(acc2[i][1], s2, s3);
                float cxi = c_sh[x0 + xg * 4 + i];
                float mx_ = cross ? cxi * cy.x : 0.f;
                float my_ = cross ? cxi * cy.y : 0.f;
                float mz_ = cross ? cxi * cy.z : 0.f;
                float mw_ = cross ? cxi * cy.w : 0.f;
                float4 r;
                r.x = s0 * scale + (1.f - mx_) * (-1.0e9f);
                r.y = s1 * scale + (1.f - my_) * (-1.0e9f);
                r.z = s2 * scale + (1.f - mz_) * (-1.0e9f);
                r.w = s3 * scale + (1.f - mw_) * (-1.0e9f);
                *(float4*)&att[(xg * 4 + i) * 416 + y0] = r;
            }
        }
        __syncthreads();

        // ---- softmax: warp w handles rows w, w+8, w+16, w+24 ----
#pragma unroll
        for (int rr = 0; rr < 4; rr++) {
            int xr = w + rr * 8;
            float* row = att + xr * 416;
            float mx = -3.0e38f;
#pragma unroll
            for (int j = 0; j < 13; j++) mx = fmaxf(mx, row[lane + 32 * j]);
            mx = warpMax(mx);
            float ev[13];
            float ssum = 0.f;
#pragma unroll
            for (int j = 0; j < 13; j++) {
                ev[j] = __expf(row[lane + 32 * j] - mx);
                ssum += ev[j];
            }
            ssum = warpSum(ssum);
            float inv = c_sh[x0 + xr] / ssum;
#pragma unroll
            for (int j = 0; j < 13; j++) row[lane + 32 * j] = ev[j] * inv;
        }
        __syncthreads();

        // ---- AV: reduction-paired FFMA2; warp w owns rows 4w..4w+3 ----
        const float* ar = att + (w * 4) * 416;
        ull o2[4] = {0ull, 0ull, 0ull, 0ull};
#pragma unroll 2
        for (int y = 0; y < 416; y += 4) {
            float vv0 = v_sh[(y + 0) * 33 + lane];
            float vv1 = v_sh[(y + 1) * 33 + lane];
            float vv2 = v_sh[(y + 2) * 33 + lane];
            float vv3 = v_sh[(y + 3) * 33 + lane];
            ull vp01 = pk2(vv0, vv1);
            ull vp23 = pk2(vv2, vv3);
#pragma unroll
            for (int i = 0; i < 4; i++) {
                ulonglong2 ap = *(const ulonglong2*)&ar[i * 416 + y];
                ffma2(o2[i], ap.x, vp01);
                ffma2(o2[i], ap.y, vp23);
            }
        }
#pragma unroll
        for (int i = 0; i < 4; i++) {
            float lo, hi;
            upk2(o2[i], lo, hi);
            float ov = lo + hi;
            int xs_ = x0 + w * 4 + i;
            float gv = g_g[(baseBH + xs_) * Ee + lane];
            float sg = 1.f / (1.f + __expf(-gv));
            g_ao[((size_t)b * Ss + xs_) * Oo + h * Ee + lane] = ov * sg;
        }
        __syncthreads();
    }
}

// ============ Kernel 4: output projection + LN2, FFMA2 k-pairs =============
__global__ void k_outln(const float* __restrict__ wmat,
                        const float* __restrict__ bias,
                        const float* __restrict__ g2,
                        const float* __restrict__ b2,
                        float* __restrict__ out) {
    __shared__ float xs[16 * 256];
    __shared__ float ys[16 * 257];
    __shared__ float mus[16], rss[16];
    int t = threadIdx.x;
    int r0 = blockIdx.x * 16;

    for (int i = t; i < 1024; i += 256) {
        *(float4*)&xs[i * 4] = *(const float4*)&g_ao[(size_t)r0 * 256 + i * 4];
    }
    __syncthreads();

    ull acc2[16];
    float bb = bias[t];
#pragma unroll
    for (int r = 0; r < 16; r++) acc2[r] = pk2(bb * (r == 0 ? 1.f : 1.f) * 0.f, 0.f);
    // bias added at the end instead (acc2 starts at 0)
#pragma unroll
    for (int r = 0; r < 16; r++) acc2[r] = 0ull;

#pragma unroll 2
    for (int k4 = 0; k4 < 64; k4++) {
        int kk = k4 * 4;
        float w0 = wmat[(kk + 0) * 256 + t];
        float w1 = wmat[(kk + 1) * 256 + t];
        float w2 = wmat[(kk + 2) * 256 + t];
        float w3 = wmat[(kk + 3) * 256 + t];
        ull wp01 = pk2(w0, w1);
        ull wp23 = pk2(w2, w3);
#pragma unroll
        for (int r = 0; r < 16; r++) {
            ulonglong2 xv = *(const ulonglong2*)&xs[r * 256 + kk];
            ffma2(acc2[r], xv.x, wp01);
            ffma2(acc2[r], xv.y, wp23);
        }
    }
#pragma unroll
    for (int r = 0; r < 16; r++) {
        float lo, hi;
        upk2(acc2[r], lo, hi);
        ys[r * 257 + t] = lo + hi + bb;
    }
    __syncthreads();

    int w = t >> 5, lane = t & 31;
#pragma unroll
    for (int half = 0; half < 2; half++) {
        int rr = w + half * 8;
        float s = 0.f;
#pragma unroll
        for (int j = 0; j < 8; j++) s += ys[rr * 257 + lane + 32 * j];
        s = warpSum(s);
        float mu = s * (1.f / 256.f);
        float vs = 0.f;
#pragma unroll
        for (int j = 0; j < 8; j++) {
            float d = ys[rr * 257 + lane + 32 * j] - mu;
            vs += d * d;
        }
        vs = warpSum(vs);
        if (lane == 0) { mus[rr] = mu; rss[rr] = rsqrtf(vs * (1.f / 256.f) + 1e-6f); }
    }
    __syncthreads();

    float gt = g2[t], bt = b2[t];
#pragma unroll
    for (int r = 0; r < 16; r++) {
        out[(size_t)(r0 + r) * 256 + t] =
            (ys[r * 257 + t] - mus[r]) * rss[r] * gt + bt;
    }
}

// ===========================================================================
extern "C" void kernel_launch(void* const* d_in, const int* in_sizes, int n_in,
                              void* d_out, int out_size) {
    const float* x   = (const float*)d_in[0];
    const float* pm  = (const float*)d_in[1];
    const float* mm  = (const float*)d_in[2];
    const float* qp  = (const float*)d_in[3];
    const float* kp  = (const float*)d_in[4];
    const float* vp  = (const float*)d_in[5];
    const float* gp  = (const float*)d_in[6];
    const float* ow  = (const float*)d_in[7];
    const float* ob  = (const float*)d_in[8];
    const float* l1g = (const float*)d_in[9];
    const float* l1b = (const float*)d_in[10];
    const float* l2g = (const float*)d_in[11];
    const float* l2b = (const float*)d_in[12];
    float* out = (float*)d_out;

    const int attn_smem = (32 * 420 + 416 * 33 + 32 * 416 + 2048 + 416) * 4; // 171776
    cudaFuncSetAttribute(k_attn, cudaFuncAttributeMaxDynamicSharedMemorySize,
                         attn_smem);

    k_ln1 <<<BSs, 256>>>(x, l1g, l1b);
    k_qkvg<<<dim3(416, 8), 256>>>(qp, kp, vp, gp);
    k_attn<<<Bb * Hh, 256, attn_smem>>>(pm, mm);
    k_outln<<<BSs / 16, 256>>>(ow, ob, l2g, l2b, out);
}

// round 5
// speedup vs baseline: 1.1612x; 1.1612x over previous
#include <cuda_runtime.h>
#include <cuda_bf16.h>
#include <cstdint>

#define Bb   128
#define Ss   416
#define Nn   32
#define Mm   384
#define Dd   256
#define Hh   8
#define Ee   32
#define Oo   256
#define BSs  (Bb*Ss)          // 53248

typedef unsigned long long ull;

// -------- scratch (static device globals; no runtime allocation) ----------
__device__ float g_xln[BSs*Dd];
__device__ float g_q  [Bb*Hh*Ss*Ee];
__device__ float g_k  [Bb*Hh*Ss*Ee];
__device__ float g_v  [Bb*Hh*Ss*Ee];
__device__ float g_g  [Bb*Hh*Ss*Ee];
__device__ float g_ao [BSs*Oo];

// -------- packed fp32x2 helpers (k_outln) ----------------------------------
__device__ __forceinline__ ull pk2(float lo, float hi) {
    ull r; asm("mov.b64 %0, {%1, %2};" : "=l"(r) : "f"(lo), "f"(hi)); return r;
}
__device__ __forceinline__ void upk2(ull v, float& lo, float& hi) {
    asm("mov.b64 {%0, %1}, %2;" : "=f"(lo), "=f"(hi) : "l"(v));
}
__device__ __forceinline__ void ffma2(ull& d, ull a, ull b) {
    asm("fma.rn.f32x2 %0, %1, %2, %0;" : "+l"(d) : "l"(a), "l"(b));
}

__device__ __forceinline__ float warpSum(float v) {
#pragma unroll
    for (int o = 16; o; o >>= 1) v += __shfl_xor_sync(0xffffffffu, v, o);
    return v;
}
__device__ __forceinline__ float warpMax(float v) {
#pragma unroll
    for (int o = 16; o; o >>= 1) v = fmaxf(v, __shfl_xor_sync(0xffffffffu, v, o));
    return v;
}

// -------- mma.sync helpers (sm_80-baseline HMMA; works on plain sm_103) ----
__device__ __forceinline__ uint32_t smem_u32(const void* p) {
    uint32_t a;
    asm("{ .reg .u64 t; cvta.to.shared.u64 t, %1; cvt.u32.u64 %0, t; }"
        : "=r"(a) : "l"(p));
    return a;
}
__device__ __forceinline__ void ldsm4(uint32_t& r0, uint32_t& r1,
                                      uint32_t& r2, uint32_t& r3, uint32_t a) {
    asm volatile("ldmatrix.sync.aligned.m8n8.x4.shared.b16 {%0,%1,%2,%3}, [%4];"
                 : "=r"(r0), "=r"(r1), "=r"(r2), "=r"(r3) : "r"(a));
}
__device__ __forceinline__ void mma16816(float* d, const uint32_t* a,
                                         const uint32_t* b) {
    asm volatile(
        "mma.sync.aligned.m16n8k16.row.col.f32.bf16.bf16.f32 "
        "{%0,%1,%2,%3}, {%4,%5,%6,%7}, {%8,%9}, {%0,%1,%2,%3};"
        : "+f"(d[0]), "+f"(d[1]), "+f"(d[2]), "+f"(d[3])
        : "r"(a[0]), "r"(a[1]), "r"(a[2]), "r"(a[3]), "r"(b[0]), "r"(b[1]));
}

// =================== Kernel 1: LayerNorm over D=256 =======================
__global__ void k_ln1(const float* __restrict__ x,
                      const float* __restrict__ gam,
                      const float* __restrict__ bet) {
    int row = blockIdx.x;
    int t = threadIdx.x;
    int w = t >> 5, lane = t & 31;
    __shared__ float red[8];

    float v = x[(size_t)row * Dd + t];
    float s = warpSum(v);
    if (lane == 0) red[w] = s;
    __syncthreads();
    float mu = 0.f;
#pragma unroll
    for (int i = 0; i < 8; i++) mu += red[i];
    mu *= (1.f / 256.f);
    float d = v - mu;
    __syncthreads();
    s = warpSum(d * d);
    if (lane == 0) red[w] = s;
    __syncthreads();
    float var = 0.f;
#pragma unroll
    for (int i = 0; i < 8; i++) var += red[i];
    var *= (1.f / 256.f);
    g_xln[(size_t)row * Dd + t] = d * rsqrtf(var + 1e-6f) * gam[t] + bet[t];
}

// ============ Kernel 2: QKVG projections via mma.sync bf16x3 ===============
// Block tile 128x64, 8 warps (4m x 2n), each warp 32x32 (2 m16 x 4 n8 tiles).
// K loop: 8 chunks of 32. A,W split hi/lo bf16; 3 MMA terms (hh, hl, lh).
__global__ void __launch_bounds__(256)
k_qkvg(const float* __restrict__ qp, const float* __restrict__ kp,
       const float* __restrict__ vp, const float* __restrict__ gp) {
    __shared__ __align__(16) __nv_bfloat16 Ahi[128 * 40];
    __shared__ __align__(16) __nv_bfloat16 Alo[128 * 40];
    __shared__ __align__(16) __nv_bfloat16 Bhi[64 * 40];
    __shared__ __align__(16) __nv_bfloat16 Blo[64 * 40];

    int tid = threadIdx.x;
    int wid = tid >> 5, lane = tid & 31;
    int wm = wid & 3, wn = wid >> 2;

    int m0 = blockIdx.x * 128;
    int n0 = blockIdx.y * 64;
    int proj = n0 >> 8;
    const float* Wp = (proj == 0) ? qp : (proj == 1) ? kp
                     : (proj == 2) ? vp : gp;
    float* Og = (proj == 0) ? g_q : (proj == 1) ? g_k
               : (proj == 2) ? g_v : g_g;
    int nin = n0 & 255;

    uint32_t ahi_b = smem_u32(Ahi), alo_b = smem_u32(Alo);
    uint32_t bhi_b = smem_u32(Bhi), blo_b = smem_u32(Blo);

    float acc[2][4][4];
#pragma unroll
    for (int i = 0; i < 2; i++)
#pragma unroll
        for (int j = 0; j < 4; j++)
#pragma unroll
            for (int c = 0; c < 4; c++) acc[i][j][c] = 0.f;

    // precomputed ldmatrix lane addressing
    int a_row = (lane & 15);
    int a_kof = (lane >> 4) * 8;
    int b_row = ((lane >> 4) & 1) * 8 + (lane & 7);
    int b_kof = ((lane >> 3) & 1) * 8;

    for (int k0 = 0; k0 < 256; k0 += 32) {
        // ---- stage A 128x32 (hi/lo) ----
#pragma unroll
        for (int it = 0; it < 8; it++) {
            int p = tid + it * 256;
            int row = p >> 4, kp2 = p & 15;
            float2 a2 = *(const float2*)&g_xln[(size_t)(m0 + row) * Dd + k0 + kp2 * 2];
            __nv_bfloat16 h0 = __float2bfloat16(a2.x);
            __nv_bfloat16 h1 = __float2bfloat16(a2.y);
            __nv_bfloat162 ph; ph.x = h0; ph.y = h1;
            __nv_bfloat162 pl;
            pl.x = __float2bfloat16(a2.x - __bfloat162float(h0));
            pl.y = __float2bfloat16(a2.y - __bfloat162float(h1));
            *(__nv_bfloat162*)&Ahi[row * 40 + kp2 * 2] = ph;
            *(__nv_bfloat162*)&Alo[row * 40 + kp2 * 2] = pl;
        }
        // ---- stage B 64x32 (hi/lo): Bs[n][k], W[h][k][e] ----
#pragma unroll
        for (int it = 0; it < 4; it++) {
            int p = tid + it * 256;
            int n = p >> 4, kp2 = p & 15;
            int k = k0 + kp2 * 2;
            int nglob = nin + n;
            int h = nglob >> 5, e = nglob & 31;
            float w0 = Wp[h * 8192 + k * 32 + e];
            float w1 = Wp[h * 8192 + (k + 1) * 32 + e];
            __nv_bfloat16 h0 = __float2bfloat16(w0);
            __nv_bfloat16 h1 = __float2bfloat16(w1);
            __nv_bfloat162 ph; ph.x = h0; ph.y = h1;
            __nv_bfloat162 pl;
            pl.x = __float2bfloat16(w0 - __bfloat162float(h0));
            pl.y = __float2bfloat16(w1 - __bfloat162float(h1));
            *(__nv_bfloat162*)&Bhi[n * 40 + kp2 * 2] = ph;
            *(__nv_bfloat162*)&Blo[n * 40 + kp2 * 2] = pl;
        }
        __syncthreads();

#pragma unroll
        for (int ks = 0; ks < 2; ks++) {
            int kk = ks * 16;
            uint32_t ah[2][4], al[2][4];
#pragma unroll
            for (int mt = 0; mt < 2; mt++) {
                int row = wm * 32 + mt * 16 + a_row;
                uint32_t off = (uint32_t)(row * 40 + kk + a_kof) * 2;
                ldsm4(ah[mt][0], ah[mt][1], ah[mt][2], ah[mt][3], ahi_b + off);
                ldsm4(al[mt][0], al[mt][1], al[mt][2], al[mt][3], alo_b + off);
            }
            uint32_t bh[4][2], bl[4][2];
#pragma unroll
            for (int jp = 0; jp < 2; jp++) {          // n8-tile pairs
                int row = wn * 32 + jp * 16 + b_row;
                uint32_t off = (uint32_t)(row * 40 + kk + b_kof) * 2;
                ldsm4(bh[jp*2][0], bh[jp*2][1], bh[jp*2+1][0], bh[jp*2+1][1],
                      bhi_b + off);
                ldsm4(bl[jp*2][0], bl[jp*2][1], bl[jp*2+1][0], bl[jp*2+1][1],
                      blo_b + off);
            }
#pragma unroll
            for (int mt = 0; mt < 2; mt++)
#pragma unroll
                for (int j = 0; j < 4; j++) {
                    mma16816(acc[mt][j], ah[mt], bh[j]);
                    mma16816(acc[mt][j], ah[mt], bl[j]);
                    mma16816(acc[mt][j], al[mt], bh[j]);
                }
        }
        __syncthreads();
    }

    // ---- epilogue: D fragment -> Og [B,H,S,E] ----
    int h = (nin + wn * 32) >> 5;
#pragma unroll
    for (int mt = 0; mt < 2; mt++) {
        int m = m0 + wm * 32 + mt * 16 + (lane >> 2);
        int b1 = m / Ss, s1 = m - b1 * Ss;
        int m2 = m + 8;
        int b2 = m2 / Ss, s2 = m2 - b2 * Ss;
#pragma unroll
        for (int j = 0; j < 4; j++) {
            int e = j * 8 + (lane & 3) * 2;
            float2 v01 = make_float2(acc[mt][j][0], acc[mt][j][1]);
            float2 v23 = make_float2(acc[mt][j][2], acc[mt][j][3]);
            *(float2*)&Og[(((size_t)(b1 * Hh + h)) * Ss + s1) * Ee + e] = v01;
            *(float2*)&Og[(((size_t)(b2 * Hh + h)) * Ss + s2) * Ee + e] = v23;
        }
    }
}

// ============ Kernel 3: fused attention, one block per (b,h) (scalar) ======
// smem: kT[32*420] | v[416*33] | att[32*416] | q[1024] | c[416] = 167680 B
__global__ void k_attn(const float* __restrict__ pmask,
                       const float* __restrict__ mmask) {
    extern __shared__ float sm[];
    float* kT   = sm;                        // e-major: kT[e*420 + y]
    float* v_sh = kT + 32 * 420;             // v_sh[y*33 + e]
    float* att  = v_sh + 416 * 33;           // att[x*416 + y]
    float* q_sh = att + 32 * 416;            // q_sh[x*32 + e]
    float* c_sh = q_sh + 1024;               // 416

    int tid = threadIdx.x;
    int bh = blockIdx.x;
    int h = bh & 7, b = bh >> 3;
    size_t baseBH = (size_t)(b * Hh + h) * Ss;

    const float* kb = g_k + baseBH * Ee;
    for (int i = tid; i < Ss * Ee; i += 256) {
        int y = i >> 5, e = i & 31;
        kT[e * 420 + y] = kb[i];
    }
    const float* vb = g_v + baseBH * Ee;
    for (int i = tid; i < Ss * Ee; i += 256) {
        int y = i >> 5, e = i & 31;
        v_sh[y * 33 + e] = vb[i];
    }
    for (int i = tid; i < Ss; i += 256) {
        float val = (i < Nn) ? pmask[b * Nn + i] : mmask[b * Mm + (i - Nn)];
        c_sh[i] = (val == -2.0f) ? 0.f : 1.f;
    }
    __syncthreads();

    const float scale = 0.1767766952966369f;   // 1/sqrt(32)
    int w = tid >> 5;
    int lane = tid & 31;
    int xg = w;

    for (int tile = 0; tile < 13; tile++) {
        int x0 = tile * 32;
        const float* qb = g_q + (baseBH + x0) * Ee;
#pragma unroll
        for (int i = tid; i < 1024; i += 256) q_sh[i] = qb[i];
        __syncthreads();

        bool xIsP = (tile == 0);
        for (int yq = lane; yq < 104; yq += 32) {
            int y0 = yq << 2;
            float4 acc[4];
#pragma unroll
            for (int i = 0; i < 4; i++) acc[i] = make_float4(0.f, 0.f, 0.f, 0.f);
#pragma unroll 8
            for (int e = 0; e < 32; e++) {
                float4 kv = *(const float4*)&kT[e * 420 + y0];
#pragma unroll
                for (int i = 0; i < 4; i++) {
                    float a = q_sh[(xg * 4 + i) * 32 + e];
                    acc[i].x = fmaf(a, kv.x, acc[i].x);
                    acc[i].y = fmaf(a, kv.y, acc[i].y);
                    acc[i].z = fmaf(a, kv.z, acc[i].z);
                    acc[i].w = fmaf(a, kv.w, acc[i].w);
                }
            }
            float4 cy = *(const float4*)&c_sh[y0];
            bool cross = (xIsP != (y0 < Nn));
#pragma unroll
            for (int i = 0; i < 4; i++) {
                float cxi = c_sh[x0 + xg * 4 + i];
                float mx_ = cross ? cxi * cy.x : 0.f;
                float my_ = cross ? cxi * cy.y : 0.f;
                float mz_ = cross ? cxi * cy.z : 0.f;
                float mw_ = cross ? cxi * cy.w : 0.f;
                float4 r;
                r.x = acc[i].x * scale + (1.f - mx_) * (-1.0e9f);
                r.y = acc[i].y * scale + (1.f - my_) * (-1.0e9f);
                r.z = acc[i].z * scale + (1.f - mz_) * (-1.0e9f);
                r.w = acc[i].w * scale + (1.f - mw_) * (-1.0e9f);
                *(float4*)&att[(xg * 4 + i) * 416 + y0] = r;
            }
        }
        __syncthreads();

#pragma unroll
        for (int rr = 0; rr < 4; rr++) {
            int xr = w + rr * 8;
            float* row = att + xr * 416;
            float mx = -3.0e38f;
#pragma unroll
            for (int j = 0; j < 13; j++) mx = fmaxf(mx, row[lane + 32 * j]);
            mx = warpMax(mx);
            float ev[13];
            float ssum = 0.f;
#pragma unroll
            for (int j = 0; j < 13; j++) {
                ev[j] = __expf(row[lane + 32 * j] - mx);
                ssum += ev[j];
            }
            ssum = warpSum(ssum);
            float inv = c_sh[x0 + xr] / ssum;
#pragma unroll
            for (int j = 0; j < 13; j++) row[lane + 32 * j] = ev[j] * inv;
        }
        __syncthreads();

        const float* ar = att + (w * 4) * 416;
        float o0 = 0.f, o1 = 0.f, o2 = 0.f, o3 = 0.f;
#pragma unroll 2
        for (int y = 0; y < 416; y += 4) {
            float4 a0 = *(const float4*)&ar[y];
            float4 a1 = *(const float4*)&ar[416 + y];
            float4 a2 = *(const float4*)&ar[832 + y];
            float4 a3 = *(const float4*)&ar[1248 + y];
            float vv0 = v_sh[(y + 0) * 33 + lane];
            float vv1 = v_sh[(y + 1) * 33 + lane];
            float vv2 = v_sh[(y + 2) * 33 + lane];
            float vv3 = v_sh[(y + 3) * 33 + lane];
            o0 = fmaf(a0.x, vv0, fmaf(a0.y, vv1, fmaf(a0.z, vv2, fmaf(a0.w, vv3, o0))));
            o1 = fmaf(a1.x, vv0, fmaf(a1.y, vv1, fmaf(a1.z, vv2, fmaf(a1.w, vv3, o1))));
            o2 = fmaf(a2.x, vv0, fmaf(a2.y, vv1, fmaf(a2.z, vv2, fmaf(a2.w, vv3, o2))));
            o3 = fmaf(a3.x, vv0, fmaf(a3.y, vv1, fmaf(a3.z, vv2, fmaf(a3.w, vv3, o3))));
        }
        float ov[4] = {o0, o1, o2, o3};
#pragma unroll
        for (int i = 0; i < 4; i++) {
            int xs_ = x0 + w * 4 + i;
            float gv = g_g[(baseBH + xs_) * Ee + lane];
            float sg = 1.f / (1.f + __expf(-gv));
            g_ao[((size_t)b * Ss + xs_) * Oo + h * Ee + lane] = ov[i] * sg;
        }
        __syncthreads();
    }
}

// ============ Kernel 4: output projection + LN2, FFMA2 k-pairs =============
__global__ void k_outln(const float* __restrict__ wmat,
                        const float* __restrict__ bias,
                        const float* __restrict__ g2,
                        const float* __restrict__ b2,
                        float* __restrict__ out) {
    __shared__ float xs[16 * 256];
    __shared__ float ys[16 * 257];
    __shared__ float mus[16], rss[16];
    int t = threadIdx.x;
    int r0 = blockIdx.x * 16;

    for (int i = t; i < 1024; i += 256) {
        *(float4*)&xs[i * 4] = *(const float4*)&g_ao[(size_t)r0 * 256 + i * 4];
    }
    __syncthreads();

    ull acc2[16];
    float bb = bias[t];
#pragma unroll
    for (int r = 0; r < 16; r++) acc2[r] = 0ull;

#pragma unroll 2
    for (int k4 = 0; k4 < 64; k4++) {
        int kk = k4 * 4;
        float w0 = wmat[(kk + 0) * 256 + t];
        float w1 = wmat[(kk + 1) * 256 + t];
        float w2 = wmat[(kk + 2) * 256 + t];
        float w3 = wmat[(kk + 3) * 256 + t];
        ull wp01 = pk2(w0, w1);
        ull wp23 = pk2(w2, w3);
#pragma unroll
        for (int r = 0; r < 16; r++) {
            ulonglong2 xv = *(const ulonglong2*)&xs[r * 256 + kk];
            ffma2(acc2[r], xv.x, wp01);
            ffma2(acc2[r], xv.y, wp23);
        }
    }
#pragma unroll
    for (int r = 0; r < 16; r++) {
        float lo, hi;
        upk2(acc2[r], lo, hi);
        ys[r * 257 + t] = lo + hi + bb;
    }
    __syncthreads();

    int w = t >> 5, lane = t & 31;
#pragma unroll
    for (int half = 0; half < 2; half++) {
        int rr = w + half * 8;
        float s = 0.f;
#pragma unroll
        for (int j = 0; j < 8; j++) s += ys[rr * 257 + lane + 32 * j];
        s = warpSum(s);
        float mu = s * (1.f / 256.f);
        float vs = 0.f;
#pragma unroll
        for (int j = 0; j < 8; j++) {
            float d = ys[rr * 257 + lane + 32 * j] - mu;
            vs += d * d;
        }
        vs = warpSum(vs);
        if (lane == 0) { mus[rr] = mu; rss[rr] = rsqrtf(vs * (1.f / 256.f) + 1e-6f); }
    }
    __syncthreads();

    float gt = g2[t], bt = b2[t];
#pragma unroll
    for (int r = 0; r < 16; r++) {
        out[(size_t)(r0 + r) * 256 + t] =
            (ys[r * 257 + t] - mus[r]) * rss[r] * gt + bt;
    }
}

// ===========================================================================
extern "C" void kernel_launch(void* const* d_in, const int* in_sizes, int n_in,
                              void* d_out, int out_size) {
    const float* x   = (const float*)d_in[0];
    const float* pm  = (const float*)d_in[1];
    const float* mm  = (const float*)d_in[2];
    const float* qp  = (const float*)d_in[3];
    const float* kp  = (const float*)d_in[4];
    const float* vp  = (const float*)d_in[5];
    const float* gp  = (const float*)d_in[6];
    const float* ow  = (const float*)d_in[7];
    const float* ob  = (const float*)d_in[8];
    const float* l1g = (const float*)d_in[9];
    const float* l1b = (const float*)d_in[10];
    const float* l2g = (const float*)d_in[11];
    const float* l2b = (const float*)d_in[12];
    float* out = (float*)d_out;

    const int attn_smem = (32 * 420 + 416 * 33 + 32 * 416 + 1024 + 416) * 4; // 167680
    cudaFuncSetAttribute(k_attn, cudaFuncAttributeMaxDynamicSharedMemorySize,
                         attn_smem);

    k_ln1 <<<BSs, 256>>>(x, l1g, l1b);
    k_qkvg<<<dim3(416, 16), 256>>>(qp, kp, vp, gp);
    k_attn<<<Bb * Hh, 256, attn_smem>>>(pm, mm);
    k_outln<<<BSs / 16, 256>>>(ow, ob, l2g, l2b, out);
}

// round 6
// speedup vs baseline: 1.7143x; 1.4763x over previous
#include <cuda_runtime.h>
#include <cuda_bf16.h>
#include <cstdint>

#define Bb   128
#define Ss   416
#define Nn   32
#define Mm   384
#define Dd   256
#define Hh   8
#define Ee   32
#define Oo   256
#define BSs  (Bb*Ss)          // 53248

typedef unsigned long long ull;

// -------- scratch (static device globals; no runtime allocation) ----------
__device__ float g_xln[BSs*Dd];
__device__ float g_q  [Bb*Hh*Ss*Ee];
__device__ float g_k  [Bb*Hh*Ss*Ee];
__device__ float g_v  [Bb*Hh*Ss*Ee];
__device__ float g_g  [Bb*Hh*Ss*Ee];
__device__ float g_ao [BSs*Oo];

// -------- packed fp32x2 helpers (k_outln) ----------------------------------
__device__ __forceinline__ ull pk2(float lo, float hi) {
    ull r; asm("mov.b64 %0, {%1, %2};" : "=l"(r) : "f"(lo), "f"(hi)); return r;
}
__device__ __forceinline__ void upk2(ull v, float& lo, float& hi) {
    asm("mov.b64 {%0, %1}, %2;" : "=f"(lo), "=f"(hi) : "l"(v));
}
__device__ __forceinline__ void ffma2(ull& d, ull a, ull b) {
    asm("fma.rn.f32x2 %0, %1, %2, %0;" : "+l"(d) : "l"(a), "l"(b));
}

__device__ __forceinline__ float warpSum(float v) {
#pragma unroll
    for (int o = 16; o; o >>= 1) v += __shfl_xor_sync(0xffffffffu, v, o);
    return v;
}
__device__ __forceinline__ float warpMax(float v) {
#pragma unroll
    for (int o = 16; o; o >>= 1) v = fmaxf(v, __shfl_xor_sync(0xffffffffu, v, o));
    return v;
}

// -------- mma.sync helpers (sm_80-baseline HMMA; works on plain sm_103) ----
__device__ __forceinline__ uint32_t smem_u32(const void* p) {
    uint32_t a;
    asm("{ .reg .u64 t; cvta.to.shared.u64 t, %1; cvt.u32.u64 %0, t; }"
        : "=r"(a) : "l"(p));
    return a;
}
__device__ __forceinline__ void ldsm4(uint32_t& r0, uint32_t& r1,
                                      uint32_t& r2, uint32_t& r3, uint32_t a) {
    asm volatile("ldmatrix.sync.aligned.m8n8.x4.shared.b16 {%0,%1,%2,%3}, [%4];"
                 : "=r"(r0), "=r"(r1), "=r"(r2), "=r"(r3) : "r"(a));
}
__device__ __forceinline__ void ldsm2(uint32_t& r0, uint32_t& r1, uint32_t a) {
    asm volatile("ldmatrix.sync.aligned.m8n8.x2.shared.b16 {%0,%1}, [%2];"
                 : "=r"(r0), "=r"(r1) : "r"(a));
}
__device__ __forceinline__ void mma16816(float* d, const uint32_t* a,
                                         const uint32_t* b) {
    asm volatile(
        "mma.sync.aligned.m16n8k16.row.col.f32.bf16.bf16.f32 "
        "{%0,%1,%2,%3}, {%4,%5,%6,%7}, {%8,%9}, {%0,%1,%2,%3};"
        : "+f"(d[0]), "+f"(d[1]), "+f"(d[2]), "+f"(d[3])
        : "r"(a[0]), "r"(a[1]), "r"(a[2]), "r"(a[3]), "r"(b[0]), "r"(b[1]));
}
__device__ __forceinline__ void hilo(float v, __nv_bfloat16& h, __nv_bfloat16& l) {
    h = __float2bfloat16(v);
    l = __float2bfloat16(v - __bfloat162float(h));
}

// =================== Kernel 1: LayerNorm over D=256 =======================
__global__ void k_ln1(const float* __restrict__ x,
                      const float* __restrict__ gam,
                      const float* __restrict__ bet) {
    int row = blockIdx.x;
    int t = threadIdx.x;
    int w = t >> 5, lane = t & 31;
    __shared__ float red[8];

    float v = x[(size_t)row * Dd + t];
    float s = warpSum(v);
    if (lane == 0) red[w] = s;
    __syncthreads();
    float mu = 0.f;
#pragma unroll
    for (int i = 0; i < 8; i++) mu += red[i];
    mu *= (1.f / 256.f);
    float d = v - mu;
    __syncthreads();
    s = warpSum(d * d);
    if (lane == 0) red[w] = s;
    __syncthreads();
    float var = 0.f;
#pragma unroll
    for (int i = 0; i < 8; i++) var += red[i];
    var *= (1.f / 256.f);
    g_xln[(size_t)row * Dd + t] = d * rsqrtf(var + 1e-6f) * gam[t] + bet[t];
}

// ============ Kernel 2: QKVG projections via mma.sync bf16x3 ===============
__global__ void __launch_bounds__(256)
k_qkvg(const float* __restrict__ qp, const float* __restrict__ kp,
       const float* __restrict__ vp, const float* __restrict__ gp) {
    __shared__ __align__(16) __nv_bfloat16 Ahi[128 * 40];
    __shared__ __align__(16) __nv_bfloat16 Alo[128 * 40];
    __shared__ __align__(16) __nv_bfloat16 Bhi[64 * 40];
    __shared__ __align__(16) __nv_bfloat16 Blo[64 * 40];

    int tid = threadIdx.x;
    int wid = tid >> 5, lane = tid & 31;
    int wm = wid & 3, wn = wid >> 2;

    int m0 = blockIdx.x * 128;
    int n0 = blockIdx.y * 64;
    int proj = n0 >> 8;
    const float* Wp = (proj == 0) ? qp : (proj == 1) ? kp
                     : (proj == 2) ? vp : gp;
    float* Og = (proj == 0) ? g_q : (proj == 1) ? g_k
               : (proj == 2) ? g_v : g_g;
    int nin = n0 & 255;

    uint32_t ahi_b = smem_u32(Ahi), alo_b = smem_u32(Alo);
    uint32_t bhi_b = smem_u32(Bhi), blo_b = smem_u32(Blo);

    float acc[2][4][4];
#pragma unroll
    for (int i = 0; i < 2; i++)
#pragma unroll
        for (int j = 0; j < 4; j++)
#pragma unroll
            for (int c = 0; c < 4; c++) acc[i][j][c] = 0.f;

    int a_row = (lane & 15);
    int a_kof = (lane >> 4) * 8;
    int b_row = ((lane >> 4) & 1) * 8 + (lane & 7);
    int b_kof = ((lane >> 3) & 1) * 8;

    for (int k0 = 0; k0 < 256; k0 += 32) {
#pragma unroll
        for (int it = 0; it < 8; it++) {
            int p = tid + it * 256;
            int row = p >> 4, kp2 = p & 15;
            float2 a2 = *(const float2*)&g_xln[(size_t)(m0 + row) * Dd + k0 + kp2 * 2];
            __nv_bfloat162 ph, pl;
            hilo(a2.x, ph.x, pl.x);
            hilo(a2.y, ph.y, pl.y);
            *(__nv_bfloat162*)&Ahi[row * 40 + kp2 * 2] = ph;
            *(__nv_bfloat162*)&Alo[row * 40 + kp2 * 2] = pl;
        }
#pragma unroll
        for (int it = 0; it < 4; it++) {
            int p = tid + it * 256;
            int n = p >> 4, kp2 = p & 15;
            int k = k0 + kp2 * 2;
            int nglob = nin + n;
            int h = nglob >> 5, e = nglob & 31;
            float w0 = Wp[h * 8192 + k * 32 + e];
            float w1 = Wp[h * 8192 + (k + 1) * 32 + e];
            __nv_bfloat162 ph, pl;
            hilo(w0, ph.x, pl.x);
            hilo(w1, ph.y, pl.y);
            *(__nv_bfloat162*)&Bhi[n * 40 + kp2 * 2] = ph;
            *(__nv_bfloat162*)&Blo[n * 40 + kp2 * 2] = pl;
        }
        __syncthreads();

#pragma unroll
        for (int ks = 0; ks < 2; ks++) {
            int kk = ks * 16;
            uint32_t ah[2][4], al[2][4];
#pragma unroll
            for (int mt = 0; mt < 2; mt++) {
                int row = wm * 32 + mt * 16 + a_row;
                uint32_t off = (uint32_t)(row * 40 + kk + a_kof) * 2;
                ldsm4(ah[mt][0], ah[mt][1], ah[mt][2], ah[mt][3], ahi_b + off);
                ldsm4(al[mt][0], al[mt][1], al[mt][2], al[mt][3], alo_b + off);
            }
            uint32_t bh[4][2], bl[4][2];
#pragma unroll
            for (int jp = 0; jp < 2; jp++) {
                int row = wn * 32 + jp * 16 + b_row;
                uint32_t off = (uint32_t)(row * 40 + kk + b_kof) * 2;
                ldsm4(bh[jp*2][0], bh[jp*2][1], bh[jp*2+1][0], bh[jp*2+1][1],
                      bhi_b + off);
                ldsm4(bl[jp*2][0], bl[jp*2][1], bl[jp*2+1][0], bl[jp*2+1][1],
                      blo_b + off);
            }
#pragma unroll
            for (int mt = 0; mt < 2; mt++)
#pragma unroll
                for (int j = 0; j < 4; j++) {
                    mma16816(acc[mt][j], ah[mt], bh[j]);
                    mma16816(acc[mt][j], ah[mt], bl[j]);
                    mma16816(acc[mt][j], al[mt], bh[j]);
                }
        }
        __syncthreads();
    }

    int h = (nin + wn * 32) >> 5;
#pragma unroll
    for (int mt = 0; mt < 2; mt++) {
        int m = m0 + wm * 32 + mt * 16 + (lane >> 2);
        int b1 = m / Ss, s1 = m - b1 * Ss;
        int m2 = m + 8;
        int b2 = m2 / Ss, s2 = m2 - b2 * Ss;
#pragma unroll
        for (int j = 0; j < 4; j++) {
            int e = j * 8 + (lane & 3) * 2;
            float2 v01 = make_float2(acc[mt][j][0], acc[mt][j][1]);
            float2 v23 = make_float2(acc[mt][j][2], acc[mt][j][3]);
            *(float2*)&Og[(((size_t)(b1 * Hh + h)) * Ss + s1) * Ee + e] = v01;
            *(float2*)&Og[(((size_t)(b2 * Hh + h)) * Ss + s2) * Ee + e] = v23;
        }
    }
}

// ============ Kernel 3: fused attention via mma.sync bf16x3 =================
// One block per (b,h), 8 warps. K/V^T staged hi/lo once; per 32-row x-tile:
// QK^T (HMMA) -> mask/scale -> softmax (fp32 smem) -> att as hi/lo bf16
// (overlaying fp32 buffer) -> AV (HMMA) -> sigmoid(g) gate -> g_ao.
#define KHI_OFF   0
#define KLO_OFF   (KHI_OFF + 416*40*2)     // 33280
#define VTH_OFF   (KLO_OFF + 416*40*2)     // 66560
#define VTL_OFF   (VTH_OFF + 32*424*2)     // 93696
#define ATT_OFF   (VTL_OFF + 32*424*2)     // 120832
#define QHI_OFF   (ATT_OFF + 32*424*4)     // 175104
#define QLO_OFF   (QHI_OFF + 32*40*2)      // 177664
#define CSH_OFF   (QLO_OFF + 32*40*2)      // 180224
#define ATTN_SMEM (CSH_OFF + 416*4)        // 181888

__global__ void __launch_bounds__(256)
k_attn(const float* __restrict__ pmask, const float* __restrict__ mmask) {
    extern __shared__ char smc[];
    __nv_bfloat16* khi = (__nv_bfloat16*)(smc + KHI_OFF);
    __nv_bfloat16* klo = (__nv_bfloat16*)(smc + KLO_OFF);
    __nv_bfloat16* vth = (__nv_bfloat16*)(smc + VTH_OFF);
    __nv_bfloat16* vtl = (__nv_bfloat16*)(smc + VTL_OFF);
    float*         att = (float*)(smc + ATT_OFF);          // 32 x 424 fp32
    __nv_bfloat16* athi = (__nv_bfloat16*)(smc + ATT_OFF); // overlay: 32x424
    __nv_bfloat16* atlo = athi + 32 * 424;                 // overlay 2nd half
    __nv_bfloat16* qhi = (__nv_bfloat16*)(smc + QHI_OFF);
    __nv_bfloat16* qlo = (__nv_bfloat16*)(smc + QLO_OFF);
    float*         c_sh = (float*)(smc + CSH_OFF);

    uint32_t khi_b = smem_u32(khi), klo_b = smem_u32(klo);
    uint32_t vth_b = smem_u32(vth), vtl_b = smem_u32(vtl);
    uint32_t ath_b = smem_u32(athi), atl_b = smem_u32(atlo);
    uint32_t qhi_b = smem_u32(qhi), qlo_b = smem_u32(qlo);

    int tid = threadIdx.x;
    int wid = tid >> 5, lane = tid & 31;
    int bh = blockIdx.x;
    int h = bh & 7, b = bh >> 3;
    size_t baseBH = (size_t)(b * Hh + h) * Ss;

    // ---- stage K hi/lo [y][k], stride 40 ----
    const float* kb = g_k + baseBH * Ee;
    for (int i = tid; i < Ss * 16; i += 256) {
        int y = i >> 4, ep = i & 15;
        float2 kv = *(const float2*)&kb[y * 32 + ep * 2];
        __nv_bfloat162 ph, pl;
        hilo(kv.x, ph.x, pl.x);
        hilo(kv.y, ph.y, pl.y);
        *(__nv_bfloat162*)&khi[y * 40 + ep * 2] = ph;
        *(__nv_bfloat162*)&klo[y * 40 + ep * 2] = pl;
    }
    // ---- stage V^T hi/lo [e][y], stride 424 ----
    const float* vb = g_v + baseBH * Ee;
    for (int i = tid; i < Ss * Ee; i += 256) {
        int y = i >> 5, e = i & 31;
        float v = vb[y * 32 + e];
        __nv_bfloat16 hv, lv;
        hilo(v, hv, lv);
        vth[e * 424 + y] = hv;
        vtl[e * 424 + y] = lv;
    }
    for (int i = tid; i < Ss; i += 256) {
        float val = (i < Nn) ? pmask[b * Nn + i] : mmask[b * Mm + (i - Nn)];
        c_sh[i] = (val == -2.0f) ? 0.f : 1.f;
    }
    __syncthreads();

    const float scale = 0.1767766952966369f;   // 1/sqrt(32)
    int a_row = (lane & 15);
    int a_kof = (lane >> 4) * 8;
    int b_row = ((lane >> 4) & 1) * 8 + (lane & 7);
    int b_kof = ((lane >> 3) & 1) * 8;

    int mh = wid & 1;          // QK: m-half
    int nq = wid >> 1;         // QK: n-quarter (104 cols)
    int nbase = nq * 104;
    int amh = wid >> 2;        // AV: m-half
    int ant = wid & 3;         // AV: n8 tile

    for (int tile = 0; tile < 13; tile++) {
        int x0 = tile * 32;
        // ---- stage Q tile hi/lo ----
        const float* qb = g_q + (baseBH + x0) * Ee;
        for (int i = tid; i < 32 * 16; i += 256) {
            int xr = i >> 4, ep = i & 15;
            float2 qv = *(const float2*)&qb[xr * 32 + ep * 2];
            __nv_bfloat162 ph, pl;
            hilo(qv.x, ph.x, pl.x);
            hilo(qv.y, ph.y, pl.y);
            *(__nv_bfloat162*)&qhi[xr * 40 + ep * 2] = ph;
            *(__nv_bfloat162*)&qlo[xr * 40 + ep * 2] = pl;
        }
        __syncthreads();

        // ---- QK^T: warp = (mh, nq); 13 n8 tiles; k=32 ----
        float acc[13][4];
#pragma unroll
        for (int t2 = 0; t2 < 13; t2++)
#pragma unroll
            for (int c = 0; c < 4; c++) acc[t2][c] = 0.f;

#pragma unroll
        for (int ks = 0; ks < 2; ks++) {
            int kk = ks * 16;
            uint32_t ah[4], al[4];
            {
                uint32_t off = (uint32_t)((mh * 16 + a_row) * 40 + kk + a_kof) * 2;
                ldsm4(ah[0], ah[1], ah[2], ah[3], qhi_b + off);
                ldsm4(al[0], al[1], al[2], al[3], qlo_b + off);
            }
#pragma unroll
            for (int jp = 0; jp < 6; jp++) {
                uint32_t bh2[4], bl2[4];
                uint32_t off = (uint32_t)((nbase + jp * 16 + b_row) * 40 + kk + b_kof) * 2;
                ldsm4(bh2[0], bh2[1], bh2[2], bh2[3], khi_b + off);
                ldsm4(bl2[0], bl2[1], bl2[2], bl2[3], klo_b + off);
                mma16816(acc[jp*2],   ah, &bh2[0]);
                mma16816(acc[jp*2],   ah, &bl2[0]);
                mma16816(acc[jp*2],   al, &bh2[0]);
                mma16816(acc[jp*2+1], ah, &bh2[2]);
                mma16816(acc[jp*2+1], ah, &bl2[2]);
                mma16816(acc[jp*2+1], al, &bh2[2]);
            }
            {   // last n8 tile (t=12) via x2
                uint32_t bh1[2], bl1[2];
                uint32_t off = (uint32_t)((nbase + 96 + (lane & 7)) * 40 + kk
                                          + 8 * ((lane >> 3) & 1)) * 2;
                ldsm2(bh1[0], bh1[1], khi_b + off);
                ldsm2(bl1[0], bl1[1], klo_b + off);
                mma16816(acc[12], ah, bh1);
                mma16816(acc[12], ah, bl1);
                mma16816(acc[12], al, bh1);
            }
        }

        // ---- mask/scale epilogue -> att fp32 ----
        bool xIsP = (x0 == 0);
        int lx1 = mh * 16 + (lane >> 2);
        int lx2 = lx1 + 8;
        float cx1 = c_sh[x0 + lx1];
        float cx2 = c_sh[x0 + lx2];
#pragma unroll
        for (int t2 = 0; t2 < 13; t2++) {
            int ybase = nbase + t2 * 8;
            int yc = ybase + (lane & 3) * 2;
            bool cross = (xIsP != (ybase < Nn));
            float cy0 = c_sh[yc], cy1 = c_sh[yc + 1];
            float m00 = cross ? cx1 * cy0 : 0.f;
            float m01 = cross ? cx1 * cy1 : 0.f;
            float m10 = cross ? cx2 * cy0 : 0.f;
            float m11 = cross ? cx2 * cy1 : 0.f;
            float2 r1 = make_float2(acc[t2][0] * scale + (1.f - m00) * (-1.0e9f),
                                    acc[t2][1] * scale + (1.f - m01) * (-1.0e9f));
            float2 r2 = make_float2(acc[t2][2] * scale + (1.f - m10) * (-1.0e9f),
                                    acc[t2][3] * scale + (1.f - m11) * (-1.0e9f));
            *(float2*)&att[lx1 * 424 + yc] = r1;
            *(float2*)&att[lx2 * 424 + yc] = r2;
        }
        __syncthreads();

        // ---- softmax: warp w rows {w, w+8, w+16, w+24}; keep values in regs
        float nv[4][13];
#pragma unroll
        for (int rr = 0; rr < 4; rr++) {
            int xr = wid + rr * 8;
            const float* row = att + xr * 424;
            float mx = -3.0e38f;
#pragma unroll
            for (int j = 0; j < 13; j++) mx = fmaxf(mx, row[lane + 32 * j]);
            mx = warpMax(mx);
            float ssum = 0.f;
#pragma unroll
            for (int j = 0; j < 13; j++) {
                nv[rr][j] = __expf(row[lane + 32 * j] - mx);
                ssum += nv[rr][j];
            }
            ssum = warpSum(ssum);
            float inv = c_sh[x0 + xr] / ssum;
#pragma unroll
            for (int j = 0; j < 13; j++) nv[rr][j] *= inv;
        }
        __syncthreads();   // all fp32 reads done before bf16 overlay writes

#pragma unroll
        for (int rr = 0; rr < 4; rr++) {
            int xr = wid + rr * 8;
#pragma unroll
            for (int j = 0; j < 13; j++) {
                __nv_bfloat16 hv, lv;
                hilo(nv[rr][j], hv, lv);
                athi[xr * 424 + lane + 32 * j] = hv;
                atlo[xr * 424 + lane + 32 * j] = lv;
            }
        }
        __syncthreads();

        // ---- AV: warp = (amh, ant); m16n8, k=416 in 13 double-chunks ----
        float oacc[4] = {0.f, 0.f, 0.f, 0.f};
#pragma unroll
        for (int kc = 0; kc < 13; kc++) {
            int kk = kc * 32;
            uint32_t a0h[4], a0l[4], a1h[4], a1l[4];
            uint32_t offA0 = (uint32_t)((amh * 16 + a_row) * 424 + kk + a_kof) * 2;
            uint32_t offA1 = offA0 + 32;   // +16 bf16 columns
            ldsm4(a0h[0], a0h[1], a0h[2], a0h[3], ath_b + offA0);
            ldsm4(a0l[0], a0l[1], a0l[2], a0l[3], atl_b + offA0);
            ldsm4(a1h[0], a1h[1], a1h[2], a1h[3], ath_b + offA1);
            ldsm4(a1l[0], a1l[1], a1l[2], a1l[3], atl_b + offA1);
            uint32_t bh4[4], bl4[4];
            uint32_t offB = (uint32_t)((ant * 8 + (lane & 7)) * 424 + kk
                                       + (lane >> 3) * 8) * 2;
            ldsm4(bh4[0], bh4[1], bh4[2], bh4[3], vth_b + offB);
            ldsm4(bl4[0], bl4[1], bl4[2], bl4[3], vtl_b + offB);
            mma16816(oacc, a0h, &bh4[0]);
            mma16816(oacc, a0h, &bl4[0]);
            mma16816(oacc, a0l, &bh4[0]);
            mma16816(oacc, a1h, &bh4[2]);
            mma16816(oacc, a1h, &bl4[2]);
            mma16816(oacc, a1l, &bh4[2]);
        }

        // ---- gate + store ----
        {
            int lx = amh * 16 + (lane >> 2);
            int e = ant * 8 + (lane & 3) * 2;
#pragma unroll
            for (int half = 0; half < 2; half++) {
                int xs_ = x0 + lx + half * 8;
                float2 gv = *(const float2*)&g_g[(baseBH + xs_) * Ee + e];
                float s0 = 1.f / (1.f + __expf(-gv.x));
                float s1 = 1.f / (1.f + __expf(-gv.y));
                float2 ov = make_float2(oacc[half * 2] * s0,
                                        oacc[half * 2 + 1] * s1);
                *(float2*)&g_ao[((size_t)b * Ss + xs_) * Oo + h * Ee + e] = ov;
            }
        }
        __syncthreads();
    }
}

// ============ Kernel 4: output projection + LN2, FFMA2 k-pairs =============
__global__ void k_outln(const float* __restrict__ wmat,
                        const float* __restrict__ bias,
                        const float* __restrict__ g2,
                        const float* __restrict__ b2,
                        float* __restrict__ out) {
    __shared__ float xs[16 * 256];
    __shared__ float ys[16 * 257];
    __shared__ float mus[16], rss[16];
    int t = threadIdx.x;
    int r0 = blockIdx.x * 16;

    for (int i = t; i < 1024; i += 256) {
        *(float4*)&xs[i * 4] = *(const float4*)&g_ao[(size_t)r0 * 256 + i * 4];
    }
    __syncthreads();

    ull acc2[16];
    float bb = bias[t];
#pragma unroll
    for (int r = 0; r < 16; r++) acc2[r] = 0ull;

#pragma unroll 2
    for (int k4 = 0; k4 < 64; k4++) {
        int kk = k4 * 4;
        float w0 = wmat[(kk + 0) * 256 + t];
        float w1 = wmat[(kk + 1) * 256 + t];
        float w2 = wmat[(kk + 2) * 256 + t];
        float w3 = wmat[(kk + 3) * 256 + t];
        ull wp01 = pk2(w0, w1);
        ull wp23 = pk2(w2, w3);
#pragma unroll
        for (int r = 0; r < 16; r++) {
            ulonglong2 xv = *(const ulonglong2*)&xs[r * 256 + kk];
            ffma2(acc2[r], xv.x, wp01);
            ffma2(acc2[r], xv.y, wp23);
        }
    }
#pragma unroll
    for (int r = 0; r < 16; r++) {
        float lo, hi;
        upk2(acc2[r], lo, hi);
        ys[r * 257 + t] = lo + hi + bb;
    }
    __syncthreads();

    int w = t >> 5, lane = t & 31;
#pragma unroll
    for (int half = 0; half < 2; half++) {
        int rr = w + half * 8;
        float s = 0.f;
#pragma unroll
        for (int j = 0; j < 8; j++) s += ys[rr * 257 + lane + 32 * j];
        s = warpSum(s);
        float mu = s * (1.f / 256.f);
        float vs = 0.f;
#pragma unroll
        for (int j = 0; j < 8; j++) {
            float d = ys[rr * 257 + lane + 32 * j] - mu;
            vs += d * d;
        }
        vs = warpSum(vs);
        if (lane == 0) { mus[rr] = mu; rss[rr] = rsqrtf(vs * (1.f / 256.f) + 1e-6f); }
    }
    __syncthreads();

    float gt = g2[t], bt = b2[t];
#pragma unroll
    for (int r = 0; r < 16; r++) {
        out[(size_t)(r0 + r) * 256 + t] =
            (ys[r * 257 + t] - mus[r]) * rss[r] * gt + bt;
    }
}

// ===========================================================================
extern "C" void kernel_launch(void* const* d_in, const int* in_sizes, int n_in,
                              void* d_out, int out_size) {
    const float* x   = (const float*)d_in[0];
    const float* pm  = (const float*)d_in[1];
    const float* mm  = (const float*)d_in[2];
    const float* qp  = (const float*)d_in[3];
    const float* kp  = (const float*)d_in[4];
    const float* vp  = (const float*)d_in[5];
    const float* gp  = (const float*)d_in[6];
    const float* ow  = (const float*)d_in[7];
    const float* ob  = (const float*)d_in[8];
    const float* l1g = (const float*)d_in[9];
    const float* l1b = (const float*)d_in[10];
    const float* l2g = (const float*)d_in[11];
    const float* l2b = (const float*)d_in[12];
    float* out = (float*)d_out;

    cudaFuncSetAttribute(k_attn, cudaFuncAttributeMaxDynamicSharedMemorySize,
                         ATTN_SMEM);

    k_ln1 <<<BSs, 256>>>(x, l1g, l1b);
    k_qkvg<<<dim3(416, 16), 256>>>(qp, kp, vp, gp);
    k_attn<<<Bb * Hh, 256, ATTN_SMEM>>>(pm, mm);
    k_outln<<<BSs / 16, 256>>>(ow, ob, l2g, l2b, out);
}

// round 7
// speedup vs baseline: 2.2571x; 1.3166x over previous
#include <cuda_runtime.h>
#include <cuda_bf16.h>
#include <cstdint>

#define Bb   128
#define Ss   416
#define Nn   32
#define Mm   384
#define Dd   256
#define Hh   8
#define Ee   32
#define Oo   256
#define BSs  (Bb*Ss)          // 53248
#define NBH  (Bb*Hh*Ss*Ee)    // 13,631,488

// -------- scratch (static device globals; no runtime allocation) ----------
__device__ __nv_bfloat16 g_xh[BSs*Dd], g_xl[BSs*Dd];
__device__ __nv_bfloat16 g_wh[5*256*256], g_wl[5*256*256];  // [proj][n][k]; 4=out_w
__device__ __nv_bfloat16 g_qh[NBH], g_ql[NBH];
__device__ __nv_bfloat16 g_kh[NBH], g_kl[NBH];
__device__ __nv_bfloat16 g_vh[NBH], g_vl[NBH];
__device__ float         g_g [NBH];
__device__ __nv_bfloat16 g_aoh[BSs*Oo], g_aol[BSs*Oo];

__device__ __forceinline__ float warpSum(float v) {
#pragma unroll
    for (int o = 16; o; o >>= 1) v += __shfl_xor_sync(0xffffffffu, v, o);
    return v;
}
__device__ __forceinline__ float warpMax(float v) {
#pragma unroll
    for (int o = 16; o; o >>= 1) v = fmaxf(v, __shfl_xor_sync(0xffffffffu, v, o));
    return v;
}

// -------- mma.sync helpers --------------------------------------------------
__device__ __forceinline__ uint32_t smem_u32(const void* p) {
    uint32_t a;
    asm("{ .reg .u64 t; cvta.to.shared.u64 t, %1; cvt.u32.u64 %0, t; }"
        : "=r"(a) : "l"(p));
    return a;
}
__device__ __forceinline__ void ldsm4(uint32_t& r0, uint32_t& r1,
                                      uint32_t& r2, uint32_t& r3, uint32_t a) {
    asm volatile("ldmatrix.sync.aligned.m8n8.x4.shared.b16 {%0,%1,%2,%3}, [%4];"
                 : "=r"(r0), "=r"(r1), "=r"(r2), "=r"(r3) : "r"(a));
}
__device__ __forceinline__ void ldsm4t(uint32_t& r0, uint32_t& r1,
                                       uint32_t& r2, uint32_t& r3, uint32_t a) {
    asm volatile("ldmatrix.sync.aligned.m8n8.x4.trans.shared.b16 {%0,%1,%2,%3}, [%4];"
                 : "=r"(r0), "=r"(r1), "=r"(r2), "=r"(r3) : "r"(a));
}
__device__ __forceinline__ void ldsm2(uint32_t& r0, uint32_t& r1, uint32_t a) {
    asm volatile("ldmatrix.sync.aligned.m8n8.x2.shared.b16 {%0,%1}, [%2];"
                 : "=r"(r0), "=r"(r1) : "r"(a));
}
__device__ __forceinline__ void mma16816(float* d, const uint32_t* a,
                                         const uint32_t* b) {
    asm volatile(
        "mma.sync.aligned.m16n8k16.row.col.f32.bf16.bf16.f32 "
        "{%0,%1,%2,%3}, {%4,%5,%6,%7}, {%8,%9}, {%0,%1,%2,%3};"
        : "+f"(d[0]), "+f"(d[1]), "+f"(d[2]), "+f"(d[3])
        : "r"(a[0]), "r"(a[1]), "r"(a[2]), "r"(a[3]), "r"(b[0]), "r"(b[1]));
}
__device__ __forceinline__ void hilo(float v, __nv_bfloat16& h, __nv_bfloat16& l) {
    h = __float2bfloat16(v);
    l = __float2bfloat16(v - __bfloat162float(h));
}

// ========== Kernel 0: one-time weight conversion to hi/lo bf16 [n][k] ======
__global__ void k_wconv(const float* __restrict__ qp, const float* __restrict__ kp,
                        const float* __restrict__ vp, const float* __restrict__ gp,
                        const float* __restrict__ ow) {
    int n = blockIdx.x;          // 0..255
    int proj = blockIdx.y;       // 0..4
    int k = threadIdx.x;         // 0..255
    float v;
    if (proj < 4) {
        const float* Wp = (proj == 0) ? qp : (proj == 1) ? kp
                         : (proj == 2) ? vp : gp;
        v = Wp[(n >> 5) * 8192 + k * 32 + (n & 31)];
    } else {
        v = ow[k * 256 + n];
    }
    __nv_bfloat16 h, l;
    hilo(v, h, l);
    size_t idx = (size_t)(proj * 256 + n) * 256 + k;
    g_wh[idx] = h;
    g_wl[idx] = l;
}

// =================== Kernel 1: LayerNorm -> hi/lo bf16 =====================
__global__ void k_ln1(const float* __restrict__ x,
                      const float* __restrict__ gam,
                      const float* __restrict__ bet) {
    int row = blockIdx.x;
    int t = threadIdx.x;
    int w = t >> 5, lane = t & 31;
    __shared__ float red[8];

    float v = x[(size_t)row * Dd + t];
    float s = warpSum(v);
    if (lane == 0) red[w] = s;
    __syncthreads();
    float mu = 0.f;
#pragma unroll
    for (int i = 0; i < 8; i++) mu += red[i];
    mu *= (1.f / 256.f);
    float d = v - mu;
    __syncthreads();
    s = warpSum(d * d);
    if (lane == 0) red[w] = s;
    __syncthreads();
    float var = 0.f;
#pragma unroll
    for (int i = 0; i < 8; i++) var += red[i];
    var *= (1.f / 256.f);
    float r = d * rsqrtf(var + 1e-6f) * gam[t] + bet[t];
    __nv_bfloat16 h, l;
    hilo(r, h, l);
    g_xh[(size_t)row * Dd + t] = h;
    g_xl[(size_t)row * Dd + t] = l;
}

// ============ Kernel 2: QKVG projections via mma.sync bf16x3 ===============
__global__ void __launch_bounds__(256)
k_qkvg() {
    __shared__ __align__(16) __nv_bfloat16 Ahi[128 * 40];
    __shared__ __align__(16) __nv_bfloat16 Alo[128 * 40];
    __shared__ __align__(16) __nv_bfloat16 Bhi[64 * 40];
    __shared__ __align__(16) __nv_bfloat16 Blo[64 * 40];

    int tid = threadIdx.x;
    int wid = tid >> 5, lane = tid & 31;
    int wm = wid & 3, wn = wid >> 2;

    int m0 = blockIdx.x * 128;
    int n0 = blockIdx.y * 64;
    int proj = n0 >> 8;
    int nin = n0 & 255;

    uint32_t ahi_b = smem_u32(Ahi), alo_b = smem_u32(Alo);
    uint32_t bhi_b = smem_u32(Bhi), blo_b = smem_u32(Blo);

    float acc[2][4][4];
#pragma unroll
    for (int i = 0; i < 2; i++)
#pragma unroll
        for (int j = 0; j < 4; j++)
#pragma unroll
            for (int c = 0; c < 4; c++) acc[i][j][c] = 0.f;

    int a_row = (lane & 15);
    int a_kof = (lane >> 4) * 8;
    int b_row = ((lane >> 4) & 1) * 8 + (lane & 7);
    int b_kof = ((lane >> 3) & 1) * 8;

    for (int k0 = 0; k0 < 256; k0 += 32) {
        // stage A 128x32 hi/lo: pure 16B copies
#pragma unroll
        for (int it = 0; it < 2; it++) {
            int idx = tid + it * 256;
            int row = idx >> 2, q = idx & 3;
            *(uint4*)&Ahi[row * 40 + q * 8] =
                *(const uint4*)&g_xh[(size_t)(m0 + row) * 256 + k0 + q * 8];
            *(uint4*)&Alo[row * 40 + q * 8] =
                *(const uint4*)&g_xl[(size_t)(m0 + row) * 256 + k0 + q * 8];
        }
        // stage B 64x32 hi/lo
        {
            int n = tid >> 2, q = tid & 3;
            size_t src = (size_t)(proj * 256 + nin + n) * 256 + k0 + q * 8;
            *(uint4*)&Bhi[n * 40 + q * 8] = *(const uint4*)&g_wh[src];
            *(uint4*)&Blo[n * 40 + q * 8] = *(const uint4*)&g_wl[src];
        }
        __syncthreads();

#pragma unroll
        for (int ks = 0; ks < 2; ks++) {
            int kk = ks * 16;
            uint32_t ah[2][4], al[2][4];
#pragma unroll
            for (int mt = 0; mt < 2; mt++) {
                int row = wm * 32 + mt * 16 + a_row;
                uint32_t off = (uint32_t)(row * 40 + kk + a_kof) * 2;
                ldsm4(ah[mt][0], ah[mt][1], ah[mt][2], ah[mt][3], ahi_b + off);
                ldsm4(al[mt][0], al[mt][1], al[mt][2], al[mt][3], alo_b + off);
            }
            uint32_t bh[4][2], bl[4][2];
#pragma unroll
            for (int jp = 0; jp < 2; jp++) {
                int row = wn * 32 + jp * 16 + b_row;
                uint32_t off = (uint32_t)(row * 40 + kk + b_kof) * 2;
                ldsm4(bh[jp*2][0], bh[jp*2][1], bh[jp*2+1][0], bh[jp*2+1][1],
                      bhi_b + off);
                ldsm4(bl[jp*2][0], bl[jp*2][1], bl[jp*2+1][0], bl[jp*2+1][1],
                      blo_b + off);
            }
#pragma unroll
            for (int mt = 0; mt < 2; mt++)
#pragma unroll
                for (int j = 0; j < 4; j++) {
                    mma16816(acc[mt][j], ah[mt], bh[j]);
                    mma16816(acc[mt][j], ah[mt], bl[j]);
                    mma16816(acc[mt][j], al[mt], bh[j]);
                }
        }
        __syncthreads();
    }

    // ---- epilogue -> q/k/v hi/lo bf16, g fp32; layout [B,H,S,E] ----
    int h = (nin + wn * 32) >> 5;
    __nv_bfloat16* Oh = (proj == 0) ? g_qh : (proj == 1) ? g_kh : g_vh;
    __nv_bfloat16* Ol = (proj == 0) ? g_ql : (proj == 1) ? g_kl : g_vl;
    bool isG = (proj == 3);
#pragma unroll
    for (int mt = 0; mt < 2; mt++) {
        int m = m0 + wm * 32 + mt * 16 + (lane >> 2);
        int b1 = m / Ss, s1 = m - b1 * Ss;
        int m2 = m + 8;
        int b2 = m2 / Ss, s2 = m2 - b2 * Ss;
        size_t i1 = (((size_t)(b1 * Hh + h)) * Ss + s1) * Ee;
        size_t i2 = (((size_t)(b2 * Hh + h)) * Ss + s2) * Ee;
#pragma unroll
        for (int j = 0; j < 4; j++) {
            int e = j * 8 + (lane & 3) * 2;
            if (isG) {
                *(float2*)&g_g[i1 + e] = make_float2(acc[mt][j][0], acc[mt][j][1]);
                *(float2*)&g_g[i2 + e] = make_float2(acc[mt][j][2], acc[mt][j][3]);
            } else {
                __nv_bfloat162 h1, l1, h2, l2;
                hilo(acc[mt][j][0], h1.x, l1.x);
                hilo(acc[mt][j][1], h1.y, l1.y);
                hilo(acc[mt][j][2], h2.x, l2.x);
                hilo(acc[mt][j][3], h2.y, l2.y);
                *(__nv_bfloat162*)&Oh[i1 + e] = h1;
                *(__nv_bfloat162*)&Ol[i1 + e] = l1;
                *(__nv_bfloat162*)&Oh[i2 + e] = h2;
                *(__nv_bfloat162*)&Ol[i2 + e] = l2;
            }
        }
    }
}

// ============ Kernel 3: fused attention via mma.sync bf16x3 =================
#define KHI_OFF   0
#define KLO_OFF   (KHI_OFF + 416*40*2)     // 33280
#define VH_OFF    (KLO_OFF + 416*40*2)     // 66560  ([y][e], stride 40)
#define VL_OFF    (VH_OFF  + 416*40*2)     // 99840
#define ATT_OFF   (VL_OFF  + 416*40*2)     // 133120 (32x424 fp32 / bf16 overlay)
#define QHI_OFF   (ATT_OFF + 32*424*4)     // 187392
#define QLO_OFF   (QHI_OFF + 32*40*2)      // 189952
#define CSH_OFF   (QLO_OFF + 32*40*2)      // 192512
#define ATTN_SMEM (CSH_OFF + 416*4)        // 194176

__global__ void __launch_bounds__(256)
k_attn(const float* __restrict__ pmask, const float* __restrict__ mmask) {
    extern __shared__ char smc[];
    __nv_bfloat16* khi = (__nv_bfloat16*)(smc + KHI_OFF);
    __nv_bfloat16* klo = (__nv_bfloat16*)(smc + KLO_OFF);
    __nv_bfloat16* v_h = (__nv_bfloat16*)(smc + VH_OFF);
    __nv_bfloat16* v_l = (__nv_bfloat16*)(smc + VL_OFF);
    float*         att = (float*)(smc + ATT_OFF);
    __nv_bfloat16* athi = (__nv_bfloat16*)(smc + ATT_OFF);
    __nv_bfloat16* atlo = athi + 32 * 424;
    __nv_bfloat16* qhi = (__nv_bfloat16*)(smc + QHI_OFF);
    __nv_bfloat16* qlo = (__nv_bfloat16*)(smc + QLO_OFF);
    float*         c_sh = (float*)(smc + CSH_OFF);

    uint32_t khi_b = smem_u32(khi), klo_b = smem_u32(klo);
    uint32_t vh_b = smem_u32(v_h), vl_b = smem_u32(v_l);
    uint32_t ath_b = smem_u32(athi), atl_b = smem_u32(atlo);
    uint32_t qhi_b = smem_u32(qhi), qlo_b = smem_u32(qlo);

    int tid = threadIdx.x;
    int wid = tid >> 5, lane = tid & 31;
    int bh = blockIdx.x;
    int h = bh & 7, b = bh >> 3;
    size_t baseBH = (size_t)(b * Hh + h) * Ss;

    // ---- stage K and V hi/lo (pure 16B copies), [y][e-or-k] stride 40 ----
    for (int i = tid; i < Ss * 4; i += 256) {
        int y = i >> 2, q = i & 3;
        size_t src = (baseBH + y) * Ee + q * 8;
        *(uint4*)&khi[y * 40 + q * 8] = *(const uint4*)&g_kh[src];
        *(uint4*)&klo[y * 40 + q * 8] = *(const uint4*)&g_kl[src];
        *(uint4*)&v_h[y * 40 + q * 8] = *(const uint4*)&g_vh[src];
        *(uint4*)&v_l[y * 40 + q * 8] = *(const uint4*)&g_vl[src];
    }
    for (int i = tid; i < Ss; i += 256) {
        float val = (i < Nn) ? pmask[b * Nn + i] : mmask[b * Mm + (i - Nn)];
        c_sh[i] = (val == -2.0f) ? 0.f : 1.f;
    }
    __syncthreads();

    const float scale = 0.1767766952966369f;   // 1/sqrt(32)
    int a_row = (lane & 15);
    int a_kof = (lane >> 4) * 8;
    int b_row = ((lane >> 4) & 1) * 8 + (lane & 7);
    int b_kof = ((lane >> 3) & 1) * 8;

    int mh = wid & 1;          // QK: m-half
    int nq = wid >> 1;         // QK: n-quarter
    int nbase = nq * 104;
    int amh = wid >> 2;        // AV: m-half
    int ant = wid & 3;         // AV: n8 tile

    for (int tile = 0; tile < 13; tile++) {
        int x0 = tile * 32;
        // ---- stage Q tile hi/lo: one 16B copy per thread ----
        {
            int i = tid & 127;
            int xr = i >> 2, q = i & 3;
            size_t src = (baseBH + x0 + xr) * Ee + q * 8;
            if (tid < 128)
                *(uint4*)&qhi[xr * 40 + q * 8] = *(const uint4*)&g_qh[src];
            else
                *(uint4*)&qlo[xr * 40 + q * 8] = *(const uint4*)&g_ql[src];
        }
        __syncthreads();

        // ---- QK^T ----
        float acc[13][4];
#pragma unroll
        for (int t2 = 0; t2 < 13; t2++)
#pragma unroll
            for (int c = 0; c < 4; c++) acc[t2][c] = 0.f;

#pragma unroll
        for (int ks = 0; ks < 2; ks++) {
            int kk = ks * 16;
            uint32_t ah[4], al[4];
            {
                uint32_t off = (uint32_t)((mh * 16 + a_row) * 40 + kk + a_kof) * 2;
                ldsm4(ah[0], ah[1], ah[2], ah[3], qhi_b + off);
                ldsm4(al[0], al[1], al[2], al[3], qlo_b + off);
            }
#pragma unroll
            for (int jp = 0; jp < 6; jp++) {
                uint32_t bh2[4], bl2[4];
                uint32_t off = (uint32_t)((nbase + jp * 16 + b_row) * 40 + kk + b_kof) * 2;
                ldsm4(bh2[0], bh2[1], bh2[2], bh2[3], khi_b + off);
                ldsm4(bl2[0], bl2[1], bl2[2], bl2[3], klo_b + off);
                mma16816(acc[jp*2],   ah, &bh2[0]);
                mma16816(acc[jp*2],   ah, &bl2[0]);
                mma16816(acc[jp*2],   al, &bh2[0]);
                mma16816(acc[jp*2+1], ah, &bh2[2]);
                mma16816(acc[jp*2+1], ah, &bl2[2]);
                mma16816(acc[jp*2+1], al, &bh2[2]);
            }
            {
                uint32_t bh1[2], bl1[2];
                uint32_t off = (uint32_t)((nbase + 96 + (lane & 7)) * 40 + kk
                                          + 8 * ((lane >> 3) & 1)) * 2;
                ldsm2(bh1[0], bh1[1], khi_b + off);
                ldsm2(bl1[0], bl1[1], klo_b + off);
                mma16816(acc[12], ah, bh1);
                mma16816(acc[12], ah, bl1);
                mma16816(acc[12], al, bh1);
            }
        }

        // ---- mask/scale epilogue -> att fp32 ----
        bool xIsP = (x0 == 0);
        int lx1 = mh * 16 + (lane >> 2);
        int lx2 = lx1 + 8;
        float cx1 = c_sh[x0 + lx1];
        float cx2 = c_sh[x0 + lx2];
#pragma unroll
        for (int t2 = 0; t2 < 13; t2++) {
            int ybase = nbase + t2 * 8;
            int yc = ybase + (lane & 3) * 2;
            bool cross = (xIsP != (ybase < Nn));
            float cy0 = c_sh[yc], cy1 = c_sh[yc + 1];
            float m00 = cross ? cx1 * cy0 : 0.f;
            float m01 = cross ? cx1 * cy1 : 0.f;
            float m10 = cross ? cx2 * cy0 : 0.f;
            float m11 = cross ? cx2 * cy1 : 0.f;
            float2 r1 = make_float2(acc[t2][0] * scale + (1.f - m00) * (-1.0e9f),
                                    acc[t2][1] * scale + (1.f - m01) * (-1.0e9f));
            float2 r2 = make_float2(acc[t2][2] * scale + (1.f - m10) * (-1.0e9f),
                                    acc[t2][3] * scale + (1.f - m11) * (-1.0e9f));
            *(float2*)&att[lx1 * 424 + yc] = r1;
            *(float2*)&att[lx2 * 424 + yc] = r2;
        }
        __syncthreads();

        // ---- softmax ----
        float nv[4][13];
#pragma unroll
        for (int rr = 0; rr < 4; rr++) {
            int xr = wid + rr * 8;
            const float* row = att + xr * 424;
            float mx = -3.0e38f;
#pragma unroll
            for (int j = 0; j < 13; j++) mx = fmaxf(mx, row[lane + 32 * j]);
            mx = warpMax(mx);
            float ssum = 0.f;
#pragma unroll
            for (int j = 0; j < 13; j++) {
                nv[rr][j] = __expf(row[lane + 32 * j] - mx);
                ssum += nv[rr][j];
            }
            ssum = warpSum(ssum);
            float inv = c_sh[x0 + xr] / ssum;
#pragma unroll
            for (int j = 0; j < 13; j++) nv[rr][j] *= inv;
        }
        __syncthreads();

#pragma unroll
        for (int rr = 0; rr < 4; rr++) {
            int xr = wid + rr * 8;
#pragma unroll
            for (int j = 0; j < 13; j++) {
                __nv_bfloat16 hv, lv;
                hilo(nv[rr][j], hv, lv);
                athi[xr * 424 + lane + 32 * j] = hv;
                atlo[xr * 424 + lane + 32 * j] = lv;
            }
        }
        __syncthreads();

        // ---- AV: A = att (row-major), B = V via trans-ldsm on [y][e] ----
        float oacc[4] = {0.f, 0.f, 0.f, 0.f};
#pragma unroll
        for (int kc = 0; kc < 13; kc++) {
            int kk = kc * 32;
            uint32_t a0h[4], a0l[4], a1h[4], a1l[4];
            uint32_t offA0 = (uint32_t)((amh * 16 + a_row) * 424 + kk + a_kof) * 2;
            uint32_t offA1 = offA0 + 32;
            ldsm4(a0h[0], a0h[1], a0h[2], a0h[3], ath_b + offA0);
            ldsm4(a0l[0], a0l[1], a0l[2], a0l[3], atl_b + offA0);
            ldsm4(a1h[0], a1h[1], a1h[2], a1h[3], ath_b + offA1);
            ldsm4(a1l[0], a1l[1], a1l[2], a1l[3], atl_b + offA1);
            uint32_t bh4[4], bl4[4];
            uint32_t offB = (uint32_t)((kk + lane) * 40 + ant * 8) * 2;
            ldsm4t(bh4[0], bh4[1], bh4[2], bh4[3], vh_b + offB);
            ldsm4t(bl4[0], bl4[1], bl4[2], bl4[3], vl_b + offB);
            mma16816(oacc, a0h, &bh4[0]);
            mma16816(oacc, a0h, &bl4[0]);
            mma16816(oacc, a0l, &bh4[0]);
            mma16816(oacc, a1h, &bh4[2]);
            mma16816(oacc, a1h, &bl4[2]);
            mma16816(oacc, a1l, &bh4[2]);
        }

        // ---- gate + store hi/lo bf16 ----
        {
            int lx = amh * 16 + (lane >> 2);
            int e = ant * 8 + (lane & 3) * 2;
#pragma unroll
            for (int half = 0; half < 2; half++) {
                int xs_ = x0 + lx + half * 8;
                float2 gv = *(const float2*)&g_g[(baseBH + xs_) * Ee + e];
                float s0 = 1.f / (1.f + __expf(-gv.x));
                float s1 = 1.f / (1.f + __expf(-gv.y));
                float o0 = oacc[half * 2] * s0;
                float o1 = oacc[half * 2 + 1] * s1;
                __nv_bfloat162 oh, ol;
                hilo(o0, oh.x, ol.x);
                hilo(o1, oh.y, ol.y);
                size_t di = ((size_t)b * Ss + xs_) * Oo + h * Ee + e;
                *(__nv_bfloat162*)&g_aoh[di] = oh;
                *(__nv_bfloat162*)&g_aol[di] = ol;
            }
        }
        __syncthreads();
    }
}

// ============ Kernel 4: output projection (HMMA bf16x3) + LN2 ==============
#define OAHI_OFF 0                         // 32*40*2 = 2560
#define OALO_OFF 2560
#define OBHI_OFF 5120                      // 256*40*2 = 20480
#define OBLO_OFF 25600
#define OYS_OFF  46080                     // 32*264*4 = 33792
#define OMU_OFF  79872                     // 128
#define ORS_OFF  80000                     // 128
#define OLN_SMEM 80128

__global__ void __launch_bounds__(256)
k_outln(const float* __restrict__ bias, const float* __restrict__ g2,
        const float* __restrict__ b2, float* __restrict__ out) {
    extern __shared__ char smo[];
    __nv_bfloat16* Ahi = (__nv_bfloat16*)(smo + OAHI_OFF);
    __nv_bfloat16* Alo = (__nv_bfloat16*)(smo + OALO_OFF);
    __nv_bfloat16* Bhi = (__nv_bfloat16*)(smo + OBHI_OFF);
    __nv_bfloat16* Blo = (__nv_bfloat16*)(smo + OBLO_OFF);
    float* ys  = (float*)(smo + OYS_OFF);
    float* mus = (float*)(smo + OMU_OFF);
    float* rss = (float*)(smo + ORS_OFF);

    uint32_t ahi_b = smem_u32(Ahi), alo_b = smem_u32(Alo);
    uint32_t bhi_b = smem_u32(Bhi), blo_b = smem_u32(Blo);

    int tid = threadIdx.x;
    int wid = tid >> 5, lane = tid & 31;
    int mh = wid & 1, nq = wid >> 1;
    int r0 = blockIdx.x * 32;

    int a_row = (lane & 15);
    int a_kof = (lane >> 4) * 8;
    int b_row = ((lane >> 4) & 1) * 8 + (lane & 7);
    int b_kof = ((lane >> 3) & 1) * 8;

    float acc[8][4];
#pragma unroll
    for (int j = 0; j < 8; j++)
#pragma unroll
        for (int c = 0; c < 4; c++) acc[j][c] = 0.f;

    for (int k0 = 0; k0 < 256; k0 += 32) {
        // stage A 32x32 hi/lo
        {
            int i = tid & 127;
            int row = i >> 2, q = i & 3;
            size_t src = (size_t)(r0 + row) * 256 + k0 + q * 8;
            if (tid < 128)
                *(uint4*)&Ahi[row * 40 + q * 8] = *(const uint4*)&g_aoh[src];
            else
                *(uint4*)&Alo[row * 40 + q * 8] = *(const uint4*)&g_aol[src];
        }
        // stage B 256x32 hi/lo (out_w is proj slot 4)
#pragma unroll
        for (int it = 0; it < 8; it++) {
            int idx = tid + it * 256;     // 0..2047
            int rem = idx & 1023;
            int n = rem >> 2, q = rem & 3;
            size_t src = (size_t)(4 * 256 + n) * 256 + k0 + q * 8;
            if (idx < 1024)
                *(uint4*)&Bhi[n * 40 + q * 8] = *(const uint4*)&g_wh[src];
            else
                *(uint4*)&Blo[n * 40 + q * 8] = *(const uint4*)&g_wl[src];
        }
        __syncthreads();

#pragma unroll
        for (int ks = 0; ks < 2; ks++) {
            int kk = ks * 16;
            uint32_t ah[4], al[4];
            {
                uint32_t off = (uint32_t)((mh * 16 + a_row) * 40 + kk + a_kof) * 2;
                ldsm4(ah[0], ah[1], ah[2], ah[3], ahi_b + off);
                ldsm4(al[0], al[1], al[2], al[3], alo_b + off);
            }
#pragma unroll
            for (int jp = 0; jp < 4; jp++) {
                uint32_t bh2[4], bl2[4];
                uint32_t off = (uint32_t)((nq * 64 + jp * 16 + b_row) * 40 + kk + b_kof) * 2;
                ldsm4(bh2[0], bh2[1], bh2[2], bh2[3], bhi_b + off);
                ldsm4(bl2[0], bl2[1], bl2[2], bl2[3], blo_b + off);
                mma16816(acc[jp*2],   ah, &bh2[0]);
                mma16816(acc[jp*2],   ah, &bl2[0]);
                mma16816(acc[jp*2],   al, &bh2[0]);
                mma16816(acc[jp*2+1], ah, &bh2[2]);
                mma16816(acc[jp*2+1], ah, &bl2[2]);
                mma16816(acc[jp*2+1], al, &bh2[2]);
            }
        }
        __syncthreads();
    }

    // ---- epilogue: fragments + bias -> ys ----
    int lx1 = mh * 16 + (lane >> 2);
    int lx2 = lx1 + 8;
#pragma unroll
    for (int j = 0; j < 8; j++) {
        int n = nq * 64 + j * 8 + (lane & 3) * 2;
        float b0 = bias[n], b1 = bias[n + 1];
        ys[lx1 * 264 + n]     = acc[j][0] + b0;
        ys[lx1 * 264 + n + 1] = acc[j][1] + b1;
        ys[lx2 * 264 + n]     = acc[j][2] + b0;
        ys[lx2 * 264 + n + 1] = acc[j][3] + b1;
    }
    __syncthreads();

    // ---- LN2 ----
#pragma unroll
    for (int rr = 0; rr < 4; rr++) {
        int xr = wid + rr * 8;
        const float* row = ys + xr * 264;
        float s = 0.f;
#pragma unroll
        for (int j = 0; j < 8; j++) s += row[lane + 32 * j];
        s = warpSum(s);
        float mu = s * (1.f / 256.f);
        float vs = 0.f;
#pragma unroll
        for (int j = 0; j < 8; j++) {
            float d = row[lane + 32 * j] - mu;
            vs += d * d;
        }
        vs = warpSum(vs);
        if (lane == 0) { mus[xr] = mu; rss[xr] = rsqrtf(vs * (1.f / 256.f) + 1e-6f); }
    }
    __syncthreads();

    float gt = g2[tid], bt = b2[tid];
#pragma unroll 4
    for (int r = 0; r < 32; r++) {
        out[(size_t)(r0 + r) * 256 + tid] =
            (ys[r * 264 + tid] - mus[r]) * rss[r] * gt + bt;
    }
}

// ===========================================================================
extern "C" void kernel_launch(void* const* d_in, const int* in_sizes, int n_in,
                              void* d_out, int out_size) {
    const float* x   = (const float*)d_in[0];
    const float* pm  = (const float*)d_in[1];
    const float* mm  = (const float*)d_in[2];
    const float* qp  = (const float*)d_in[3];
    const float* kp  = (const float*)d_in[4];
    const float* vp  = (const float*)d_in[5];
    const float* gp  = (const float*)d_in[6];
    const float* ow  = (const float*)d_in[7];
    const float* ob  = (const float*)d_in[8];
    const float* l1g = (const float*)d_in[9];
    const float* l1b = (const float*)d_in[10];
    const float* l2g = (const float*)d_in[11];
    const float* l2b = (const float*)d_in[12];
    float* out = (float*)d_out;

    cudaFuncSetAttribute(k_attn, cudaFuncAttributeMaxDynamicSharedMemorySize,
                         ATTN_SMEM);
    cudaFuncSetAttribute(k_outln, cudaFuncAttributeMaxDynamicSharedMemorySize,
                         OLN_SMEM);

    k_wconv<<<dim3(256, 5), 256>>>(qp, kp, vp, gp, ow);
    k_ln1  <<<BSs, 256>>>(x, l1g, l1b);
    k_qkvg <<<dim3(416, 16), 256>>>();
    k_attn <<<Bb * Hh, 256, ATTN_SMEM>>>(pm, mm);
    k_outln<<<BSs / 32, 256, OLN_SMEM>>>(ob, l2g, l2b, out);
}

// round 8
// speedup vs baseline: 2.4678x; 1.0934x over previous
#include <cuda_runtime.h>
#include <cuda_bf16.h>
#include <cstdint>

#define Bb   128
#define Ss   416
#define Nn   32
#define Mm   384
#define Dd   256
#define Hh   8
#define Ee   32
#define Oo   256
#define BSs  (Bb*Ss)          // 53248
#define NBH  (Bb*Hh*Ss*Ee)    // 13,631,488

// -------- scratch (static device globals; no runtime allocation) ----------
__device__ __nv_bfloat16 g_xh[BSs*Dd], g_xl[BSs*Dd];
__device__ __nv_bfloat16 g_wh[5*256*256], g_wl[5*256*256];  // [proj][n][k]; 4=out_w
__device__ __nv_bfloat16 g_qh[NBH], g_ql[NBH];
__device__ __nv_bfloat16 g_kh[NBH], g_kl[NBH];
__device__ __nv_bfloat16 g_vh[NBH], g_vl[NBH];
__device__ float         g_g [NBH];
__device__ __nv_bfloat16 g_aoh[BSs*Oo], g_aol[BSs*Oo];

__device__ __forceinline__ float warpSum(float v) {
#pragma unroll
    for (int o = 16; o; o >>= 1) v += __shfl_xor_sync(0xffffffffu, v, o);
    return v;
}
__device__ __forceinline__ float warpMax(float v) {
#pragma unroll
    for (int o = 16; o; o >>= 1) v = fmaxf(v, __shfl_xor_sync(0xffffffffu, v, o));
    return v;
}

// -------- mma.sync helpers --------------------------------------------------
__device__ __forceinline__ uint32_t smem_u32(const void* p) {
    uint32_t a;
    asm("{ .reg .u64 t; cvta.to.shared.u64 t, %1; cvt.u32.u64 %0, t; }"
        : "=r"(a) : "l"(p));
    return a;
}
__device__ __forceinline__ void ldsm4(uint32_t& r0, uint32_t& r1,
                                      uint32_t& r2, uint32_t& r3, uint32_t a) {
    asm volatile("ldmatrix.sync.aligned.m8n8.x4.shared.b16 {%0,%1,%2,%3}, [%4];"
                 : "=r"(r0), "=r"(r1), "=r"(r2), "=r"(r3) : "r"(a));
}
__device__ __forceinline__ void ldsm4t(uint32_t& r0, uint32_t& r1,
                                       uint32_t& r2, uint32_t& r3, uint32_t a) {
    asm volatile("ldmatrix.sync.aligned.m8n8.x4.trans.shared.b16 {%0,%1,%2,%3}, [%4];"
                 : "=r"(r0), "=r"(r1), "=r"(r2), "=r"(r3) : "r"(a));
}
__device__ __forceinline__ void ldsm2(uint32_t& r0, uint32_t& r1, uint32_t a) {
    asm volatile("ldmatrix.sync.aligned.m8n8.x2.shared.b16 {%0,%1}, [%2];"
                 : "=r"(r0), "=r"(r1) : "r"(a));
}
__device__ __forceinline__ void mma16816(float* d, const uint32_t* a,
                                         const uint32_t* b) {
    asm volatile(
        "mma.sync.aligned.m16n8k16.row.col.f32.bf16.bf16.f32 "
        "{%0,%1,%2,%3}, {%4,%5,%6,%7}, {%8,%9}, {%0,%1,%2,%3};"
        : "+f"(d[0]), "+f"(d[1]), "+f"(d[2]), "+f"(d[3])
        : "r"(a[0]), "r"(a[1]), "r"(a[2]), "r"(a[3]), "r"(b[0]), "r"(b[1]));
}
__device__ __forceinline__ void hilo(float v, __nv_bfloat16& h, __nv_bfloat16& l) {
    h = __float2bfloat16(v);
    l = __float2bfloat16(v - __bfloat162float(h));
}

// ========== Kernel 0: one-time weight conversion to hi/lo bf16 [n][k] ======
__global__ void k_wconv(const float* __restrict__ qp, const float* __restrict__ kp,
                        const float* __restrict__ vp, const float* __restrict__ gp,
                        const float* __restrict__ ow) {
    int n = blockIdx.x;
    int proj = blockIdx.y;
    int k = threadIdx.x;
    float v;
    if (proj < 4) {
        const float* Wp = (proj == 0) ? qp : (proj == 1) ? kp
                         : (proj == 2) ? vp : gp;
        v = Wp[(n >> 5) * 8192 + k * 32 + (n & 31)];
    } else {
        v = ow[k * 256 + n];
    }
    __nv_bfloat16 h, l;
    hilo(v, h, l);
    size_t idx = (size_t)(proj * 256 + n) * 256 + k;
    g_wh[idx] = h;
    g_wl[idx] = l;
}

// =================== Kernel 1: LayerNorm -> hi/lo bf16 =====================
__global__ void k_ln1(const float* __restrict__ x,
                      const float* __restrict__ gam,
                      const float* __restrict__ bet) {
    int row = blockIdx.x;
    int t = threadIdx.x;
    int w = t >> 5, lane = t & 31;
    __shared__ float red[8];

    float v = x[(size_t)row * Dd + t];
    float s = warpSum(v);
    if (lane == 0) red[w] = s;
    __syncthreads();
    float mu = 0.f;
#pragma unroll
    for (int i = 0; i < 8; i++) mu += red[i];
    mu *= (1.f / 256.f);
    float d = v - mu;
    __syncthreads();
    s = warpSum(d * d);
    if (lane == 0) red[w] = s;
    __syncthreads();
    float var = 0.f;
#pragma unroll
    for (int i = 0; i < 8; i++) var += red[i];
    var *= (1.f / 256.f);
    float r = d * rsqrtf(var + 1e-6f) * gam[t] + bet[t];
    __nv_bfloat16 h, l;
    hilo(r, h, l);
    g_xh[(size_t)row * Dd + t] = h;
    g_xl[(size_t)row * Dd + t] = l;
}

// ============ Kernel 2: QKVG projections via mma.sync bf16x3 ===============
__global__ void __launch_bounds__(256)
k_qkvg() {
    __shared__ __align__(16) __nv_bfloat16 Ahi[128 * 40];
    __shared__ __align__(16) __nv_bfloat16 Alo[128 * 40];
    __shared__ __align__(16) __nv_bfloat16 Bhi[64 * 40];
    __shared__ __align__(16) __nv_bfloat16 Blo[64 * 40];

    int tid = threadIdx.x;
    int wid = tid >> 5, lane = tid & 31;
    int wm = wid & 3, wn = wid >> 2;

    int m0 = blockIdx.x * 128;
    int n0 = blockIdx.y * 64;
    int proj = n0 >> 8;
    int nin = n0 & 255;

    uint32_t ahi_b = smem_u32(Ahi), alo_b = smem_u32(Alo);
    uint32_t bhi_b = smem_u32(Bhi), blo_b = smem_u32(Blo);

    float acc[2][4][4];
#pragma unroll
    for (int i = 0; i < 2; i++)
#pragma unroll
        for (int j = 0; j < 4; j++)
#pragma unroll
            for (int c = 0; c < 4; c++) acc[i][j][c] = 0.f;

    int a_row = (lane & 15);
    int a_kof = (lane >> 4) * 8;
    int b_row = ((lane >> 4) & 1) * 8 + (lane & 7);
    int b_kof = ((lane >> 3) & 1) * 8;

    for (int k0 = 0; k0 < 256; k0 += 32) {
#pragma unroll
        for (int it = 0; it < 2; it++) {
            int idx = tid + it * 256;
            int row = idx >> 2, q = idx & 3;
            *(uint4*)&Ahi[row * 40 + q * 8] =
                *(const uint4*)&g_xh[(size_t)(m0 + row) * 256 + k0 + q * 8];
            *(uint4*)&Alo[row * 40 + q * 8] =
                *(const uint4*)&g_xl[(size_t)(m0 + row) * 256 + k0 + q * 8];
        }
        {
            int n = tid >> 2, q = tid & 3;
            size_t src = (size_t)(proj * 256 + nin + n) * 256 + k0 + q * 8;
            *(uint4*)&Bhi[n * 40 + q * 8] = *(const uint4*)&g_wh[src];
            *(uint4*)&Blo[n * 40 + q * 8] = *(const uint4*)&g_wl[src];
        }
        __syncthreads();

#pragma unroll
        for (int ks = 0; ks < 2; ks++) {
            int kk = ks * 16;
            uint32_t ah[2][4], al[2][4];
#pragma unroll
            for (int mt = 0; mt < 2; mt++) {
                int row = wm * 32 + mt * 16 + a_row;
                uint32_t off = (uint32_t)(row * 40 + kk + a_kof) * 2;
                ldsm4(ah[mt][0], ah[mt][1], ah[mt][2], ah[mt][3], ahi_b + off);
                ldsm4(al[mt][0], al[mt][1], al[mt][2], al[mt][3], alo_b + off);
            }
            uint32_t bh[4][2], bl[4][2];
#pragma unroll
            for (int jp = 0; jp < 2; jp++) {
                int row = wn * 32 + jp * 16 + b_row;
                uint32_t off = (uint32_t)(row * 40 + kk + b_kof) * 2;
                ldsm4(bh[jp*2][0], bh[jp*2][1], bh[jp*2+1][0], bh[jp*2+1][1],
                      bhi_b + off);
                ldsm4(bl[jp*2][0], bl[jp*2][1], bl[jp*2+1][0], bl[jp*2+1][1],
                      blo_b + off);
            }
#pragma unroll
            for (int mt = 0; mt < 2; mt++)
#pragma unroll
                for (int j = 0; j < 4; j++) {
                    mma16816(acc[mt][j], ah[mt], bh[j]);
                    mma16816(acc[mt][j], ah[mt], bl[j]);
                    mma16816(acc[mt][j], al[mt], bh[j]);
                }
        }
        __syncthreads();
    }

    int h = (nin + wn * 32) >> 5;
    __nv_bfloat16* Oh = (proj == 0) ? g_qh : (proj == 1) ? g_kh : g_vh;
    __nv_bfloat16* Ol = (proj == 0) ? g_ql : (proj == 1) ? g_kl : g_vl;
    bool isG = (proj == 3);
#pragma unroll
    for (int mt = 0; mt < 2; mt++) {
        int m = m0 + wm * 32 + mt * 16 + (lane >> 2);
        int b1 = m / Ss, s1 = m - b1 * Ss;
        int m2 = m + 8;
        int b2 = m2 / Ss, s2 = m2 - b2 * Ss;
        size_t i1 = (((size_t)(b1 * Hh + h)) * Ss + s1) * Ee;
        size_t i2 = (((size_t)(b2 * Hh + h)) * Ss + s2) * Ee;
#pragma unroll
        for (int j = 0; j < 4; j++) {
            int e = j * 8 + (lane & 3) * 2;
            if (isG) {
                *(float2*)&g_g[i1 + e] = make_float2(acc[mt][j][0], acc[mt][j][1]);
                *(float2*)&g_g[i2 + e] = make_float2(acc[mt][j][2], acc[mt][j][3]);
            } else {
                __nv_bfloat162 h1, l1, h2, l2;
                hilo(acc[mt][j][0], h1.x, l1.x);
                hilo(acc[mt][j][1], h1.y, l1.y);
                hilo(acc[mt][j][2], h2.x, l2.x);
                hilo(acc[mt][j][3], h2.y, l2.y);
                *(__nv_bfloat162*)&Oh[i1 + e] = h1;
                *(__nv_bfloat162*)&Ol[i1 + e] = l1;
                *(__nv_bfloat162*)&Oh[i2 + e] = h2;
                *(__nv_bfloat162*)&Ol[i2 + e] = l2;
            }
        }
    }
}

// ============ Kernel 3: fused attention; register softmax ==================
#define KHI_OFF   0
#define KLO_OFF   (KHI_OFF + 416*40*2)     // 33280
#define VH_OFF    (KLO_OFF + 416*40*2)     // 66560  ([y][e], stride 40)
#define VL_OFF    (VH_OFF  + 416*40*2)     // 99840
#define ATH_OFF   (VL_OFF  + 416*40*2)     // 133120 (32x424 bf16 hi)
#define ATL_OFF   (ATH_OFF + 32*424*2)     // 160256 (32x424 bf16 lo)
#define QHI_OFF   (ATL_OFF + 32*424*2)     // 187392
#define QLO_OFF   (QHI_OFF + 32*40*2)      // 189952
#define CSH_OFF   (QLO_OFF + 32*40*2)      // 192512
#define RED_OFF   (CSH_OFF + 416*4)        // 194176 (32 rows x 8 floats)
#define ATTN_SMEM (RED_OFF + 32*8*4)       // 195200

__global__ void __launch_bounds__(256)
k_attn(const float* __restrict__ pmask, const float* __restrict__ mmask) {
    extern __shared__ char smc[];
    __nv_bfloat16* khi = (__nv_bfloat16*)(smc + KHI_OFF);
    __nv_bfloat16* klo = (__nv_bfloat16*)(smc + KLO_OFF);
    __nv_bfloat16* v_h = (__nv_bfloat16*)(smc + VH_OFF);
    __nv_bfloat16* v_l = (__nv_bfloat16*)(smc + VL_OFF);
    __nv_bfloat16* athi = (__nv_bfloat16*)(smc + ATH_OFF);
    __nv_bfloat16* atlo = (__nv_bfloat16*)(smc + ATL_OFF);
    __nv_bfloat16* qhi = (__nv_bfloat16*)(smc + QHI_OFF);
    __nv_bfloat16* qlo = (__nv_bfloat16*)(smc + QLO_OFF);
    float*         c_sh = (float*)(smc + CSH_OFF);
    float*         red  = (float*)(smc + RED_OFF);   // [row][nq*2 + {m,s}]

    uint32_t khi_b = smem_u32(khi), klo_b = smem_u32(klo);
    uint32_t vh_b = smem_u32(v_h), vl_b = smem_u32(v_l);
    uint32_t ath_b = smem_u32(athi), atl_b = smem_u32(atlo);
    uint32_t qhi_b = smem_u32(qhi), qlo_b = smem_u32(qlo);

    int tid = threadIdx.x;
    int wid = tid >> 5, lane = tid & 31;
    int bh = blockIdx.x;
    int h = bh & 7, b = bh >> 3;
    size_t baseBH = (size_t)(b * Hh + h) * Ss;

    for (int i = tid; i < Ss * 4; i += 256) {
        int y = i >> 2, q = i & 3;
        size_t src = (baseBH + y) * Ee + q * 8;
        *(uint4*)&khi[y * 40 + q * 8] = *(const uint4*)&g_kh[src];
        *(uint4*)&klo[y * 40 + q * 8] = *(const uint4*)&g_kl[src];
        *(uint4*)&v_h[y * 40 + q * 8] = *(const uint4*)&g_vh[src];
        *(uint4*)&v_l[y * 40 + q * 8] = *(const uint4*)&g_vl[src];
    }
    for (int i = tid; i < Ss; i += 256) {
        float val = (i < Nn) ? pmask[b * Nn + i] : mmask[b * Mm + (i - Nn)];
        c_sh[i] = (val == -2.0f) ? 0.f : 1.f;
    }
    __syncthreads();

    const float scale = 0.1767766952966369f;   // 1/sqrt(32)
    int a_row = (lane & 15);
    int a_kof = (lane >> 4) * 8;
    int b_row = ((lane >> 4) & 1) * 8 + (lane & 7);
    int b_kof = ((lane >> 3) & 1) * 8;

    int mh = wid & 1;          // QK: m-half
    int nq = wid >> 1;         // QK: n-quarter
    int nbase = nq * 104;
    int amh = wid >> 2;        // AV: m-half
    int ant = wid & 3;         // AV: n8 tile

    for (int tile = 0; tile < 13; tile++) {
        int x0 = tile * 32;
        {
            int i = tid & 127;
            int xr = i >> 2, q = i & 3;
            size_t src = (baseBH + x0 + xr) * Ee + q * 8;
            if (tid < 128)
                *(uint4*)&qhi[xr * 40 + q * 8] = *(const uint4*)&g_qh[src];
            else
                *(uint4*)&qlo[xr * 40 + q * 8] = *(const uint4*)&g_ql[src];
        }
        __syncthreads();

        // ---- QK^T ----
        float acc[13][4];
#pragma unroll
        for (int t2 = 0; t2 < 13; t2++)
#pragma unroll
            for (int c = 0; c < 4; c++) acc[t2][c] = 0.f;

#pragma unroll
        for (int ks = 0; ks < 2; ks++) {
            int kk = ks * 16;
            uint32_t ah[4], al[4];
            {
                uint32_t off = (uint32_t)((mh * 16 + a_row) * 40 + kk + a_kof) * 2;
                ldsm4(ah[0], ah[1], ah[2], ah[3], qhi_b + off);
                ldsm4(al[0], al[1], al[2], al[3], qlo_b + off);
            }
#pragma unroll
            for (int jp = 0; jp < 6; jp++) {
                uint32_t bh2[4], bl2[4];
                uint32_t off = (uint32_t)((nbase + jp * 16 + b_row) * 40 + kk + b_kof) * 2;
                ldsm4(bh2[0], bh2[1], bh2[2], bh2[3], khi_b + off);
                ldsm4(bl2[0], bl2[1], bl2[2], bl2[3], klo_b + off);
                mma16816(acc[jp*2],   ah, &bh2[0]);
                mma16816(acc[jp*2],   ah, &bl2[0]);
                mma16816(acc[jp*2],   al, &bh2[0]);
                mma16816(acc[jp*2+1], ah, &bh2[2]);
                mma16816(acc[jp*2+1], ah, &bl2[2]);
                mma16816(acc[jp*2+1], al, &bh2[2]);
            }
            {
                uint32_t bh1[2], bl1[2];
                uint32_t off = (uint32_t)((nbase + 96 + (lane & 7)) * 40 + kk
                                          + 8 * ((lane >> 3) & 1)) * 2;
                ldsm2(bh1[0], bh1[1], khi_b + off);
                ldsm2(bl1[0], bl1[1], klo_b + off);
                mma16816(acc[12], ah, bh1);
                mma16816(acc[12], ah, bl1);
                mma16816(acc[12], al, bh1);
            }
        }

        // ---- mask/scale in registers ----
        bool xIsP = (x0 == 0);
        int lx1 = mh * 16 + (lane >> 2);
        int lx2 = lx1 + 8;
        float cx1 = c_sh[x0 + lx1];
        float cx2 = c_sh[x0 + lx2];
#pragma unroll
        for (int t2 = 0; t2 < 13; t2++) {
            int ybase = nbase + t2 * 8;
            int yc = ybase + (lane & 3) * 2;
            bool cross = (xIsP != (ybase < Nn));
            float cy0 = c_sh[yc], cy1 = c_sh[yc + 1];
            float m00 = cross ? cx1 * cy0 : 0.f;
            float m01 = cross ? cx1 * cy1 : 0.f;
            float m10 = cross ? cx2 * cy0 : 0.f;
            float m11 = cross ? cx2 * cy1 : 0.f;
            acc[t2][0] = acc[t2][0] * scale + (1.f - m00) * (-1.0e9f);
            acc[t2][1] = acc[t2][1] * scale + (1.f - m01) * (-1.0e9f);
            acc[t2][2] = acc[t2][2] * scale + (1.f - m10) * (-1.0e9f);
            acc[t2][3] = acc[t2][3] * scale + (1.f - m11) * (-1.0e9f);
        }

        // ---- register softmax: local slice max ----
        float m1 = -3.0e38f, m2 = -3.0e38f;
#pragma unroll
        for (int t2 = 0; t2 < 13; t2++) {
            m1 = fmaxf(m1, fmaxf(acc[t2][0], acc[t2][1]));
            m2 = fmaxf(m2, fmaxf(acc[t2][2], acc[t2][3]));
        }
#pragma unroll
        for (int o = 1; o <= 2; o <<= 1) {
            m1 = fmaxf(m1, __shfl_xor_sync(0xffffffffu, m1, o));
            m2 = fmaxf(m2, __shfl_xor_sync(0xffffffffu, m2, o));
        }
        // exp in regs + local sums
        float s1 = 0.f, s2 = 0.f;
#pragma unroll
        for (int t2 = 0; t2 < 13; t2++) {
            acc[t2][0] = __expf(acc[t2][0] - m1);
            acc[t2][1] = __expf(acc[t2][1] - m1);
            acc[t2][2] = __expf(acc[t2][2] - m2);
            acc[t2][3] = __expf(acc[t2][3] - m2);
            s1 += acc[t2][0] + acc[t2][1];
            s2 += acc[t2][2] + acc[t2][3];
        }
#pragma unroll
        for (int o = 1; o <= 2; o <<= 1) {
            s1 += __shfl_xor_sync(0xffffffffu, s1, o);
            s2 += __shfl_xor_sync(0xffffffffu, s2, o);
        }
        // one cross-warp exchange: (m, s) per slice
        if ((lane & 3) == 0) {
            red[lx1 * 8 + nq * 2]     = m1;
            red[lx1 * 8 + nq * 2 + 1] = s1;
            red[lx2 * 8 + nq * 2]     = m2;
            red[lx2 * 8 + nq * 2 + 1] = s2;
        }
        __syncthreads();
        float M1 = -3.0e38f, M2 = -3.0e38f;
#pragma unroll
        for (int q = 0; q < 4; q++) {
            M1 = fmaxf(M1, red[lx1 * 8 + q * 2]);
            M2 = fmaxf(M2, red[lx2 * 8 + q * 2]);
        }
        float S1 = 0.f, S2 = 0.f;
#pragma unroll
        for (int q = 0; q < 4; q++) {
            S1 += red[lx1 * 8 + q * 2 + 1] * __expf(red[lx1 * 8 + q * 2] - M1);
            S2 += red[lx2 * 8 + q * 2 + 1] * __expf(red[lx2 * 8 + q * 2] - M2);
        }
        float f1 = cx1 * __expf(m1 - M1) / S1;
        float f2 = cx2 * __expf(m2 - M2) / S2;

        // ---- emit att bf16 hi/lo directly from regs ----
#pragma unroll
        for (int t2 = 0; t2 < 13; t2++) {
            int yc = nbase + t2 * 8 + (lane & 3) * 2;
            __nv_bfloat162 h1v, l1v, h2v, l2v;
            hilo(acc[t2][0] * f1, h1v.x, l1v.x);
            hilo(acc[t2][1] * f1, h1v.y, l1v.y);
            hilo(acc[t2][2] * f2, h2v.x, l2v.x);
            hilo(acc[t2][3] * f2, h2v.y, l2v.y);
            *(__nv_bfloat162*)&athi[lx1 * 424 + yc] = h1v;
            *(__nv_bfloat162*)&atlo[lx1 * 424 + yc] = l1v;
            *(__nv_bfloat162*)&athi[lx2 * 424 + yc] = h2v;
            *(__nv_bfloat162*)&atlo[lx2 * 424 + yc] = l2v;
        }
        __syncthreads();

        // ---- AV: 6 independent accumulators (chain depth 13) ----
        float oa[6][4];
#pragma unroll
        for (int i = 0; i < 6; i++)
#pragma unroll
            for (int c = 0; c < 4; c++) oa[i][c] = 0.f;
#pragma unroll
        for (int kc = 0; kc < 13; kc++) {
            int kk = kc * 32;
            uint32_t a0h[4], a0l[4], a1h[4], a1l[4];
            uint32_t offA0 = (uint32_t)((amh * 16 + a_row) * 424 + kk + a_kof) * 2;
            uint32_t offA1 = offA0 + 32;
            ldsm4(a0h[0], a0h[1], a0h[2], a0h[3], ath_b + offA0);
            ldsm4(a0l[0], a0l[1], a0l[2], a0l[3], atl_b + offA0);
            ldsm4(a1h[0], a1h[1], a1h[2], a1h[3], ath_b + offA1);
            ldsm4(a1l[0], a1l[1], a1l[2], a1l[3], atl_b + offA1);
            uint32_t bh4[4], bl4[4];
            uint32_t offB = (uint32_t)((kk + lane) * 40 + ant * 8) * 2;
            ldsm4t(bh4[0], bh4[1], bh4[2], bh4[3], vh_b + offB);
            ldsm4t(bl4[0], bl4[1], bl4[2], bl4[3], vl_b + offB);
            mma16816(oa[0], a0h, &bh4[0]);
            mma16816(oa[1], a0h, &bl4[0]);
            mma16816(oa[2], a0l, &bh4[0]);
            mma16816(oa[3], a1h, &bh4[2]);
            mma16816(oa[4], a1h, &bl4[2]);
            mma16816(oa[5], a1l, &bh4[2]);
        }
        float oacc[4];
#pragma unroll
        for (int c = 0; c < 4; c++)
            oacc[c] = (oa[0][c] + oa[1][c]) + (oa[2][c] + oa[3][c])
                    + (oa[4][c] + oa[5][c]);

        // ---- gate + store hi/lo bf16 ----
        {
            int lx = amh * 16 + (lane >> 2);
            int e = ant * 8 + (lane & 3) * 2;
#pragma unroll
            for (int half = 0; half < 2; half++) {
                int xs_ = x0 + lx + half * 8;
                float2 gv = *(const float2*)&g_g[(baseBH + xs_) * Ee + e];
                float s0 = 1.f / (1.f + __expf(-gv.x));
                float s1g = 1.f / (1.f + __expf(-gv.y));
                float o0 = oacc[half * 2] * s0;
                float o1 = oacc[half * 2 + 1] * s1g;
                __nv_bfloat162 oh, ol;
                hilo(o0, oh.x, ol.x);
                hilo(o1, oh.y, ol.y);
                size_t di = ((size_t)b * Ss + xs_) * Oo + h * Ee + e;
                *(__nv_bfloat162*)&g_aoh[di] = oh;
                *(__nv_bfloat162*)&g_aol[di] = ol;
            }
        }
        __syncthreads();
    }
}

// ============ Kernel 4: output projection (HMMA bf16x3) + LN2 ==============
#define OAHI_OFF 0
#define OALO_OFF 2560
#define OBHI_OFF 5120
#define OBLO_OFF 25600
#define OYS_OFF  46080
#define OMU_OFF  79872
#define ORS_OFF  80000
#define OLN_SMEM 80128

__global__ void __launch_bounds__(256)
k_outln(const float* __restrict__ bias, const float* __restrict__ g2,
        const float* __restrict__ b2, float* __restrict__ out) {
    extern __shared__ char smo[];
    __nv_bfloat16* Ahi = (__nv_bfloat16*)(smo + OAHI_OFF);
    __nv_bfloat16* Alo = (__nv_bfloat16*)(smo + OALO_OFF);
    __nv_bfloat16* Bhi = (__nv_bfloat16*)(smo + OBHI_OFF);
    __nv_bfloat16* Blo = (__nv_bfloat16*)(smo + OBLO_OFF);
    float* ys  = (float*)(smo + OYS_OFF);
    float* mus = (float*)(smo + OMU_OFF);
    float* rss = (float*)(smo + ORS_OFF);

    uint32_t ahi_b = smem_u32(Ahi), alo_b = smem_u32(Alo);
    uint32_t bhi_b = smem_u32(Bhi), blo_b = smem_u32(Blo);

    int tid = threadIdx.x;
    int wid = tid >> 5, lane = tid & 31;
    int mh = wid & 1, nq = wid >> 1;
    int r0 = blockIdx.x * 32;

    int a_row = (lane & 15);
    int a_kof = (lane >> 4) * 8;
    int b_row = ((lane >> 4) & 1) * 8 + (lane & 7);
    int b_kof = ((lane >> 3) & 1) * 8;

    float acc[8][4];
#pragma unroll
    for (int j = 0; j < 8; j++)
#pragma unroll
        for (int c = 0; c < 4; c++) acc[j][c] = 0.f;

    for (int k0 = 0; k0 < 256; k0 += 32) {
        {
            int i = tid & 127;
            int row = i >> 2, q = i & 3;
            size_t src = (size_t)(r0 + row) * 256 + k0 + q * 8;
            if (tid < 128)
                *(uint4*)&Ahi[row * 40 + q * 8] = *(const uint4*)&g_aoh[src];
            else
                *(uint4*)&Alo[row * 40 + q * 8] = *(const uint4*)&g_aol[src];
        }
#pragma unroll
        for (int it = 0; it < 8; it++) {
            int idx = tid + it * 256;
            int rem = idx & 1023;
            int n = rem >> 2, q = rem & 3;
            size_t src = (size_t)(4 * 256 + n) * 256 + k0 + q * 8;
            if (idx < 1024)
                *(uint4*)&Bhi[n * 40 + q * 8] = *(const uint4*)&g_wh[src];
            else
                *(uint4*)&Blo[n * 40 + q * 8] = *(const uint4*)&g_wl[src];
        }
        __syncthreads();

#pragma unroll
        for (int ks = 0; ks < 2; ks++) {
            int kk = ks * 16;
            uint32_t ah[4], al[4];
            {
                uint32_t off = (uint32_t)((mh * 16 + a_row) * 40 + kk + a_kof) * 2;
                ldsm4(ah[0], ah[1], ah[2], ah[3], ahi_b + off);
                ldsm4(al[0], al[1], al[2], al[3], alo_b + off);
            }
#pragma unroll
            for (int jp = 0; jp < 4; jp++) {
                uint32_t bh2[4], bl2[4];
                uint32_t off = (uint32_t)((nq * 64 + jp * 16 + b_row) * 40 + kk + b_kof) * 2;
                ldsm4(bh2[0], bh2[1], bh2[2], bh2[3], bhi_b + off);
                ldsm4(bl2[0], bl2[1], bl2[2], bl2[3], blo_b + off);
                mma16816(acc[jp*2],   ah, &bh2[0]);
                mma16816(acc[jp*2],   ah, &bl2[0]);
                mma16816(acc[jp*2],   al, &bh2[0]);
                mma16816(acc[jp*2+1], ah, &bh2[2]);
                mma16816(acc[jp*2+1], ah, &bl2[2]);
                mma16816(acc[jp*2+1], al, &bh2[2]);
            }
        }
        __syncthreads();
    }

    int lx1 = mh * 16 + (lane >> 2);
    int lx2 = lx1 + 8;
#pragma unroll
    for (int j = 0; j < 8; j++) {
        int n = nq * 64 + j * 8 + (lane & 3) * 2;
        float b0 = bias[n], b1 = bias[n + 1];
        ys[lx1 * 264 + n]     = acc[j][0] + b0;
        ys[lx1 * 264 + n + 1] = acc[j][1] + b1;
        ys[lx2 * 264 + n]     = acc[j][2] + b0;
        ys[lx2 * 264 + n + 1] = acc[j][3] + b1;
    }
    __syncthreads();

#pragma unroll
    for (int rr = 0; rr < 4; rr++) {
        int xr = wid + rr * 8;
        const float* row = ys + xr * 264;
        float s = 0.f;
#pragma unroll
        for (int j = 0; j < 8; j++) s += row[lane + 32 * j];
        s = warpSum(s);
        float mu = s * (1.f / 256.f);
        float vs = 0.f;
#pragma unroll
        for (int j = 0; j < 8; j++) {
            float d = row[lane + 32 * j] - mu;
            vs += d * d;
        }
        vs = warpSum(vs);
        if (lane == 0) { mus[xr] = mu; rss[xr] = rsqrtf(vs * (1.f / 256.f) + 1e-6f); }
    }
    __syncthreads();

    float gt = g2[tid], bt = b2[tid];
#pragma unroll 4
    for (int r = 0; r < 32; r++) {
        out[(size_t)(r0 + r) * 256 + tid] =
            (ys[r * 264 + tid] - mus[r]) * rss[r] * gt + bt;
    }
}

// ===========================================================================
extern "C" void kernel_launch(void* const* d_in, const int* in_sizes, int n_in,
                              void* d_out, int out_size) {
    const float* x   = (const float*)d_in[0];
    const float* pm  = (const float*)d_in[1];
    const float* mm  = (const float*)d_in[2];
    const float* qp  = (const float*)d_in[3];
    const float* kp  = (const float*)d_in[4];
    const float* vp  = (const float*)d_in[5];
    const float* gp  = (const float*)d_in[6];
    const float* ow  = (const float*)d_in[7];
    const float* ob  = (const float*)d_in[8];
    const float* l1g = (const float*)d_in[9];
    const float* l1b = (const float*)d_in[10];
    const float* l2g = (const float*)d_in[11];
    const float* l2b = (const float*)d_in[12];
    float* out = (float*)d_out;

    cudaFuncSetAttribute(k_attn, cudaFuncAttributeMaxDynamicSharedMemorySize,
                         ATTN_SMEM);
    cudaFuncSetAttribute(k_outln, cudaFuncAttributeMaxDynamicSharedMemorySize,
                         OLN_SMEM);

    k_wconv<<<dim3(256, 5), 256>>>(qp, kp, vp, gp, ow);
    k_ln1  <<<BSs, 256>>>(x, l1g, l1b);
    k_qkvg <<<dim3(416, 16), 256>>>();
    k_attn <<<Bb * Hh, 256, ATTN_SMEM>>>(pm, mm);
    k_outln<<<BSs / 32, 256, OLN_SMEM>>>(ob, l2g, l2b, out);
}

// round 9
// speedup vs baseline: 2.7049x; 1.0961x over previous
#include <cuda_runtime.h>
#include <cuda_bf16.h>
#include <cstdint>

#define Bb   128
#define Ss   416
#define Nn   32
#define Mm   384
#define Dd   256
#define Hh   8
#define Ee   32
#define Oo   256
#define BSs  (Bb*Ss)          // 53248
#define NBH  (Bb*Hh*Ss*Ee)    // 13,631,488

// -------- scratch (static device globals; no runtime allocation) ----------
__device__ __nv_bfloat16 g_xh[BSs*Dd], g_xl[BSs*Dd];
__device__ __nv_bfloat16 g_wh[5*256*256], g_wl[5*256*256];  // [proj][n][k]; 4=out_w
__device__ __nv_bfloat16 g_qh[NBH], g_ql[NBH];
__device__ __nv_bfloat16 g_kh[NBH], g_kl[NBH];
__device__ __nv_bfloat16 g_vh[NBH], g_vl[NBH];
__device__ float         g_g [NBH];
__device__ __nv_bfloat16 g_aoh[BSs*Oo], g_aol[BSs*Oo];

__device__ __forceinline__ float warpSum(float v) {
#pragma unroll
    for (int o = 16; o; o >>= 1) v += __shfl_xor_sync(0xffffffffu, v, o);
    return v;
}

// -------- mma.sync helpers --------------------------------------------------
__device__ __forceinline__ uint32_t smem_u32(const void* p) {
    uint32_t a;
    asm("{ .reg .u64 t; cvta.to.shared.u64 t, %1; cvt.u32.u64 %0, t; }"
        : "=r"(a) : "l"(p));
    return a;
}
__device__ __forceinline__ void ldsm4(uint32_t& r0, uint32_t& r1,
                                      uint32_t& r2, uint32_t& r3, uint32_t a) {
    asm volatile("ldmatrix.sync.aligned.m8n8.x4.shared.b16 {%0,%1,%2,%3}, [%4];"
                 : "=r"(r0), "=r"(r1), "=r"(r2), "=r"(r3) : "r"(a));
}
__device__ __forceinline__ void ldsm4t(uint32_t& r0, uint32_t& r1,
                                       uint32_t& r2, uint32_t& r3, uint32_t a) {
    asm volatile("ldmatrix.sync.aligned.m8n8.x4.trans.shared.b16 {%0,%1,%2,%3}, [%4];"
                 : "=r"(r0), "=r"(r1), "=r"(r2), "=r"(r3) : "r"(a));
}
__device__ __forceinline__ void ldsm2(uint32_t& r0, uint32_t& r1, uint32_t a) {
    asm volatile("ldmatrix.sync.aligned.m8n8.x2.shared.b16 {%0,%1}, [%2];"
                 : "=r"(r0), "=r"(r1) : "r"(a));
}
__device__ __forceinline__ void mma16816(float* d, const uint32_t* a,
                                         const uint32_t* b) {
    asm volatile(
        "mma.sync.aligned.m16n8k16.row.col.f32.bf16.bf16.f32 "
        "{%0,%1,%2,%3}, {%4,%5,%6,%7}, {%8,%9}, {%0,%1,%2,%3};"
        : "+f"(d[0]), "+f"(d[1]), "+f"(d[2]), "+f"(d[3])
        : "r"(a[0]), "r"(a[1]), "r"(a[2]), "r"(a[3]), "r"(b[0]), "r"(b[1]));
}
__device__ __forceinline__ void mma1688(float* d, const uint32_t* a, uint32_t b) {
    asm volatile(
        "mma.sync.aligned.m16n8k8.row.col.f32.bf16.bf16.f32 "
        "{%0,%1,%2,%3}, {%4,%5}, {%6}, {%0,%1,%2,%3};"
        : "+f"(d[0]), "+f"(d[1]), "+f"(d[2]), "+f"(d[3])
        : "r"(a[0]), "r"(a[1]), "r"(b));
}
__device__ __forceinline__ void hilo(float v, __nv_bfloat16& h, __nv_bfloat16& l) {
    h = __float2bfloat16(v);
    l = __float2bfloat16(v - __bfloat162float(h));
}
// pack two floats into hi-bf16x2 and lo-bf16x2 regs
__device__ __forceinline__ void packhl(float a, float b,
                                       uint32_t& ph, uint32_t& pl) {
    __nv_bfloat162 th, tl;
    hilo(a, th.x, tl.x);
    hilo(b, th.y, tl.y);
    ph = *(uint32_t*)&th;
    pl = *(uint32_t*)&tl;
}

// ========== Kernel 0: one-time weight conversion to hi/lo bf16 [n][k] ======
__global__ void k_wconv(const float* __restrict__ qp, const float* __restrict__ kp,
                        const float* __restrict__ vp, const float* __restrict__ gp,
                        const float* __restrict__ ow) {
    int n = blockIdx.x;
    int proj = blockIdx.y;
    int k = threadIdx.x;
    float v;
    if (proj < 4) {
        const float* Wp = (proj == 0) ? qp : (proj == 1) ? kp
                         : (proj == 2) ? vp : gp;
        v = Wp[(n >> 5) * 8192 + k * 32 + (n & 31)];
    } else {
        v = ow[k * 256 + n];
    }
    __nv_bfloat16 h, l;
    hilo(v, h, l);
    size_t idx = (size_t)(proj * 256 + n) * 256 + k;
    g_wh[idx] = h;
    g_wl[idx] = l;
}

// =================== Kernel 1: LayerNorm -> hi/lo bf16 =====================
__global__ void k_ln1(const float* __restrict__ x,
                      const float* __restrict__ gam,
                      const float* __restrict__ bet) {
    int row = blockIdx.x;
    int t = threadIdx.x;
    int w = t >> 5, lane = t & 31;
    __shared__ float red[8];

    float v = x[(size_t)row * Dd + t];
    float s = warpSum(v);
    if (lane == 0) red[w] = s;
    __syncthreads();
    float mu = 0.f;
#pragma unroll
    for (int i = 0; i < 8; i++) mu += red[i];
    mu *= (1.f / 256.f);
    float d = v - mu;
    __syncthreads();
    s = warpSum(d * d);
    if (lane == 0) red[w] = s;
    __syncthreads();
    float var = 0.f;
#pragma unroll
    for (int i = 0; i < 8; i++) var += red[i];
    var *= (1.f / 256.f);
    float r = d * rsqrtf(var + 1e-6f) * gam[t] + bet[t];
    __nv_bfloat16 h, l;
    hilo(r, h, l);
    g_xh[(size_t)row * Dd + t] = h;
    g_xl[(size_t)row * Dd + t] = l;
}

// ============ Kernel 2: QKVG projections via mma.sync bf16x3 ===============
__global__ void __launch_bounds__(256)
k_qkvg() {
    __shared__ __align__(16) __nv_bfloat16 Ahi[128 * 40];
    __shared__ __align__(16) __nv_bfloat16 Alo[128 * 40];
    __shared__ __align__(16) __nv_bfloat16 Bhi[64 * 40];
    __shared__ __align__(16) __nv_bfloat16 Blo[64 * 40];

    int tid = threadIdx.x;
    int wid = tid >> 5, lane = tid & 31;
    int wm = wid & 3, wn = wid >> 2;

    int m0 = blockIdx.x * 128;
    int n0 = blockIdx.y * 64;
    int proj = n0 >> 8;
    int nin = n0 & 255;

    uint32_t ahi_b = smem_u32(Ahi), alo_b = smem_u32(Alo);
    uint32_t bhi_b = smem_u32(Bhi), blo_b = smem_u32(Blo);

    float acc[2][4][4];
#pragma unroll
    for (int i = 0; i < 2; i++)
#pragma unroll
        for (int j = 0; j < 4; j++)
#pragma unroll
            for (int c = 0; c < 4; c++) acc[i][j][c] = 0.f;

    int a_row = (lane & 15);
    int a_kof = (lane >> 4) * 8;
    int b_row = ((lane >> 4) & 1) * 8 + (lane & 7);
    int b_kof = ((lane >> 3) & 1) * 8;

    for (int k0 = 0; k0 < 256; k0 += 32) {
#pragma unroll
        for (int it = 0; it < 2; it++) {
            int idx = tid + it * 256;
            int row = idx >> 2, q = idx & 3;
            *(uint4*)&Ahi[row * 40 + q * 8] =
                *(const uint4*)&g_xh[(size_t)(m0 + row) * 256 + k0 + q * 8];
            *(uint4*)&Alo[row * 40 + q * 8] =
                *(const uint4*)&g_xl[(size_t)(m0 + row) * 256 + k0 + q * 8];
        }
        {
            int n = tid >> 2, q = tid & 3;
            size_t src = (size_t)(proj * 256 + nin + n) * 256 + k0 + q * 8;
            *(uint4*)&Bhi[n * 40 + q * 8] = *(const uint4*)&g_wh[src];
            *(uint4*)&Blo[n * 40 + q * 8] = *(const uint4*)&g_wl[src];
        }
        __syncthreads();

#pragma unroll
        for (int ks = 0; ks < 2; ks++) {
            int kk = ks * 16;
            uint32_t ah[2][4], al[2][4];
#pragma unroll
            for (int mt = 0; mt < 2; mt++) {
                int row = wm * 32 + mt * 16 + a_row;
                uint32_t off = (uint32_t)(row * 40 + kk + a_kof) * 2;
                ldsm4(ah[mt][0], ah[mt][1], ah[mt][2], ah[mt][3], ahi_b + off);
                ldsm4(al[mt][0], al[mt][1], al[mt][2], al[mt][3], alo_b + off);
            }
            uint32_t bh[4][2], bl[4][2];
#pragma unroll
            for (int jp = 0; jp < 2; jp++) {
                int row = wn * 32 + jp * 16 + b_row;
                uint32_t off = (uint32_t)(row * 40 + kk + b_kof) * 2;
                ldsm4(bh[jp*2][0], bh[jp*2][1], bh[jp*2+1][0], bh[jp*2+1][1],
                      bhi_b + off);
                ldsm4(bl[jp*2][0], bl[jp*2][1], bl[jp*2+1][0], bl[jp*2+1][1],
                      blo_b + off);
            }
#pragma unroll
            for (int mt = 0; mt < 2; mt++)
#pragma unroll
                for (int j = 0; j < 4; j++) {
                    mma16816(acc[mt][j], ah[mt], bh[j]);
                    mma16816(acc[mt][j], ah[mt], bl[j]);
                    mma16816(acc[mt][j], al[mt], bh[j]);
                }
        }
        __syncthreads();
    }

    int h = (nin + wn * 32) >> 5;
    __nv_bfloat16* Oh = (proj == 0) ? g_qh : (proj == 1) ? g_kh : g_vh;
    __nv_bfloat16* Ol = (proj == 0) ? g_ql : (proj == 1) ? g_kl : g_vl;
    bool isG = (proj == 3);
#pragma unroll
    for (int mt = 0; mt < 2; mt++) {
        int m = m0 + wm * 32 + mt * 16 + (lane >> 2);
        int b1 = m / Ss, s1 = m - b1 * Ss;
        int m2 = m + 8;
        int b2 = m2 / Ss, s2 = m2 - b2 * Ss;
        size_t i1 = (((size_t)(b1 * Hh + h)) * Ss + s1) * Ee;
        size_t i2 = (((size_t)(b2 * Hh + h)) * Ss + s2) * Ee;
#pragma unroll
        for (int j = 0; j < 4; j++) {
            int e = j * 8 + (lane & 3) * 2;
            if (isG) {
                *(float2*)&g_g[i1 + e] = make_float2(acc[mt][j][0], acc[mt][j][1]);
                *(float2*)&g_g[i2 + e] = make_float2(acc[mt][j][2], acc[mt][j][3]);
            } else {
                __nv_bfloat162 h1, l1, h2, l2;
                hilo(acc[mt][j][0], h1.x, l1.x);
                hilo(acc[mt][j][1], h1.y, l1.y);
                hilo(acc[mt][j][2], h2.x, l2.x);
                hilo(acc[mt][j][3], h2.y, l2.y);
                *(__nv_bfloat162*)&Oh[i1 + e] = h1;
                *(__nv_bfloat162*)&Ol[i1 + e] = l1;
                *(__nv_bfloat162*)&Oh[i2 + e] = h2;
                *(__nv_bfloat162*)&Ol[i2 + e] = l2;
            }
        }
    }
}

// ==== Kernel 3: fused attention; fragment-resident softmax+AV, 512 thr =====
#define KHI_OFF   0                       // 416*40*2 = 33280
#define KLO_OFF   33280
#define VH_OFF    66560
#define VL_OFF    99840
#define QHI_OFF   133120                  // 64*40*2 = 5120
#define QLO_OFF   138240
#define CSH_OFF   143360                  // 416*4 = 1664
#define RED_OFF   145024                  // 2*32*8*4 = 2048
#define OP_OFF    147072                  // 2*4*32*32*4 = 32768
#define ATTN_SMEM 179840

__global__ void __launch_bounds__(512, 1)
k_attn(const float* __restrict__ pmask, const float* __restrict__ mmask) {
    extern __shared__ char smc[];
    __nv_bfloat16* khi = (__nv_bfloat16*)(smc + KHI_OFF);
    __nv_bfloat16* klo = (__nv_bfloat16*)(smc + KLO_OFF);
    __nv_bfloat16* v_h = (__nv_bfloat16*)(smc + VH_OFF);
    __nv_bfloat16* v_l = (__nv_bfloat16*)(smc + VL_OFF);
    __nv_bfloat16* qhi = (__nv_bfloat16*)(smc + QHI_OFF);
    __nv_bfloat16* qlo = (__nv_bfloat16*)(smc + QLO_OFF);
    float*         c_sh = (float*)(smc + CSH_OFF);
    float*         red  = (float*)(smc + RED_OFF);   // [xt][row][nq*2+{m,s}]
    float*         opart = (float*)(smc + OP_OFF);   // [xt][nq][row][e]

    uint32_t khi_b = smem_u32(khi), klo_b = smem_u32(klo);
    uint32_t vh_b = smem_u32(v_h), vl_b = smem_u32(v_l);
    uint32_t qhi_b = smem_u32(qhi), qlo_b = smem_u32(qlo);

    int tid = threadIdx.x;
    int wid = tid >> 5, lane = tid & 31;
    int bh = blockIdx.x;
    int h = bh & 7, b = bh >> 3;
    size_t baseBH = (size_t)(b * Hh + h) * Ss;

    // warp roles
    int xt = wid >> 3;          // which of the 2 concurrent x-tiles
    int mh = (wid >> 2) & 1;    // m-half (rows 0-15 / 16-31 of tile)
    int nq = wid & 3;           // y quarter (104 cols)
    int nbase = nq * 104;

    // ---- stage K and V hi/lo (pure 16B copies), [y][*] stride 40 ----
    for (int i = tid; i < Ss * 4; i += 512) {
        int y = i >> 2, q = i & 3;
        size_t src = (baseBH + y) * Ee + q * 8;
        *(uint4*)&khi[y * 40 + q * 8] = *(const uint4*)&g_kh[src];
        *(uint4*)&klo[y * 40 + q * 8] = *(const uint4*)&g_kl[src];
        *(uint4*)&v_h[y * 40 + q * 8] = *(const uint4*)&g_vh[src];
        *(uint4*)&v_l[y * 40 + q * 8] = *(const uint4*)&g_vl[src];
    }
    for (int i = tid; i < Ss; i += 512) {
        float val = (i < Nn) ? pmask[b * Nn + i] : mmask[b * Mm + (i - Nn)];
        c_sh[i] = (val == -2.0f) ? 0.f : 1.f;
    }
    __syncthreads();

    const float scale = 0.1767766952966369f;   // 1/sqrt(32)
    int a_row = (lane & 15);
    int a_kof = (lane >> 4) * 8;
    int b_row = ((lane >> 4) & 1) * 8 + (lane & 7);
    int b_kof = ((lane >> 3) & 1) * 8;

    for (int pr = 0; pr < 7; pr++) {
        int t0 = pr * 2;
        int x0pair = t0 * 32;
        // ---- stage Q for both tiles (guard tail) ----
        {
            int i = tid & 255;
            int xr = i >> 2, q = i & 3;
            int gx = x0pair + xr;
            if (gx < Ss) {
                size_t src = (baseBH + gx) * Ee + q * 8;
                if (tid < 256)
                    *(uint4*)&qhi[xr * 40 + q * 8] = *(const uint4*)&g_qh[src];
                else
                    *(uint4*)&qlo[xr * 40 + q * 8] = *(const uint4*)&g_ql[src];
            }
        }
        __syncthreads();

        int myTile = t0 + xt;
        bool active = (myTile < 13);
        int x0 = myTile * 32;

        float acc[13][4];
        float f1 = 0.f, f2 = 0.f;
        int lx1 = mh * 16 + (lane >> 2);
        int lx2 = lx1 + 8;

        if (active) {
#pragma unroll
            for (int t2 = 0; t2 < 13; t2++)
#pragma unroll
                for (int c = 0; c < 4; c++) acc[t2][c] = 0.f;

            // ---- QK^T ----
#pragma unroll
            for (int ks = 0; ks < 2; ks++) {
                int kk = ks * 16;
                uint32_t ah[4], al[4];
                {
                    uint32_t off = (uint32_t)((xt * 32 + mh * 16 + a_row) * 40
                                              + kk + a_kof) * 2;
                    ldsm4(ah[0], ah[1], ah[2], ah[3], qhi_b + off);
                    ldsm4(al[0], al[1], al[2], al[3], qlo_b + off);
                }
#pragma unroll
                for (int jp = 0; jp < 6; jp++) {
                    uint32_t bh2[4], bl2[4];
                    uint32_t off = (uint32_t)((nbase + jp * 16 + b_row) * 40
                                              + kk + b_kof) * 2;
                    ldsm4(bh2[0], bh2[1], bh2[2], bh2[3], khi_b + off);
                    ldsm4(bl2[0], bl2[1], bl2[2], bl2[3], klo_b + off);
                    mma16816(acc[jp*2],   ah, &bh2[0]);
                    mma16816(acc[jp*2],   ah, &bl2[0]);
                    mma16816(acc[jp*2],   al, &bh2[0]);
                    mma16816(acc[jp*2+1], ah, &bh2[2]);
                    mma16816(acc[jp*2+1], ah, &bl2[2]);
                    mma16816(acc[jp*2+1], al, &bh2[2]);
                }
                {
                    uint32_t bh1[2], bl1[2];
                    uint32_t off = (uint32_t)((nbase + 96 + (lane & 7)) * 40 + kk
                                              + 8 * ((lane >> 3) & 1)) * 2;
                    ldsm2(bh1[0], bh1[1], khi_b + off);
                    ldsm2(bl1[0], bl1[1], klo_b + off);
                    mma16816(acc[12], ah, bh1);
                    mma16816(acc[12], ah, bl1);
                    mma16816(acc[12], al, bh1);
                }
            }

            // ---- mask/scale in registers ----
            bool xIsP = (x0 == 0);
            float cx1 = c_sh[x0 + lx1];
            float cx2 = c_sh[x0 + lx2];
#pragma unroll
            for (int t2 = 0; t2 < 13; t2++) {
                int ybase = nbase + t2 * 8;
                int yc = ybase + (lane & 3) * 2;
                bool cross = (xIsP != (ybase < Nn));
                float cy0 = c_sh[yc], cy1 = c_sh[yc + 1];
                float m00 = cross ? cx1 * cy0 : 0.f;
                float m01 = cross ? cx1 * cy1 : 0.f;
                float m10 = cross ? cx2 * cy0 : 0.f;
                float m11 = cross ? cx2 * cy1 : 0.f;
                acc[t2][0] = acc[t2][0] * scale + (1.f - m00) * (-1.0e9f);
                acc[t2][1] = acc[t2][1] * scale + (1.f - m01) * (-1.0e9f);
                acc[t2][2] = acc[t2][2] * scale + (1.f - m10) * (-1.0e9f);
                acc[t2][3] = acc[t2][3] * scale + (1.f - m11) * (-1.0e9f);
            }

            // ---- local softmax: quad max/sum ----
            float m1 = -3.0e38f, m2 = -3.0e38f;
#pragma unroll
            for (int t2 = 0; t2 < 13; t2++) {
                m1 = fmaxf(m1, fmaxf(acc[t2][0], acc[t2][1]));
                m2 = fmaxf(m2, fmaxf(acc[t2][2], acc[t2][3]));
            }
#pragma unroll
            for (int o = 1; o <= 2; o <<= 1) {
                m1 = fmaxf(m1, __shfl_xor_sync(0xffffffffu, m1, o));
                m2 = fmaxf(m2, __shfl_xor_sync(0xffffffffu, m2, o));
            }
            float s1 = 0.f, s2 = 0.f;
#pragma unroll
            for (int t2 = 0; t2 < 13; t2++) {
                acc[t2][0] = __expf(acc[t2][0] - m1);
                acc[t2][1] = __expf(acc[t2][1] - m1);
                acc[t2][2] = __expf(acc[t2][2] - m2);
                acc[t2][3] = __expf(acc[t2][3] - m2);
                s1 += acc[t2][0] + acc[t2][1];
                s2 += acc[t2][2] + acc[t2][3];
            }
#pragma unroll
            for (int o = 1; o <= 2; o <<= 1) {
                s1 += __shfl_xor_sync(0xffffffffu, s1, o);
                s2 += __shfl_xor_sync(0xffffffffu, s2, o);
            }
            if ((lane & 3) == 0) {
                float* rr = red + xt * 256;
                rr[lx1 * 8 + nq * 2]     = m1;
                rr[lx1 * 8 + nq * 2 + 1] = s1;
                rr[lx2 * 8 + nq * 2]     = m2;
                rr[lx2 * 8 + nq * 2 + 1] = s2;
            }
            __syncthreads();
            {
                const float* rr = red + xt * 256;
                float M1 = -3.0e38f, M2 = -3.0e38f;
#pragma unroll
                for (int q = 0; q < 4; q++) {
                    M1 = fmaxf(M1, rr[lx1 * 8 + q * 2]);
                    M2 = fmaxf(M2, rr[lx2 * 8 + q * 2]);
                }
                float S1 = 0.f, S2 = 0.f;
#pragma unroll
                for (int q = 0; q < 4; q++) {
                    S1 += rr[lx1 * 8 + q * 2 + 1] * __expf(rr[lx1 * 8 + q * 2] - M1);
                    S2 += rr[lx2 * 8 + q * 2 + 1] * __expf(rr[lx2 * 8 + q * 2] - M2);
                }
                f1 = cx1 * __expf(m1 - M1) / S1;
                f2 = cx2 * __expf(m2 - M2) / S2;
            }
        } else {
            __syncthreads();   // match the red-exchange barrier
        }

        // ---- AV: A from C-fragments, partial O over this warp's y-slice ----
        if (active) {
            float o[4][4];
#pragma unroll
            for (int eg = 0; eg < 4; eg++)
#pragma unroll
                for (int c = 0; c < 4; c++) o[eg][c] = 0.f;

#pragma unroll
            for (int g = 0; g < 3; g++) {
                // A fragments for tile pair (4g,4g+1) and (4g+2,4g+3)
                uint32_t Ah0[4], Al0[4], Ah1[4], Al1[4];
                {
                    int ta = 4 * g, tb = 4 * g + 1;
                    packhl(acc[ta][0] * f1, acc[ta][1] * f1, Ah0[0], Al0[0]);
                    packhl(acc[ta][2] * f2, acc[ta][3] * f2, Ah0[1], Al0[1]);
                    packhl(acc[tb][0] * f1, acc[tb][1] * f1, Ah0[2], Al0[2]);
                    packhl(acc[tb][2] * f2, acc[tb][3] * f2, Ah0[3], Al0[3]);
                    int tc = 4 * g + 2, td = 4 * g + 3;
                    packhl(acc[tc][0] * f1, acc[tc][1] * f1, Ah1[0], Al1[0]);
                    packhl(acc[tc][2] * f2, acc[tc][3] * f2, Ah1[1], Al1[1]);
                    packhl(acc[td][0] * f1, acc[td][1] * f1, Ah1[2], Al1[2]);
                    packhl(acc[td][2] * f2, acc[td][3] * f2, Ah1[3], Al1[3]);
                }
#pragma unroll
                for (int eg = 0; eg < 4; eg++) {
                    uint32_t bh4[4], bl4[4];
                    uint32_t offB = (uint32_t)((nbase + g * 32 + lane) * 40
                                               + eg * 8) * 2;
                    ldsm4t(bh4[0], bh4[1], bh4[2], bh4[3], vh_b + offB);
                    ldsm4t(bl4[0], bl4[1], bl4[2], bl4[3], vl_b + offB);
                    mma16816(o[eg], Ah0, &bh4[0]);
                    mma16816(o[eg], Ah0, &bl4[0]);
                    mma16816(o[eg], Al0, &bh4[0]);
                    mma16816(o[eg], Ah1, &bh4[2]);
                    mma16816(o[eg], Ah1, &bl4[2]);
                    mma16816(o[eg], Al1, &bh4[2]);
                }
            }
            // tail tile 12: k8
            {
                uint32_t Ath[2], Atl[2];
                packhl(acc[12][0] * f1, acc[12][1] * f1, Ath[0], Atl[0]);
                packhl(acc[12][2] * f2, acc[12][3] * f2, Ath[1], Atl[1]);
                uint32_t bh4[4], bl4[4];
                uint32_t offT = (uint32_t)((nbase + 96 + (lane & 7)) * 40
                                           + (lane >> 3) * 8) * 2;
                ldsm4t(bh4[0], bh4[1], bh4[2], bh4[3], vh_b + offT);
                ldsm4t(bl4[0], bl4[1], bl4[2], bl4[3], vl_b + offT);
#pragma unroll
                for (int eg = 0; eg < 4; eg++) {
                    mma1688(o[eg], Ath, bh4[eg]);
                    mma1688(o[eg], Ath, bl4[eg]);
                    mma1688(o[eg], Atl, bh4[eg]);
                }
            }
            // write partial O: opart[xt][nq][row][e]
            float* op = opart + ((xt * 4 + nq) * 32) * 32;
#pragma unroll
            for (int eg = 0; eg < 4; eg++) {
                int e = eg * 8 + (lane & 3) * 2;
                *(float2*)&op[lx1 * 32 + e] = make_float2(o[eg][0], o[eg][1]);
                *(float2*)&op[lx2 * 32 + e] = make_float2(o[eg][2], o[eg][3]);
            }
        }
        __syncthreads();

        // ---- reduce over nq + gate + store ----
#pragma unroll
        for (int it = 0; it < 4; it++) {
            int idx = tid + it * 512;          // 0..2047
            int rxt = idx >> 10;
            int row = (idx >> 5) & 31;
            int e = idx & 31;
            int tle = t0 + rxt;
            if (tle < 13) {
                const float* op = opart + (rxt * 4 * 32) * 32 + row * 32 + e;
                float sum = op[0] + op[1024] + op[2048] + op[3072];
                int xs_ = tle * 32 + row;
                float gv = g_g[(baseBH + xs_) * Ee + e];
                float sg = 1.f / (1.f + __expf(-gv));
                float ov = sum * sg;
                __nv_bfloat16 oh, ol;
                hilo(ov, oh, ol);
                size_t di = ((size_t)b * Ss + xs_) * Oo + h * Ee + e;
                g_aoh[di] = oh;
                g_aol[di] = ol;
            }
        }
        __syncthreads();
    }
}

// ============ Kernel 4: output projection (HMMA bf16x3) + LN2 ==============
#define OAHI_OFF 0
#define OALO_OFF 2560
#define OBHI_OFF 5120
#define OBLO_OFF 25600
#define OYS_OFF  46080
#define OMU_OFF  79872
#define ORS_OFF  80000
#define OLN_SMEM 80128

__global__ void __launch_bounds__(256)
k_outln(const float* __restrict__ bias, const float* __restrict__ g2,
        const float* __restrict__ b2, float* __restrict__ out) {
    extern __shared__ char smo[];
    __nv_bfloat16* Ahi = (__nv_bfloat16*)(smo + OAHI_OFF);
    __nv_bfloat16* Alo = (__nv_bfloat16*)(smo + OALO_OFF);
    __nv_bfloat16* Bhi = (__nv_bfloat16*)(smo + OBHI_OFF);
    __nv_bfloat16* Blo = (__nv_bfloat16*)(smo + OBLO_OFF);
    float* ys  = (float*)(smo + OYS_OFF);
    float* mus = (float*)(smo + OMU_OFF);
    float* rss = (float*)(smo + ORS_OFF);

    uint32_t ahi_b = smem_u32(Ahi), alo_b = smem_u32(Alo);
    uint32_t bhi_b = smem_u32(Bhi), blo_b = smem_u32(Blo);

    int tid = threadIdx.x;
    int wid = tid >> 5, lane = tid & 31;
    int mh = wid & 1, nq = wid >> 1;
    int r0 = blockIdx.x * 32;

    int a_row = (lane & 15);
    int a_kof = (lane >> 4) * 8;
    int b_row = ((lane >> 4) & 1) * 8 + (lane & 7);
    int b_kof = ((lane >> 3) & 1) * 8;

    float acc[8][4];
#pragma unroll
    for (int j = 0; j < 8; j++)
#pragma unroll
        for (int c = 0; c < 4; c++) acc[j][c] = 0.f;

    for (int k0 = 0; k0 < 256; k0 += 32) {
        {
            int i = tid & 127;
            int row = i >> 2, q = i & 3;
            size_t src = (size_t)(r0 + row) * 256 + k0 + q * 8;
            if (tid < 128)
                *(uint4*)&Ahi[row * 40 + q * 8] = *(const uint4*)&g_aoh[src];
            else
                *(uint4*)&Alo[row * 40 + q * 8] = *(const uint4*)&g_aol[src];
        }
#pragma unroll
        for (int it = 0; it < 8; it++) {
            int idx = tid + it * 256;
            int rem = idx & 1023;
            int n = rem >> 2, q = rem & 3;
            size_t src = (size_t)(4 * 256 + n) * 256 + k0 + q * 8;
            if (idx < 1024)
                *(uint4*)&Bhi[n * 40 + q * 8] = *(const uint4*)&g_wh[src];
            else
                *(uint4*)&Blo[n * 40 + q * 8] = *(const uint4*)&g_wl[src];
        }
        __syncthreads();

#pragma unroll
        for (int ks = 0; ks < 2; ks++) {
            int kk = ks * 16;
            uint32_t ah[4], al[4];
            {
                uint32_t off = (uint32_t)((mh * 16 + a_row) * 40 + kk + a_kof) * 2;
                ldsm4(ah[0], ah[1], ah[2], ah[3], ahi_b + off);
                ldsm4(al[0], al[1], al[2], al[3], alo_b + off);
            }
#pragma unroll
            for (int jp = 0; jp < 4; jp++) {
                uint32_t bh2[4], bl2[4];
                uint32_t off = (uint32_t)((nq * 64 + jp * 16 + b_row) * 40 + kk + b_kof) * 2;
                ldsm4(bh2[0], bh2[1], bh2[2], bh2[3], bhi_b + off);
                ldsm4(bl2[0], bl2[1], bl2[2], bl2[3], blo_b + off);
                mma16816(acc[jp*2],   ah, &bh2[0]);
                mma16816(acc[jp*2],   ah, &bl2[0]);
                mma16816(acc[jp*2],   al, &bh2[0]);
                mma16816(acc[jp*2+1], ah, &bh2[2]);
                mma16816(acc[jp*2+1], ah, &bl2[2]);
                mma16816(acc[jp*2+1], al, &bh2[2]);
            }
        }
        __syncthreads();
    }

    int lx1 = mh * 16 + (lane >> 2);
    int lx2 = lx1 + 8;
#pragma unroll
    for (int j = 0; j < 8; j++) {
        int n = nq * 64 + j * 8 + (lane & 3) * 2;
        float b0 = bias[n], b1 = bias[n + 1];
        ys[lx1 * 264 + n]     = acc[j][0] + b0;
        ys[lx1 * 264 + n + 1] = acc[j][1] + b1;
        ys[lx2 * 264 + n]     = acc[j][2] + b0;
        ys[lx2 * 264 + n + 1] = acc[j][3] + b1;
    }
    __syncthreads();

#pragma unroll
    for (int rr = 0; rr < 4; rr++) {
        int xr = wid + rr * 8;
        const float* row = ys + xr * 264;
        float s = 0.f;
#pragma unroll
        for (int j = 0; j < 8; j++) s += row[lane + 32 * j];
        s = warpSum(s);
        float mu = s * (1.f / 256.f);
        float vs = 0.f;
#pragma unroll
        for (int j = 0; j < 8; j++) {
            float d = row[lane + 32 * j] - mu;
            vs += d * d;
        }
        vs = warpSum(vs);
        if (lane == 0) { mus[xr] = mu; rss[xr] = rsqrtf(vs * (1.f / 256.f) + 1e-6f); }
    }
    __syncthreads();

    float gt = g2[tid], bt = b2[tid];
#pragma unroll 4
    for (int r = 0; r < 32; r++) {
        out[(size_t)(r0 + r) * 256 + tid] =
            (ys[r * 264 + tid] - mus[r]) * rss[r] * gt + bt;
    }
}

// ===========================================================================
extern "C" void kernel_launch(void* const* d_in, const int* in_sizes, int n_in,
                              void* d_out, int out_size) {
    const float* x   = (const float*)d_in[0];
    const float* pm  = (const float*)d_in[1];
    const float* mm  = (const float*)d_in[2];
    const float* qp  = (const float*)d_in[3];
    const float* kp  = (const float*)d_in[4];
    const float* vp  = (const float*)d_in[5];
    const float* gp  = (const float*)d_in[6];
    const float* ow  = (const float*)d_in[7];
    const float* ob  = (const float*)d_in[8];
    const float* l1g = (const float*)d_in[9];
    const float* l1b = (const float*)d_in[10];
    const float* l2g = (const float*)d_in[11];
    const float* l2b = (const float*)d_in[12];
    float* out = (float*)d_out;

    cudaFuncSetAttribute(k_attn, cudaFuncAttributeMaxDynamicSharedMemorySize,
                         ATTN_SMEM);
    cudaFuncSetAttribute(k_outln, cudaFuncAttributeMaxDynamicSharedMemorySize,
                         OLN_SMEM);

    k_wconv<<<dim3(256, 5), 256>>>(qp, kp, vp, gp, ow);
    k_ln1  <<<BSs, 256>>>(x, l1g, l1b);
    k_qkvg <<<dim3(416, 16), 256>>>();
    k_attn <<<Bb * Hh, 512, ATTN_SMEM>>>(pm, mm);
    k_outln<<<BSs / 32, 256, OLN_SMEM>>>(ob, l2g, l2b, out);
}

// round 10
// speedup vs baseline: 2.8264x; 1.0449x over previous
#include <cuda_runtime.h>
#include <cuda_bf16.h>
#include <cstdint>

#define Bb   128
#define Ss   416
#define Nn   32
#define Mm   384
#define Dd   256
#define Hh   8
#define Ee   32
#define Oo   256
#define BSs  (Bb*Ss)          // 53248
#define NBH  (Bb*Hh*Ss*Ee)    // 13,631,488

// -------- scratch (static device globals; no runtime allocation) ----------
__device__ __nv_bfloat16 g_xh[BSs*Dd], g_xl[BSs*Dd];
__device__ __nv_bfloat16 g_wh[5*256*256], g_wl[5*256*256];  // [proj][n][k]; 4=out_w
__device__ __nv_bfloat16 g_qh[NBH], g_ql[NBH];
__device__ __nv_bfloat16 g_kh[NBH], g_kl[NBH];
__device__ __nv_bfloat16 g_vh[NBH], g_vl[NBH];
__device__ float         g_g [NBH];
__device__ __nv_bfloat16 g_aoh[BSs*Oo], g_aol[BSs*Oo];

__device__ __forceinline__ float warpSum(float v) {
#pragma unroll
    for (int o = 16; o; o >>= 1) v += __shfl_xor_sync(0xffffffffu, v, o);
    return v;
}

// -------- mma.sync helpers --------------------------------------------------
__device__ __forceinline__ uint32_t smem_u32(const void* p) {
    uint32_t a;
    asm("{ .reg .u64 t; cvta.to.shared.u64 t, %1; cvt.u32.u64 %0, t; }"
        : "=r"(a) : "l"(p));
    return a;
}
__device__ __forceinline__ void ldsm4(uint32_t& r0, uint32_t& r1,
                                      uint32_t& r2, uint32_t& r3, uint32_t a) {
    asm volatile("ldmatrix.sync.aligned.m8n8.x4.shared.b16 {%0,%1,%2,%3}, [%4];"
                 : "=r"(r0), "=r"(r1), "=r"(r2), "=r"(r3) : "r"(a));
}
__device__ __forceinline__ void ldsm4t(uint32_t& r0, uint32_t& r1,
                                       uint32_t& r2, uint32_t& r3, uint32_t a) {
    asm volatile("ldmatrix.sync.aligned.m8n8.x4.trans.shared.b16 {%0,%1,%2,%3}, [%4];"
                 : "=r"(r0), "=r"(r1), "=r"(r2), "=r"(r3) : "r"(a));
}
__device__ __forceinline__ void ldsm2(uint32_t& r0, uint32_t& r1, uint32_t a) {
    asm volatile("ldmatrix.sync.aligned.m8n8.x2.shared.b16 {%0,%1}, [%2];"
                 : "=r"(r0), "=r"(r1) : "r"(a));
}
__device__ __forceinline__ void mma16816(float* d, const uint32_t* a,
                                         const uint32_t* b) {
    asm volatile(
        "mma.sync.aligned.m16n8k16.row.col.f32.bf16.bf16.f32 "
        "{%0,%1,%2,%3}, {%4,%5,%6,%7}, {%8,%9}, {%0,%1,%2,%3};"
        : "+f"(d[0]), "+f"(d[1]), "+f"(d[2]), "+f"(d[3])
        : "r"(a[0]), "r"(a[1]), "r"(a[2]), "r"(a[3]), "r"(b[0]), "r"(b[1]));
}
__device__ __forceinline__ void mma1688(float* d, const uint32_t* a, uint32_t b) {
    asm volatile(
        "mma.sync.aligned.m16n8k8.row.col.f32.bf16.bf16.f32 "
        "{%0,%1,%2,%3}, {%4,%5}, {%6}, {%0,%1,%2,%3};"
        : "+f"(d[0]), "+f"(d[1]), "+f"(d[2]), "+f"(d[3])
        : "r"(a[0]), "r"(a[1]), "r"(b));
}
__device__ __forceinline__ void hilo(float v, __nv_bfloat16& h, __nv_bfloat16& l) {
    h = __float2bfloat16(v);
    l = __float2bfloat16(v - __bfloat162float(h));
}
__device__ __forceinline__ void packhl(float a, float b,
                                       uint32_t& ph, uint32_t& pl) {
    __nv_bfloat162 th, tl;
    hilo(a, th.x, tl.x);
    hilo(b, th.y, tl.y);
    ph = *(uint32_t*)&th;
    pl = *(uint32_t*)&tl;
}

// ========== Kernel 0: one-time weight conversion to hi/lo bf16 [n][k] ======
__global__ void k_wconv(const float* __restrict__ qp, const float* __restrict__ kp,
                        const float* __restrict__ vp, const float* __restrict__ gp,
                        const float* __restrict__ ow) {
    int n = blockIdx.x;
    int proj = blockIdx.y;
    int k = threadIdx.x;
    float v;
    if (proj < 4) {
        const float* Wp = (proj == 0) ? qp : (proj == 1) ? kp
                         : (proj == 2) ? vp : gp;
        v = Wp[(n >> 5) * 8192 + k * 32 + (n & 31)];
    } else {
        v = ow[k * 256 + n];
    }
    __nv_bfloat16 h, l;
    hilo(v, h, l);
    size_t idx = (size_t)(proj * 256 + n) * 256 + k;
    g_wh[idx] = h;
    g_wl[idx] = l;
}

// =================== Kernel 1: LayerNorm -> hi/lo bf16 =====================
__global__ void k_ln1(const float* __restrict__ x,
                      const float* __restrict__ gam,
                      const float* __restrict__ bet) {
    int row = blockIdx.x;
    int t = threadIdx.x;
    int w = t >> 5, lane = t & 31;
    __shared__ float red[8];

    float v = x[(size_t)row * Dd + t];
    float s = warpSum(v);
    if (lane == 0) red[w] = s;
    __syncthreads();
    float mu = 0.f;
#pragma unroll
    for (int i = 0; i < 8; i++) mu += red[i];
    mu *= (1.f / 256.f);
    float d = v - mu;
    __syncthreads();
    s = warpSum(d * d);
    if (lane == 0) red[w] = s;
    __syncthreads();
    float var = 0.f;
#pragma unroll
    for (int i = 0; i < 8; i++) var += red[i];
    var *= (1.f / 256.f);
    float r = d * rsqrtf(var + 1e-6f) * gam[t] + bet[t];
    __nv_bfloat16 h, l;
    hilo(r, h, l);
    g_xh[(size_t)row * Dd + t] = h;
    g_xl[(size_t)row * Dd + t] = l;
}

// ============ Kernel 2: QKVG projections via mma.sync bf16x3 ===============
__global__ void __launch_bounds__(256)
k_qkvg() {
    __shared__ __align__(16) __nv_bfloat16 Ahi[128 * 40];
    __shared__ __align__(16) __nv_bfloat16 Alo[128 * 40];
    __shared__ __align__(16) __nv_bfloat16 Bhi[64 * 40];
    __shared__ __align__(16) __nv_bfloat16 Blo[64 * 40];

    int tid = threadIdx.x;
    int wid = tid >> 5, lane = tid & 31;
    int wm = wid & 3, wn = wid >> 2;

    int m0 = blockIdx.x * 128;
    int n0 = blockIdx.y * 64;
    int proj = n0 >> 8;
    int nin = n0 & 255;

    uint32_t ahi_b = smem_u32(Ahi), alo_b = smem_u32(Alo);
    uint32_t bhi_b = smem_u32(Bhi), blo_b = smem_u32(Blo);

    float acc[2][4][4];
#pragma unroll
    for (int i = 0; i < 2; i++)
#pragma unroll
        for (int j = 0; j < 4; j++)
#pragma unroll
            for (int c = 0; c < 4; c++) acc[i][j][c] = 0.f;

    int a_row = (lane & 15);
    int a_kof = (lane >> 4) * 8;
    int b_row = ((lane >> 4) & 1) * 8 + (lane & 7);
    int b_kof = ((lane >> 3) & 1) * 8;

    for (int k0 = 0; k0 < 256; k0 += 32) {
#pragma unroll
        for (int it = 0; it < 2; it++) {
            int idx = tid + it * 256;
            int row = idx >> 2, q = idx & 3;
            *(uint4*)&Ahi[row * 40 + q * 8] =
                *(const uint4*)&g_xh[(size_t)(m0 + row) * 256 + k0 + q * 8];
            *(uint4*)&Alo[row * 40 + q * 8] =
                *(const uint4*)&g_xl[(size_t)(m0 + row) * 256 + k0 + q * 8];
        }
        {
            int n = tid >> 2, q = tid & 3;
            size_t src = (size_t)(proj * 256 + nin + n) * 256 + k0 + q * 8;
            *(uint4*)&Bhi[n * 40 + q * 8] = *(const uint4*)&g_wh[src];
            *(uint4*)&Blo[n * 40 + q * 8] = *(const uint4*)&g_wl[src];
        }
        __syncthreads();

#pragma unroll
        for (int ks = 0; ks < 2; ks++) {
            int kk = ks * 16;
            uint32_t ah[2][4], al[2][4];
#pragma unroll
            for (int mt = 0; mt < 2; mt++) {
                int row = wm * 32 + mt * 16 + a_row;
                uint32_t off = (uint32_t)(row * 40 + kk + a_kof) * 2;
                ldsm4(ah[mt][0], ah[mt][1], ah[mt][2], ah[mt][3], ahi_b + off);
                ldsm4(al[mt][0], al[mt][1], al[mt][2], al[mt][3], alo_b + off);
            }
            uint32_t bh[4][2], bl[4][2];
#pragma unroll
            for (int jp = 0; jp < 2; jp++) {
                int row = wn * 32 + jp * 16 + b_row;
                uint32_t off = (uint32_t)(row * 40 + kk + b_kof) * 2;
                ldsm4(bh[jp*2][0], bh[jp*2][1], bh[jp*2+1][0], bh[jp*2+1][1],
                      bhi_b + off);
                ldsm4(bl[jp*2][0], bl[jp*2][1], bl[jp*2+1][0], bl[jp*2+1][1],
                      blo_b + off);
            }
#pragma unroll
            for (int mt = 0; mt < 2; mt++)
#pragma unroll
                for (int j = 0; j < 4; j++) {
                    mma16816(acc[mt][j], ah[mt], bh[j]);
                    mma16816(acc[mt][j], ah[mt], bl[j]);
                    mma16816(acc[mt][j], al[mt], bh[j]);
                }
        }
        __syncthreads();
    }

    int h = (nin + wn * 32) >> 5;
    __nv_bfloat16* Oh = (proj == 0) ? g_qh : (proj == 1) ? g_kh : g_vh;
    __nv_bfloat16* Ol = (proj == 0) ? g_ql : (proj == 1) ? g_kl : g_vl;
    bool isG = (proj == 3);
#pragma unroll
    for (int mt = 0; mt < 2; mt++) {
        int m = m0 + wm * 32 + mt * 16 + (lane >> 2);
        int b1 = m / Ss, s1 = m - b1 * Ss;
        int m2 = m + 8;
        int b2 = m2 / Ss, s2 = m2 - b2 * Ss;
        size_t i1 = (((size_t)(b1 * Hh + h)) * Ss + s1) * Ee;
        size_t i2 = (((size_t)(b2 * Hh + h)) * Ss + s2) * Ee;
#pragma unroll
        for (int j = 0; j < 4; j++) {
            int e = j * 8 + (lane & 3) * 2;
            if (isG) {
                *(float2*)&g_g[i1 + e] = make_float2(acc[mt][j][0], acc[mt][j][1]);
                *(float2*)&g_g[i2 + e] = make_float2(acc[mt][j][2], acc[mt][j][3]);
            } else {
                __nv_bfloat162 h1, l1, h2, l2;
                hilo(acc[mt][j][0], h1.x, l1.x);
                hilo(acc[mt][j][1], h1.y, l1.y);
                hilo(acc[mt][j][2], h2.x, l2.x);
                hilo(acc[mt][j][3], h2.y, l2.y);
                *(__nv_bfloat162*)&Oh[i1 + e] = h1;
                *(__nv_bfloat162*)&Ol[i1 + e] = l1;
                *(__nv_bfloat162*)&Oh[i2 + e] = h2;
                *(__nv_bfloat162*)&Ol[i2 + e] = l2;
            }
        }
    }
}

// ==== Kernel 3: attention; 2 independent 256-thr groups, Q via LDG =========
#define KHI_OFF   0                       // 416*40*2 = 33280
#define KLO_OFF   33280
#define VH_OFF    66560
#define VL_OFF    99840
#define CSH_OFF   133120                  // 416*4 = 1664
#define RED_OFF   134784                  // 2*32*8*4 = 2048
#define OP_OFF    136832                  // 2*4*32*32*4 = 32768
#define ATTN_SMEM 169600

__global__ void __launch_bounds__(512, 1)
k_attn(const float* __restrict__ pmask, const float* __restrict__ mmask) {
    extern __shared__ char smc[];
    __nv_bfloat16* khi = (__nv_bfloat16*)(smc + KHI_OFF);
    __nv_bfloat16* klo = (__nv_bfloat16*)(smc + KLO_OFF);
    __nv_bfloat16* v_h = (__nv_bfloat16*)(smc + VH_OFF);
    __nv_bfloat16* v_l = (__nv_bfloat16*)(smc + VL_OFF);
    float*         c_sh = (float*)(smc + CSH_OFF);
    float*         red  = (float*)(smc + RED_OFF);   // [grp][row][nq*2+{m,s}]
    float*         opart = (float*)(smc + OP_OFF);   // [grp][nq][row][e]

    uint32_t khi_b = smem_u32(khi), klo_b = smem_u32(klo);
    uint32_t vh_b = smem_u32(v_h), vl_b = smem_u32(v_l);

    int tid = threadIdx.x;
    int lane = tid & 31;
    int bh = blockIdx.x;
    int h = bh & 7, b = bh >> 3;
    size_t baseBH = (size_t)(b * Hh + h) * Ss;

    // ---- stage K and V hi/lo (pure 16B copies), [y][*] stride 40 ----
    for (int i = tid; i < Ss * 4; i += 512) {
        int y = i >> 2, q = i & 3;
        size_t src = (baseBH + y) * Ee + q * 8;
        *(uint4*)&khi[y * 40 + q * 8] = *(const uint4*)&g_kh[src];
        *(uint4*)&klo[y * 40 + q * 8] = *(const uint4*)&g_kl[src];
        *(uint4*)&v_h[y * 40 + q * 8] = *(const uint4*)&g_vh[src];
        *(uint4*)&v_l[y * 40 + q * 8] = *(const uint4*)&g_vl[src];
    }
    for (int i = tid; i < Ss; i += 512) {
        float val = (i < Nn) ? pmask[b * Nn + i] : mmask[b * Mm + (i - Nn)];
        c_sh[i] = (val == -2.0f) ? 0.f : 1.f;
    }
    __syncthreads();

    const float scale = 0.1767766952966369f;   // 1/sqrt(32)
    int grp = tid >> 8;          // independent 256-thread group
    int wg = (tid >> 5) & 7;     // warp within group
    int mh = (wg >> 2) & 1;      // m-half
    int nq = wg & 3;             // y quarter
    int nbase = nq * 104;
    int gtid = tid & 255;

    int b_row = ((lane >> 4) & 1) * 8 + (lane & 7);
    int b_kof = ((lane >> 3) & 1) * 8;
    int fr = lane >> 2, fc = lane & 3;        // fragment row/col
    int lx1 = mh * 16 + fr;
    int lx2 = lx1 + 8;

    float* redg = red + grp * 256;
    float* opg  = opart + grp * 4096;
    int bar_id = grp + 1;

    for (int t = grp; t < 13; t += 2) {
        int x0 = t * 32;

        // ---- Q fragments directly from global (both k-halves) ----
        uint32_t qah[2][4], qal[2][4];
        {
            const __nv_bfloat16* ph = g_qh + (baseBH + x0 + lx1) * 32;
            const __nv_bfloat16* pl = g_ql + (baseBH + x0 + lx1) * 32;
#pragma unroll
            for (int ks = 0; ks < 2; ks++) {
                int kk = ks * 16 + fc * 2;
                qah[ks][0] = *(const uint32_t*)&ph[kk];
                qah[ks][1] = *(const uint32_t*)&ph[256 + kk];      // row +8
                qah[ks][2] = *(const uint32_t*)&ph[kk + 8];
                qah[ks][3] = *(const uint32_t*)&ph[256 + kk + 8];
                qal[ks][0] = *(const uint32_t*)&pl[kk];
                qal[ks][1] = *(const uint32_t*)&pl[256 + kk];
                qal[ks][2] = *(const uint32_t*)&pl[kk + 8];
                qal[ks][3] = *(const uint32_t*)&pl[256 + kk + 8];
            }
        }

        // ---- QK^T ----
        float acc[13][4];
#pragma unroll
        for (int t2 = 0; t2 < 13; t2++)
#pragma unroll
            for (int c = 0; c < 4; c++) acc[t2][c] = 0.f;

#pragma unroll
        for (int ks = 0; ks < 2; ks++) {
            int kk = ks * 16;
#pragma unroll
            for (int jp = 0; jp < 6; jp++) {
                uint32_t bh2[4], bl2[4];
                uint32_t off = (uint32_t)((nbase + jp * 16 + b_row) * 40
                                          + kk + b_kof) * 2;
                ldsm4(bh2[0], bh2[1], bh2[2], bh2[3], khi_b + off);
                ldsm4(bl2[0], bl2[1], bl2[2], bl2[3], klo_b + off);
                mma16816(acc[jp*2],   qah[ks], &bh2[0]);
                mma16816(acc[jp*2],   qah[ks], &bl2[0]);
                mma16816(acc[jp*2],   qal[ks], &bh2[0]);
                mma16816(acc[jp*2+1], qah[ks], &bh2[2]);
                mma16816(acc[jp*2+1], qah[ks], &bl2[2]);
                mma16816(acc[jp*2+1], qal[ks], &bh2[2]);
            }
            {
                uint32_t bh1[2], bl1[2];
                uint32_t off = (uint32_t)((nbase + 96 + (lane & 7)) * 40 + kk
                                          + 8 * ((lane >> 3) & 1)) * 2;
                ldsm2(bh1[0], bh1[1], khi_b + off);
                ldsm2(bl1[0], bl1[1], klo_b + off);
                mma16816(acc[12], qah[ks], bh1);
                mma16816(acc[12], qah[ks], bl1);
                mma16816(acc[12], qal[ks], bh1);
            }
        }

        // ---- mask/scale in registers ----
        bool xIsP = (t == 0);
        float cx1 = c_sh[x0 + lx1];
        float cx2 = c_sh[x0 + lx2];
#pragma unroll
        for (int t2 = 0; t2 < 13; t2++) {
            int ybase = nbase + t2 * 8;
            int yc = ybase + fc * 2;
            bool cross = (xIsP != (ybase < Nn));
            float cy0 = c_sh[yc], cy1 = c_sh[yc + 1];
            float m00 = cross ? cx1 * cy0 : 0.f;
            float m01 = cross ? cx1 * cy1 : 0.f;
            float m10 = cross ? cx2 * cy0 : 0.f;
            float m11 = cross ? cx2 * cy1 : 0.f;
            acc[t2][0] = acc[t2][0] * scale + (1.f - m00) * (-1.0e9f);
            acc[t2][1] = acc[t2][1] * scale + (1.f - m01) * (-1.0e9f);
            acc[t2][2] = acc[t2][2] * scale + (1.f - m10) * (-1.0e9f);
            acc[t2][3] = acc[t2][3] * scale + (1.f - m11) * (-1.0e9f);
        }

        // ---- local softmax (quad reductions) ----
        float m1 = -3.0e38f, m2 = -3.0e38f;
#pragma unroll
        for (int t2 = 0; t2 < 13; t2++) {
            m1 = fmaxf(m1, fmaxf(acc[t2][0], acc[t2][1]));
            m2 = fmaxf(m2, fmaxf(acc[t2][2], acc[t2][3]));
        }
#pragma unroll
        for (int o = 1; o <= 2; o <<= 1) {
            m1 = fmaxf(m1, __shfl_xor_sync(0xffffffffu, m1, o));
            m2 = fmaxf(m2, __shfl_xor_sync(0xffffffffu, m2, o));
        }
        float s1 = 0.f, s2 = 0.f;
#pragma unroll
        for (int t2 = 0; t2 < 13; t2++) {
            acc[t2][0] = __expf(acc[t2][0] - m1);
            acc[t2][1] = __expf(acc[t2][1] - m1);
            acc[t2][2] = __expf(acc[t2][2] - m2);
            acc[t2][3] = __expf(acc[t2][3] - m2);
            s1 += acc[t2][0] + acc[t2][1];
            s2 += acc[t2][2] + acc[t2][3];
        }
#pragma unroll
        for (int o = 1; o <= 2; o <<= 1) {
            s1 += __shfl_xor_sync(0xffffffffu, s1, o);
            s2 += __shfl_xor_sync(0xffffffffu, s2, o);
        }
        if (fc == 0) {
            redg[lx1 * 8 + nq * 2]     = m1;
            redg[lx1 * 8 + nq * 2 + 1] = s1;
            redg[lx2 * 8 + nq * 2]     = m2;
            redg[lx2 * 8 + nq * 2 + 1] = s2;
        }
        asm volatile("bar.sync %0, %1;" :: "r"(bar_id), "r"(256) : "memory");
        float f1, f2;
        {
            float M1 = -3.0e38f, M2 = -3.0e38f;
#pragma unroll
            for (int q = 0; q < 4; q++) {
                M1 = fmaxf(M1, redg[lx1 * 8 + q * 2]);
                M2 = fmaxf(M2, redg[lx2 * 8 + q * 2]);
            }
            float S1 = 0.f, S2 = 0.f;
#pragma unroll
            for (int q = 0; q < 4; q++) {
                S1 += redg[lx1 * 8 + q * 2 + 1] * __expf(redg[lx1 * 8 + q * 2] - M1);
                S2 += redg[lx2 * 8 + q * 2 + 1] * __expf(redg[lx2 * 8 + q * 2] - M2);
            }
            f1 = cx1 * __expf(m1 - M1) / S1;
            f2 = cx2 * __expf(m2 - M2) / S2;
        }

        // ---- AV: A from C-fragments, partial O over warp's y-slice ----
        {
            float o[4][4];
#pragma unroll
            for (int eg = 0; eg < 4; eg++)
#pragma unroll
                for (int c = 0; c < 4; c++) o[eg][c] = 0.f;

#pragma unroll
            for (int g = 0; g < 3; g++) {
                uint32_t Ah0[4], Al0[4], Ah1[4], Al1[4];
                {
                    int ta = 4 * g, tb = 4 * g + 1;
                    packhl(acc[ta][0] * f1, acc[ta][1] * f1, Ah0[0], Al0[0]);
                    packhl(acc[ta][2] * f2, acc[ta][3] * f2, Ah0[1], Al0[1]);
                    packhl(acc[tb][0] * f1, acc[tb][1] * f1, Ah0[2], Al0[2]);
                    packhl(acc[tb][2] * f2, acc[tb][3] * f2, Ah0[3], Al0[3]);
                    int tc = 4 * g + 2, td = 4 * g + 3;
                    packhl(acc[tc][0] * f1, acc[tc][1] * f1, Ah1[0], Al1[0]);
                    packhl(acc[tc][2] * f2, acc[tc][3] * f2, Ah1[1], Al1[1]);
                    packhl(acc[td][0] * f1, acc[td][1] * f1, Ah1[2], Al1[2]);
                    packhl(acc[td][2] * f2, acc[td][3] * f2, Ah1[3], Al1[3]);
                }
#pragma unroll
                for (int eg = 0; eg < 4; eg++) {
                    uint32_t bh4[4], bl4[4];
                    uint32_t offB = (uint32_t)((nbase + g * 32 + lane) * 40
                                               + eg * 8) * 2;
                    ldsm4t(bh4[0], bh4[1], bh4[2], bh4[3], vh_b + offB);
                    ldsm4t(bl4[0], bl4[1], bl4[2], bl4[3], vl_b + offB);
                    mma16816(o[eg], Ah0, &bh4[0]);
                    mma16816(o[eg], Ah0, &bl4[0]);
                    mma16816(o[eg], Al0, &bh4[0]);
                    mma16816(o[eg], Ah1, &bh4[2]);
                    mma16816(o[eg], Ah1, &bl4[2]);
                    mma16816(o[eg], Al1, &bh4[2]);
                }
            }
            {   // tail tile 12: k8
                uint32_t Ath[2], Atl[2];
                packhl(acc[12][0] * f1, acc[12][1] * f1, Ath[0], Atl[0]);
                packhl(acc[12][2] * f2, acc[12][3] * f2, Ath[1], Atl[1]);
                uint32_t bh4[4], bl4[4];
                uint32_t offT = (uint32_t)((nbase + 96 + (lane & 7)) * 40
                                           + (lane >> 3) * 8) * 2;
                ldsm4t(bh4[0], bh4[1], bh4[2], bh4[3], vh_b + offT);
                ldsm4t(bl4[0], bl4[1], bl4[2], bl4[3], vl_b + offT);
#pragma unroll
                for (int eg = 0; eg < 4; eg++) {
                    mma1688(o[eg], Ath, bh4[eg]);
                    mma1688(o[eg], Ath, bl4[eg]);
                    mma1688(o[eg], Atl, bh4[eg]);
                }
            }
            float* op = opg + nq * 1024;
#pragma unroll
            for (int eg = 0; eg < 4; eg++) {
                int e = eg * 8 + fc * 2;
                *(float2*)&op[lx1 * 32 + e] = make_float2(o[eg][0], o[eg][1]);
                *(float2*)&op[lx2 * 32 + e] = make_float2(o[eg][2], o[eg][3]);
            }
        }
        asm volatile("bar.sync %0, %1;" :: "r"(bar_id), "r"(256) : "memory");

        // ---- reduce over nq + gate + store (group-local) ----
#pragma unroll
        for (int it = 0; it < 4; it++) {
            int idx = gtid + it * 256;         // 0..1023
            int row = idx >> 5;
            int e = idx & 31;
            const float* op = opg + row * 32 + e;
            float sum = op[0] + op[1024] + op[2048] + op[3072];
            int xs_ = x0 + row;
            float gv = g_g[(baseBH + xs_) * Ee + e];
            float sg = 1.f / (1.f + __expf(-gv));
            float ov = sum * sg;
            __nv_bfloat16 oh, ol;
            hilo(ov, oh, ol);
            size_t di = ((size_t)b * Ss + xs_) * Oo + h * Ee + e;
            g_aoh[di] = oh;
            g_aol[di] = ol;
        }
        // no barrier needed: next-iter opart writes are fenced by the
        // red-exchange barrier; redg writes by the post-AV barrier.
    }
}

// ============ Kernel 4: output projection (HMMA bf16x3) + LN2 ==============
#define OAHI_OFF 0
#define OALO_OFF 2560
#define OBHI_OFF 5120
#define OBLO_OFF 25600
#define OYS_OFF  46080
#define OMU_OFF  79872
#define ORS_OFF  80000
#define OLN_SMEM 80128

__global__ void __launch_bounds__(256)
k_outln(const float* __restrict__ bias, const float* __restrict__ g2,
        const float* __restrict__ b2, float* __restrict__ out) {
    extern __shared__ char smo[];
    __nv_bfloat16* Ahi = (__nv_bfloat16*)(smo + OAHI_OFF);
    __nv_bfloat16* Alo = (__nv_bfloat16*)(smo + OALO_OFF);
    __nv_bfloat16* Bhi = (__nv_bfloat16*)(smo + OBHI_OFF);
    __nv_bfloat16* Blo = (__nv_bfloat16*)(smo + OBLO_OFF);
    float* ys  = (float*)(smo + OYS_OFF);
    float* mus = (float*)(smo + OMU_OFF);
    float* rss = (float*)(smo + ORS_OFF);

    uint32_t ahi_b = smem_u32(Ahi), alo_b = smem_u32(Alo);
    uint32_t bhi_b = smem_u32(Bhi), blo_b = smem_u32(Blo);

    int tid = threadIdx.x;
    int wid = tid >> 5, lane = tid & 31;
    int mh = wid & 1, nq = wid >> 1;
    int r0 = blockIdx.x * 32;

    int a_row = (lane & 15);
    int a_kof = (lane >> 4) * 8;
    int b_row = ((lane >> 4) & 1) * 8 + (lane & 7);
    int b_kof = ((lane >> 3) & 1) * 8;

    float acc[8][4];
#pragma unroll
    for (int j = 0; j < 8; j++)
#pragma unroll
        for (int c = 0; c < 4; c++) acc[j][c] = 0.f;

    for (int k0 = 0; k0 < 256; k0 += 32) {
        {
            int i = tid & 127;
            int row = i >> 2, q = i & 3;
            size_t src = (size_t)(r0 + row) * 256 + k0 + q * 8;
            if (tid < 128)
                *(uint4*)&Ahi[row * 40 + q * 8] = *(const uint4*)&g_aoh[src];
            else
                *(uint4*)&Alo[row * 40 + q * 8] = *(const uint4*)&g_aol[src];
        }
#pragma unroll
        for (int it = 0; it < 8; it++) {
            int idx = tid + it * 256;
            int rem = idx & 1023;
            int n = rem >> 2, q = rem & 3;
            size_t src = (size_t)(4 * 256 + n) * 256 + k0 + q * 8;
            if (idx < 1024)
                *(uint4*)&Bhi[n * 40 + q * 8] = *(const uint4*)&g_wh[src];
            else
                *(uint4*)&Blo[n * 40 + q * 8] = *(const uint4*)&g_wl[src];
        }
        __syncthreads();

#pragma unroll
        for (int ks = 0; ks < 2; ks++) {
            int kk = ks * 16;
            uint32_t ah[4], al[4];
            {
                uint32_t off = (uint32_t)((mh * 16 + a_row) * 40 + kk + a_kof) * 2;
                ldsm4(ah[0], ah[1], ah[2], ah[3], ahi_b + off);
                ldsm4(al[0], al[1], al[2], al[3], alo_b + off);
            }
#pragma unroll
            for (int jp = 0; jp < 4; jp++) {
                uint32_t bh2[4], bl2[4];
                uint32_t off = (uint32_t)((nq * 64 + jp * 16 + b_row) * 40 + kk + b_kof) * 2;
                ldsm4(bh2[0], bh2[1], bh2[2], bh2[3], bhi_b + off);
                ldsm4(bl2[0], bl2[1], bl2[2], bl2[3], blo_b + off);
                mma16816(acc[jp*2],   ah, &bh2[0]);
                mma16816(acc[jp*2],   ah, &bl2[0]);
                mma16816(acc[jp*2],   al, &bh2[0]);
                mma16816(acc[jp*2+1], ah, &bh2[2]);
                mma16816(acc[jp*2+1], ah, &bl2[2]);
                mma16816(acc[jp*2+1], al, &bh2[2]);
            }
        }
        __syncthreads();
    }

    int lx1 = mh * 16 + (lane >> 2);
    int lx2 = lx1 + 8;
#pragma unroll
    for (int j = 0; j < 8; j++) {
        int n = nq * 64 + j * 8 + (lane & 3) * 2;
        float b0 = bias[n], b1 = bias[n + 1];
        ys[lx1 * 264 + n]     = acc[j][0] + b0;
        ys[lx1 * 264 + n + 1] = acc[j][1] + b1;
        ys[lx2 * 264 + n]     = acc[j][2] + b0;
        ys[lx2 * 264 + n + 1] = acc[j][3] + b1;
    }
    __syncthreads();

#pragma unroll
    for (int rr = 0; rr < 4; rr++) {
        int xr = wid + rr * 8;
        const float* row = ys + xr * 264;
        float s = 0.f;
#pragma unroll
        for (int j = 0; j < 8; j++) s += row[lane + 32 * j];
        s = warpSum(s);
        float mu = s * (1.f / 256.f);
        float vs = 0.f;
#pragma unroll
        for (int j = 0; j < 8; j++) {
            float d = row[lane + 32 * j] - mu;
            vs += d * d;
        }
        vs = warpSum(vs);
        if (lane == 0) { mus[xr] = mu; rss[xr] = rsqrtf(vs * (1.f / 256.f) + 1e-6f); }
    }
    __syncthreads();

    float gt = g2[tid], bt = b2[tid];
#pragma unroll 4
    for (int r = 0; r < 32; r++) {
        out[(size_t)(r0 + r) * 256 + tid] =
            (ys[r * 264 + tid] - mus[r]) * rss[r] * gt + bt;
    }
}

// ===========================================================================
extern "C" void kernel_launch(void* const* d_in, const int* in_sizes, int n_in,
                              void* d_out, int out_size) {
    const float* x   = (const float*)d_in[0];
    const float* pm  = (const float*)d_in[1];
    const float* mm  = (const float*)d_in[2];
    const float* qp  = (const float*)d_in[3];
    const float* kp  = (const float*)d_in[4];
    const float* vp  = (const float*)d_in[5];
    const float* gp  = (const float*)d_in[6];
    const float* ow  = (const float*)d_in[7];
    const float* ob  = (const float*)d_in[8];
    const float* l1g = (const float*)d_in[9];
    const float* l1b = (const float*)d_in[10];
    const float* l2g = (const float*)d_in[11];
    const float* l2b = (const float*)d_in[12];
    float* out = (float*)d_out;

    cudaFuncSetAttribute(k_attn, cudaFuncAttributeMaxDynamicSharedMemorySize,
                         ATTN_SMEM);
    cudaFuncSetAttribute(k_outln, cudaFuncAttributeMaxDynamicSharedMemorySize,
                         OLN_SMEM);

    k_wconv<<<dim3(256, 5), 256>>>(qp, kp, vp, gp, ow);
    k_ln1  <<<BSs, 256>>>(x, l1g, l1b);
    k_qkvg <<<dim3(416, 16), 256>>>();
    k_attn <<<Bb * Hh, 512, ATTN_SMEM>>>(pm, mm);
    k_outln<<<BSs / 32, 256, OLN_SMEM>>>(ob, l2g, l2b, out);
}

// round 11
// speedup vs baseline: 3.0679x; 1.0855x over previous
#include <cuda_runtime.h>
#include <cuda_bf16.h>
#include <cstdint>

#define Bb   128
#define Ss   416
#define Nn   32
#define Mm   384
#define Dd   256
#define Hh   8
#define Ee   32
#define Oo   256
#define BSs  (Bb*Ss)          // 53248
#define NBH  (Bb*Hh*Ss*Ee)    // 13,631,488

// -------- scratch (static device globals; no runtime allocation) ----------
__device__ __nv_bfloat16 g_xh[BSs*Dd], g_xl[BSs*Dd];
__device__ __nv_bfloat16 g_wh[5*256*256], g_wl[5*256*256];  // [proj][n][k]; 4=out_w
__device__ __nv_bfloat16 g_qh[NBH], g_ql[NBH];
__device__ __nv_bfloat16 g_kh[NBH], g_kl[NBH];
__device__ __nv_bfloat16 g_vh[NBH], g_vl[NBH];
__device__ float         g_g [NBH];
__device__ __nv_bfloat16 g_aoh[BSs*Oo], g_aol[BSs*Oo];

__device__ __forceinline__ float warpSum(float v) {
#pragma unroll
    for (int o = 16; o; o >>= 1) v += __shfl_xor_sync(0xffffffffu, v, o);
    return v;
}

// -------- mma.sync helpers --------------------------------------------------
__device__ __forceinline__ uint32_t smem_u32(const void* p) {
    uint32_t a;
    asm("{ .reg .u64 t; cvta.to.shared.u64 t, %1; cvt.u32.u64 %0, t; }"
        : "=r"(a) : "l"(p));
    return a;
}
__device__ __forceinline__ void ldsm4(uint32_t& r0, uint32_t& r1,
                                      uint32_t& r2, uint32_t& r3, uint32_t a) {
    asm volatile("ldmatrix.sync.aligned.m8n8.x4.shared.b16 {%0,%1,%2,%3}, [%4];"
                 : "=r"(r0), "=r"(r1), "=r"(r2), "=r"(r3) : "r"(a));
}
__device__ __forceinline__ void ldsm4t(uint32_t& r0, uint32_t& r1,
                                       uint32_t& r2, uint32_t& r3, uint32_t a) {
    asm volatile("ldmatrix.sync.aligned.m8n8.x4.trans.shared.b16 {%0,%1,%2,%3}, [%4];"
                 : "=r"(r0), "=r"(r1), "=r"(r2), "=r"(r3) : "r"(a));
}
__device__ __forceinline__ void ldsm2(uint32_t& r0, uint32_t& r1, uint32_t a) {
    asm volatile("ldmatrix.sync.aligned.m8n8.x2.shared.b16 {%0,%1}, [%2];"
                 : "=r"(r0), "=r"(r1) : "r"(a));
}
__device__ __forceinline__ void mma16816(float* d, const uint32_t* a,
                                         const uint32_t* b) {
    asm volatile(
        "mma.sync.aligned.m16n8k16.row.col.f32.bf16.bf16.f32 "
        "{%0,%1,%2,%3}, {%4,%5,%6,%7}, {%8,%9}, {%0,%1,%2,%3};"
        : "+f"(d[0]), "+f"(d[1]), "+f"(d[2]), "+f"(d[3])
        : "r"(a[0]), "r"(a[1]), "r"(a[2]), "r"(a[3]), "r"(b[0]), "r"(b[1]));
}
__device__ __forceinline__ void mma1688(float* d, const uint32_t* a, uint32_t b) {
    asm volatile(
        "mma.sync.aligned.m16n8k8.row.col.f32.bf16.bf16.f32 "
        "{%0,%1,%2,%3}, {%4,%5}, {%6}, {%0,%1,%2,%3};"
        : "+f"(d[0]), "+f"(d[1]), "+f"(d[2]), "+f"(d[3])
        : "r"(a[0]), "r"(a[1]), "r"(b));
}
__device__ __forceinline__ void hilo(float v, __nv_bfloat16& h, __nv_bfloat16& l) {
    h = __float2bfloat16(v);
    l = __float2bfloat16(v - __bfloat162float(h));
}
// fast hi/lo pack of a float pair: (x->low half, y->high half)
__device__ __forceinline__ void packhl2(float x, float y,
                                        uint32_t& ph, uint32_t& pl) {
    asm("cvt.rn.bf16x2.f32 %0, %1, %2;" : "=r"(ph) : "f"(y), "f"(x));
    float xh = __uint_as_float(ph << 16);
    float yh = __uint_as_float(ph & 0xFFFF0000u);
    float xl = x - xh;
    float yl = y - yh;
    asm("cvt.rn.bf16x2.f32 %0, %1, %2;" : "=r"(pl) : "f"(yl), "f"(xl));
}
__device__ __forceinline__ float ex2f(float x) {
    float r; asm("ex2.approx.f32 %0, %1;" : "=f"(r) : "f"(x)); return r;
}

// ========== Kernel 0: one-time weight conversion to hi/lo bf16 [n][k] ======
__global__ void k_wconv(const float* __restrict__ qp, const float* __restrict__ kp,
                        const float* __restrict__ vp, const float* __restrict__ gp,
                        const float* __restrict__ ow) {
    int n = blockIdx.x;
    int proj = blockIdx.y;
    int k = threadIdx.x;
    float v;
    if (proj < 4) {
        const float* Wp = (proj == 0) ? qp : (proj == 1) ? kp
                         : (proj == 2) ? vp : gp;
        v = Wp[(n >> 5) * 8192 + k * 32 + (n & 31)];
    } else {
        v = ow[k * 256 + n];
    }
    __nv_bfloat16 h, l;
    hilo(v, h, l);
    size_t idx = (size_t)(proj * 256 + n) * 256 + k;
    g_wh[idx] = h;
    g_wl[idx] = l;
}

// =================== Kernel 1: LayerNorm -> hi/lo bf16 =====================
__global__ void k_ln1(const float* __restrict__ x,
                      const float* __restrict__ gam,
                      const float* __restrict__ bet) {
    int row = blockIdx.x;
    int t = threadIdx.x;
    int w = t >> 5, lane = t & 31;
    __shared__ float red[8];

    float v = x[(size_t)row * Dd + t];
    float s = warpSum(v);
    if (lane == 0) red[w] = s;
    __syncthreads();
    float mu = 0.f;
#pragma unroll
    for (int i = 0; i < 8; i++) mu += red[i];
    mu *= (1.f / 256.f);
    float d = v - mu;
    __syncthreads();
    s = warpSum(d * d);
    if (lane == 0) red[w] = s;
    __syncthreads();
    float var = 0.f;
#pragma unroll
    for (int i = 0; i < 8; i++) var += red[i];
    var *= (1.f / 256.f);
    float r = d * rsqrtf(var + 1e-6f) * gam[t] + bet[t];
    __nv_bfloat16 h, l;
    hilo(r, h, l);
    g_xh[(size_t)row * Dd + t] = h;
    g_xl[(size_t)row * Dd + t] = l;
}

// ============ Kernel 2: QKVG projections via mma.sync bf16x3 ===============
// q outputs are pre-scaled by 1/sqrt(E)*log2(e) for the log2-domain softmax.
#define QSCALE 0.2550868099f

__global__ void __launch_bounds__(256)
k_qkvg() {
    __shared__ __align__(16) __nv_bfloat16 Ahi[128 * 40];
    __shared__ __align__(16) __nv_bfloat16 Alo[128 * 40];
    __shared__ __align__(16) __nv_bfloat16 Bhi[64 * 40];
    __shared__ __align__(16) __nv_bfloat16 Blo[64 * 40];

    int tid = threadIdx.x;
    int wid = tid >> 5, lane = tid & 31;
    int wm = wid & 3, wn = wid >> 2;

    int m0 = blockIdx.x * 128;
    int n0 = blockIdx.y * 64;
    int proj = n0 >> 8;
    int nin = n0 & 255;

    uint32_t ahi_b = smem_u32(Ahi), alo_b = smem_u32(Alo);
    uint32_t bhi_b = smem_u32(Bhi), blo_b = smem_u32(Blo);

    float acc[2][4][4];
#pragma unroll
    for (int i = 0; i < 2; i++)
#pragma unroll
        for (int j = 0; j < 4; j++)
#pragma unroll
            for (int c = 0; c < 4; c++) acc[i][j][c] = 0.f;

    int a_row = (lane & 15);
    int a_kof = (lane >> 4) * 8;
    int b_row = ((lane >> 4) & 1) * 8 + (lane & 7);
    int b_kof = ((lane >> 3) & 1) * 8;

    for (int k0 = 0; k0 < 256; k0 += 32) {
#pragma unroll
        for (int it = 0; it < 2; it++) {
            int idx = tid + it * 256;
            int row = idx >> 2, q = idx & 3;
            *(uint4*)&Ahi[row * 40 + q * 8] =
                *(const uint4*)&g_xh[(size_t)(m0 + row) * 256 + k0 + q * 8];
            *(uint4*)&Alo[row * 40 + q * 8] =
                *(const uint4*)&g_xl[(size_t)(m0 + row) * 256 + k0 + q * 8];
        }
        {
            int n = tid >> 2, q = tid & 3;
            size_t src = (size_t)(proj * 256 + nin + n) * 256 + k0 + q * 8;
            *(uint4*)&Bhi[n * 40 + q * 8] = *(const uint4*)&g_wh[src];
            *(uint4*)&Blo[n * 40 + q * 8] = *(const uint4*)&g_wl[src];
        }
        __syncthreads();

#pragma unroll
        for (int ks = 0; ks < 2; ks++) {
            int kk = ks * 16;
            uint32_t ah[2][4], al[2][4];
#pragma unroll
            for (int mt = 0; mt < 2; mt++) {
                int row = wm * 32 + mt * 16 + a_row;
                uint32_t off = (uint32_t)(row * 40 + kk + a_kof) * 2;
                ldsm4(ah[mt][0], ah[mt][1], ah[mt][2], ah[mt][3], ahi_b + off);
                ldsm4(al[mt][0], al[mt][1], al[mt][2], al[mt][3], alo_b + off);
            }
            uint32_t bh[4][2], bl[4][2];
#pragma unroll
            for (int jp = 0; jp < 2; jp++) {
                int row = wn * 32 + jp * 16 + b_row;
                uint32_t off = (uint32_t)(row * 40 + kk + b_kof) * 2;
                ldsm4(bh[jp*2][0], bh[jp*2][1], bh[jp*2+1][0], bh[jp*2+1][1],
                      bhi_b + off);
                ldsm4(bl[jp*2][0], bl[jp*2][1], bl[jp*2+1][0], bl[jp*2+1][1],
                      blo_b + off);
            }
#pragma unroll
            for (int mt = 0; mt < 2; mt++)
#pragma unroll
                for (int j = 0; j < 4; j++) {
                    mma16816(acc[mt][j], ah[mt], bh[j]);
                    mma16816(acc[mt][j], ah[mt], bl[j]);
                    mma16816(acc[mt][j], al[mt], bh[j]);
                }
        }
        __syncthreads();
    }

    // pre-scale q for log2-domain softmax
    if (proj == 0) {
#pragma unroll
        for (int mt = 0; mt < 2; mt++)
#pragma unroll
            for (int j = 0; j < 4; j++)
#pragma unroll
                for (int c = 0; c < 4; c++) acc[mt][j][c] *= QSCALE;
    }

    int h = (nin + wn * 32) >> 5;
    __nv_bfloat16* Oh = (proj == 0) ? g_qh : (proj == 1) ? g_kh : g_vh;
    __nv_bfloat16* Ol = (proj == 0) ? g_ql : (proj == 1) ? g_kl : g_vl;
    bool isG = (proj == 3);
#pragma unroll
    for (int mt = 0; mt < 2; mt++) {
        int m = m0 + wm * 32 + mt * 16 + (lane >> 2);
        int b1 = m / Ss, s1 = m - b1 * Ss;
        int m2 = m + 8;
        int b2 = m2 / Ss, s2 = m2 - b2 * Ss;
        size_t i1 = (((size_t)(b1 * Hh + h)) * Ss + s1) * Ee;
        size_t i2 = (((size_t)(b2 * Hh + h)) * Ss + s2) * Ee;
#pragma unroll
        for (int j = 0; j < 4; j++) {
            int e = j * 8 + (lane & 3) * 2;
            if (isG) {
                *(float2*)&g_g[i1 + e] = make_float2(acc[mt][j][0], acc[mt][j][1]);
                *(float2*)&g_g[i2 + e] = make_float2(acc[mt][j][2], acc[mt][j][3]);
            } else {
                uint32_t h1, l1, h2, l2;
                packhl2(acc[mt][j][0], acc[mt][j][1], h1, l1);
                packhl2(acc[mt][j][2], acc[mt][j][3], h2, l2);
                *(uint32_t*)&Oh[i1 + e] = h1;
                *(uint32_t*)&Ol[i1 + e] = l1;
                *(uint32_t*)&Oh[i2 + e] = h2;
                *(uint32_t*)&Ol[i2 + e] = l2;
            }
        }
    }
}

// ==== Kernel 3: attention; 2 groups, Q via LDG, log2-domain softmax ========
#define KHI_OFF   0                       // 416*40*2 = 33280
#define KLO_OFF   33280
#define VH_OFF    66560
#define VL_OFF    99840
#define CSH_OFF   133120                  // 416*4 = 1664
#define RED_OFF   134784                  // 2*32*8*4 = 2048
#define OP_OFF    136832                  // 2*4*32*32*4 = 32768
#define ATTN_SMEM 169600

__global__ void __launch_bounds__(512, 1)
k_attn(const float* __restrict__ pmask, const float* __restrict__ mmask) {
    extern __shared__ char smc[];
    __nv_bfloat16* khi = (__nv_bfloat16*)(smc + KHI_OFF);
    __nv_bfloat16* klo = (__nv_bfloat16*)(smc + KLO_OFF);
    __nv_bfloat16* v_h = (__nv_bfloat16*)(smc + VH_OFF);
    __nv_bfloat16* v_l = (__nv_bfloat16*)(smc + VL_OFF);
    float*         c_sh = (float*)(smc + CSH_OFF);
    float*         red  = (float*)(smc + RED_OFF);   // [grp][row][nq*2+{m,s}]
    float*         opart = (float*)(smc + OP_OFF);   // [grp][nq][row][e]

    uint32_t khi_b = smem_u32(khi), klo_b = smem_u32(klo);
    uint32_t vh_b = smem_u32(v_h), vl_b = smem_u32(v_l);

    int tid = threadIdx.x;
    int lane = tid & 31;
    int bh = blockIdx.x;
    int h = bh & 7, b = bh >> 3;
    size_t baseBH = (size_t)(b * Hh + h) * Ss;

    // ---- stage K and V hi/lo (pure 16B copies), [y][*] stride 40 ----
    for (int i = tid; i < Ss * 4; i += 512) {
        int y = i >> 2, q = i & 3;
        size_t src = (baseBH + y) * Ee + q * 8;
        *(uint4*)&khi[y * 40 + q * 8] = *(const uint4*)&g_kh[src];
        *(uint4*)&klo[y * 40 + q * 8] = *(const uint4*)&g_kl[src];
        *(uint4*)&v_h[y * 40 + q * 8] = *(const uint4*)&g_vh[src];
        *(uint4*)&v_l[y * 40 + q * 8] = *(const uint4*)&g_vl[src];
    }
    for (int i = tid; i < Ss; i += 512) {
        float val = (i < Nn) ? pmask[b * Nn + i] : mmask[b * Mm + (i - Nn)];
        c_sh[i] = (val == -2.0f) ? 0.f : 1.f;
    }
    __syncthreads();

    const float BIGL = 1.0e9f;   // log2-domain "-inf" magnitude
    int grp = tid >> 8;
    int wg = (tid >> 5) & 7;
    int mh = (wg >> 2) & 1;
    int nq = wg & 3;
    int nbase = nq * 104;
    int gtid = tid & 255;

    int b_row = ((lane >> 4) & 1) * 8 + (lane & 7);
    int b_kof = ((lane >> 3) & 1) * 8;
    int fr = lane >> 2, fc = lane & 3;
    int lx1 = mh * 16 + fr;
    int lx2 = lx1 + 8;

    float* redg = red + grp * 256;
    float* opg  = opart + grp * 4096;
    int bar_id = grp + 1;

    for (int t = grp; t < 13; t += 2) {
        int x0 = t * 32;

        // ---- Q fragments directly from global (pre-scaled) ----
        uint32_t qah[2][4], qal[2][4];
        {
            const __nv_bfloat16* ph = g_qh + (baseBH + x0 + lx1) * 32;
            const __nv_bfloat16* pl = g_ql + (baseBH + x0 + lx1) * 32;
#pragma unroll
            for (int ks = 0; ks < 2; ks++) {
                int kk = ks * 16 + fc * 2;
                qah[ks][0] = *(const uint32_t*)&ph[kk];
                qah[ks][1] = *(const uint32_t*)&ph[256 + kk];
                qah[ks][2] = *(const uint32_t*)&ph[kk + 8];
                qah[ks][3] = *(const uint32_t*)&ph[256 + kk + 8];
                qal[ks][0] = *(const uint32_t*)&pl[kk];
                qal[ks][1] = *(const uint32_t*)&pl[256 + kk];
                qal[ks][2] = *(const uint32_t*)&pl[kk + 8];
                qal[ks][3] = *(const uint32_t*)&pl[256 + kk + 8];
            }
        }

        // ---- QK^T (scores in log2 domain) ----
        float acc[13][4];
#pragma unroll
        for (int t2 = 0; t2 < 13; t2++)
#pragma unroll
            for (int c = 0; c < 4; c++) acc[t2][c] = 0.f;

#pragma unroll
        for (int ks = 0; ks < 2; ks++) {
            int kk = ks * 16;
#pragma unroll
            for (int jp = 0; jp < 6; jp++) {
                uint32_t bh2[4], bl2[4];
                uint32_t off = (uint32_t)((nbase + jp * 16 + b_row) * 40
                                          + kk + b_kof) * 2;
                ldsm4(bh2[0], bh2[1], bh2[2], bh2[3], khi_b + off);
                ldsm4(bl2[0], bl2[1], bl2[2], bl2[3], klo_b + off);
                mma16816(acc[jp*2],   qah[ks], &bh2[0]);
                mma16816(acc[jp*2],   qah[ks], &bl2[0]);
                mma16816(acc[jp*2],   qal[ks], &bh2[0]);
                mma16816(acc[jp*2+1], qah[ks], &bh2[2]);
                mma16816(acc[jp*2+1], qah[ks], &bl2[2]);
                mma16816(acc[jp*2+1], qal[ks], &bh2[2]);
            }
            {
                uint32_t bh1[2], bl1[2];
                uint32_t off = (uint32_t)((nbase + 96 + (lane & 7)) * 40 + kk
                                          + 8 * ((lane >> 3) & 1)) * 2;
                ldsm2(bh1[0], bh1[1], khi_b + off);
                ldsm2(bl1[0], bl1[1], klo_b + off);
                mma16816(acc[12], qah[ks], bh1);
                mma16816(acc[12], qah[ks], bl1);
                mma16816(acc[12], qal[ks], bh1);
            }
        }

        // ---- mask bias (y-only; cx handled via f) ----
        bool xIsP = (t == 0);
        float cx1 = c_sh[x0 + lx1];
        float cx2 = c_sh[x0 + lx2];
#pragma unroll
        for (int t2 = 0; t2 < 13; t2++) {
            int ybase = nbase + t2 * 8;
            int yc = ybase + fc * 2;
            bool cross = (xIsP != (ybase < Nn));
            float cy0 = c_sh[yc], cy1 = c_sh[yc + 1];
            float by0 = cross ? fmaf(cy0, BIGL, -BIGL) : -BIGL;
            float by1 = cross ? fmaf(cy1, BIGL, -BIGL) : -BIGL;
            acc[t2][0] += by0;
            acc[t2][1] += by1;
            acc[t2][2] += by0;
            acc[t2][3] += by1;
        }

        // ---- local softmax (log2 domain, quad reductions) ----
        float m1 = -3.0e38f, m2 = -3.0e38f;
#pragma unroll
        for (int t2 = 0; t2 < 13; t2++) {
            m1 = fmaxf(m1, fmaxf(acc[t2][0], acc[t2][1]));
            m2 = fmaxf(m2, fmaxf(acc[t2][2], acc[t2][3]));
        }
#pragma unroll
        for (int o = 1; o <= 2; o <<= 1) {
            m1 = fmaxf(m1, __shfl_xor_sync(0xffffffffu, m1, o));
            m2 = fmaxf(m2, __shfl_xor_sync(0xffffffffu, m2, o));
        }
        float s1 = 0.f, s2 = 0.f;
#pragma unroll
        for (int t2 = 0; t2 < 13; t2++) {
            acc[t2][0] = ex2f(acc[t2][0] - m1);
            acc[t2][1] = ex2f(acc[t2][1] - m1);
            acc[t2][2] = ex2f(acc[t2][2] - m2);
            acc[t2][3] = ex2f(acc[t2][3] - m2);
            s1 += acc[t2][0] + acc[t2][1];
            s2 += acc[t2][2] + acc[t2][3];
        }
#pragma unroll
        for (int o = 1; o <= 2; o <<= 1) {
            s1 += __shfl_xor_sync(0xffffffffu, s1, o);
            s2 += __shfl_xor_sync(0xffffffffu, s2, o);
        }
        if (fc == 0) {
            redg[lx1 * 8 + nq * 2]     = m1;
            redg[lx1 * 8 + nq * 2 + 1] = s1;
            redg[lx2 * 8 + nq * 2]     = m2;
            redg[lx2 * 8 + nq * 2 + 1] = s2;
        }
        asm volatile("bar.sync %0, %1;" :: "r"(bar_id), "r"(256) : "memory");
        float f1, f2;
        {
            float M1 = -3.0e38f, M2 = -3.0e38f;
#pragma unroll
            for (int q = 0; q < 4; q++) {
                M1 = fmaxf(M1, redg[lx1 * 8 + q * 2]);
                M2 = fmaxf(M2, redg[lx2 * 8 + q * 2]);
            }
            float S1 = 0.f, S2 = 0.f;
#pragma unroll
            for (int q = 0; q < 4; q++) {
                S1 += redg[lx1 * 8 + q * 2 + 1] * ex2f(redg[lx1 * 8 + q * 2] - M1);
                S2 += redg[lx2 * 8 + q * 2 + 1] * ex2f(redg[lx2 * 8 + q * 2] - M2);
            }
            f1 = cx1 * ex2f(m1 - M1) / S1;
            f2 = cx2 * ex2f(m2 - M2) / S2;
        }

        // ---- AV: A from C-fragments, partial O over warp's y-slice ----
        {
            float o[4][4];
#pragma unroll
            for (int eg = 0; eg < 4; eg++)
#pragma unroll
                for (int c = 0; c < 4; c++) o[eg][c] = 0.f;

#pragma unroll
            for (int g = 0; g < 3; g++) {
                uint32_t Ah0[4], Al0[4], Ah1[4], Al1[4];
                {
                    int ta = 4 * g, tb = 4 * g + 1;
                    packhl2(acc[ta][0] * f1, acc[ta][1] * f1, Ah0[0], Al0[0]);
                    packhl2(acc[ta][2] * f2, acc[ta][3] * f2, Ah0[1], Al0[1]);
                    packhl2(acc[tb][0] * f1, acc[tb][1] * f1, Ah0[2], Al0[2]);
                    packhl2(acc[tb][2] * f2, acc[tb][3] * f2, Ah0[3], Al0[3]);
                    int tc = 4 * g + 2, td = 4 * g + 3;
                    packhl2(acc[tc][0] * f1, acc[tc][1] * f1, Ah1[0], Al1[0]);
                    packhl2(acc[tc][2] * f2, acc[tc][3] * f2, Ah1[1], Al1[1]);
                    packhl2(acc[td][0] * f1, acc[td][1] * f1, Ah1[2], Al1[2]);
                    packhl2(acc[td][2] * f2, acc[td][3] * f2, Ah1[3], Al1[3]);
                }
#pragma unroll
                for (int eg = 0; eg < 4; eg++) {
                    uint32_t bh4[4], bl4[4];
                    uint32_t offB = (uint32_t)((nbase + g * 32 + lane) * 40
                                               + eg * 8) * 2;
                    ldsm4t(bh4[0], bh4[1], bh4[2], bh4[3], vh_b + offB);
                    ldsm4t(bl4[0], bl4[1], bl4[2], bl4[3], vl_b + offB);
                    mma16816(o[eg], Ah0, &bh4[0]);
                    mma16816(o[eg], Ah0, &bl4[0]);
                    mma16816(o[eg], Al0, &bh4[0]);
                    mma16816(o[eg], Ah1, &bh4[2]);
                    mma16816(o[eg], Ah1, &bl4[2]);
                    mma16816(o[eg], Al1, &bh4[2]);
                }
            }
            {   // tail tile 12: k8
                uint32_t Ath[2], Atl[2];
                packhl2(acc[12][0] * f1, acc[12][1] * f1, Ath[0], Atl[0]);
                packhl2(acc[12][2] * f2, acc[12][3] * f2, Ath[1], Atl[1]);
                uint32_t bh4[4], bl4[4];
                uint32_t offT = (uint32_t)((nbase + 96 + (lane & 7)) * 40
                                           + (lane >> 3) * 8) * 2;
                ldsm4t(bh4[0], bh4[1], bh4[2], bh4[3], vh_b + offT);
                ldsm4t(bl4[0], bl4[1], bl4[2], bl4[3], vl_b + offT);
#pragma unroll
                for (int eg = 0; eg < 4; eg++) {
                    mma1688(o[eg], Ath, bh4[eg]);
                    mma1688(o[eg], Ath, bl4[eg]);
                    mma1688(o[eg], Atl, bh4[eg]);
                }
            }
            float* op = opg + nq * 1024;
#pragma unroll
            for (int eg = 0; eg < 4; eg++) {
                int e = eg * 8 + fc * 2;
                *(float2*)&op[lx1 * 32 + e] = make_float2(o[eg][0], o[eg][1]);
                *(float2*)&op[lx2 * 32 + e] = make_float2(o[eg][2], o[eg][3]);
            }
        }
        asm volatile("bar.sync %0, %1;" :: "r"(bar_id), "r"(256) : "memory");

        // ---- reduce over nq + gate + store (group-local) ----
#pragma unroll
        for (int it = 0; it < 2; it++) {
            int idx = gtid + it * 256;         // 0..511 -> pairs of e
            int row = idx >> 4;
            int e = (idx & 15) * 2;
            const float* op = opg + row * 32 + e;
            float sum0 = op[0] + op[1024] + op[2048] + op[3072];
            float sum1 = op[1] + op[1025] + op[2049] + op[3073];
            int xs_ = x0 + row;
            float2 gv = *(const float2*)&g_g[(baseBH + xs_) * Ee + e];
            float sg0 = 1.f / (1.f + __expf(-gv.x));
            float sg1 = 1.f / (1.f + __expf(-gv.y));
            float o0 = sum0 * sg0;
            float o1 = sum1 * sg1;
            uint32_t oh, ol;
            packhl2(o0, o1, oh, ol);
            size_t di = ((size_t)b * Ss + xs_) * Oo + h * Ee + e;
            *(uint32_t*)&g_aoh[di] = oh;
            *(uint32_t*)&g_aol[di] = ol;
        }
        // no barrier needed: next-iter opart writes are fenced by the
        // red-exchange barrier; redg writes by the post-AV barrier.
    }
}

// ============ Kernel 4: output projection (HMMA bf16x3) + LN2 ==============
#define OAHI_OFF 0
#define OALO_OFF 2560
#define OBHI_OFF 5120
#define OBLO_OFF 25600
#define OYS_OFF  46080
#define OMU_OFF  79872
#define ORS_OFF  80000
#define OLN_SMEM 80128

__global__ void __launch_bounds__(256)
k_outln(const float* __restrict__ bias, const float* __restrict__ g2,
        const float* __restrict__ b2, float* __restrict__ out) {
    extern __shared__ char smo[];
    __nv_bfloat16* Ahi = (__nv_bfloat16*)(smo + OAHI_OFF);
    __nv_bfloat16* Alo = (__nv_bfloat16*)(smo + OALO_OFF);
    __nv_bfloat16* Bhi = (__nv_bfloat16*)(smo + OBHI_OFF);
    __nv_bfloat16* Blo = (__nv_bfloat16*)(smo + OBLO_OFF);
    float* ys  = (float*)(smo + OYS_OFF);
    float* mus = (float*)(smo + OMU_OFF);
    float* rss = (float*)(smo + ORS_OFF);

    uint32_t ahi_b = smem_u32(Ahi), alo_b = smem_u32(Alo);
    uint32_t bhi_b = smem_u32(Bhi), blo_b = smem_u32(Blo);

    int tid = threadIdx.x;
    int wid = tid >> 5, lane = tid & 31;
    int mh = wid & 1, nq = wid >> 1;
    int r0 = blockIdx.x * 32;

    int a_row = (lane & 15);
    int a_kof = (lane >> 4) * 8;
    int b_row = ((lane >> 4) & 1) * 8 + (lane & 7);
    int b_kof = ((lane >> 3) & 1) * 8;

    float acc[8][4];
#pragma unroll
    for (int j = 0; j < 8; j++)
#pragma unroll
        for (int c = 0; c < 4; c++) acc[j][c] = 0.f;

    for (int k0 = 0; k0 < 256; k0 += 32) {
        {
            int i = tid & 127;
            int row = i >> 2, q = i & 3;
            size_t src = (size_t)(r0 + row) * 256 + k0 + q * 8;
            if (tid < 128)
                *(uint4*)&Ahi[row * 40 + q * 8] = *(const uint4*)&g_aoh[src];
            else
                *(uint4*)&Alo[row * 40 + q * 8] = *(const uint4*)&g_aol[src];
        }
#pragma unroll
        for (int it = 0; it < 8; it++) {
            int idx = tid + it * 256;
            int rem = idx & 1023;
            int n = rem >> 2, q = rem & 3;
            size_t src = (size_t)(4 * 256 + n) * 256 + k0 + q * 8;
            if (idx < 1024)
                *(uint4*)&Bhi[n * 40 + q * 8] = *(const uint4*)&g_wh[src];
            else
                *(uint4*)&Blo[n * 40 + q * 8] = *(const uint4*)&g_wl[src];
        }
        __syncthreads();

#pragma unroll
        for (int ks = 0; ks < 2; ks++) {
            int kk = ks * 16;
            uint32_t ah[4], al[4];
            {
                uint32_t off = (uint32_t)((mh * 16 + a_row) * 40 + kk + a_kof) * 2;
                ldsm4(ah[0], ah[1], ah[2], ah[3], ahi_b + off);
                ldsm4(al[0], al[1], al[2], al[3], alo_b + off);
            }
#pragma unroll
            for (int jp = 0; jp < 4; jp++) {
                uint32_t bh2[4], bl2[4];
                uint32_t off = (uint32_t)((nq * 64 + jp * 16 + b_row) * 40 + kk + b_kof) * 2;
                ldsm4(bh2[0], bh2[1], bh2[2], bh2[3], bhi_b + off);
                ldsm4(bl2[0], bl2[1], bl2[2], bl2[3], blo_b + off);
                mma16816(acc[jp*2],   ah, &bh2[0]);
                mma16816(acc[jp*2],   ah, &bl2[0]);
                mma16816(acc[jp*2],   al, &bh2[0]);
                mma16816(acc[jp*2+1], ah, &bh2[2]);
                mma16816(acc[jp*2+1], ah, &bl2[2]);
                mma16816(acc[jp*2+1], al, &bh2[2]);
            }
        }
        __syncthreads();
    }

    int lx1 = mh * 16 + (lane >> 2);
    int lx2 = lx1 + 8;
#pragma unroll
    for (int j = 0; j < 8; j++) {
        int n = nq * 64 + j * 8 + (lane & 3) * 2;
        float b0 = bias[n], b1 = bias[n + 1];
        ys[lx1 * 264 + n]     = acc[j][0] + b0;
        ys[lx1 * 264 + n + 1] = acc[j][1] + b1;
        ys[lx2 * 264 + n]     = acc[j][2] + b0;
        ys[lx2 * 264 + n + 1] = acc[j][3] + b1;
    }
    __syncthreads();

#pragma unroll
    for (int rr = 0; rr < 4; rr++) {
        int xr = wid + rr * 8;
        const float* row = ys + xr * 264;
        float s = 0.f;
#pragma unroll
        for (int j = 0; j < 8; j++) s += row[lane + 32 * j];
        s = warpSum(s);
        float mu = s * (1.f / 256.f);
        float vs = 0.f;
#pragma unroll
        for (int j = 0; j < 8; j++) {
            float d = row[lane + 32 * j] - mu;
            vs += d * d;
        }
        vs = warpSum(vs);
        if (lane == 0) { mus[xr] = mu; rss[xr] = rsqrtf(vs * (1.f / 256.f) + 1e-6f); }
    }
    __syncthreads();

    float gt = g2[tid], bt = b2[tid];
#pragma unroll 4
    for (int r = 0; r < 32; r++) {
        out[(size_t)(r0 + r) * 256 + tid] =
            (ys[r * 264 + tid] - mus[r]) * rss[r] * gt + bt;
    }
}

// ===========================================================================
extern "C" void kernel_launch(void* const* d_in, const int* in_sizes, int n_in,
                              void* d_out, int out_size) {
    const float* x   = (const float*)d_in[0];
    const float* pm  = (const float*)d_in[1];
    const float* mm  = (const float*)d_in[2];
    const float* qp  = (const float*)d_in[3];
    const float* kp  = (const float*)d_in[4];
    const float* vp  = (const float*)d_in[5];
    const float* gp  = (const float*)d_in[6];
    const float* ow  = (const float*)d_in[7];
    const float* ob  = (const float*)d_in[8];
    const float* l1g = (const float*)d_in[9];
    const float* l1b = (const float*)d_in[10];
    const float* l2g = (const float*)d_in[11];
    const float* l2b = (const float*)d_in[12];
    float* out = (float*)d_out;

    cudaFuncSetAttribute(k_attn, cudaFuncAttributeMaxDynamicSharedMemorySize,
                         ATTN_SMEM);
    cudaFuncSetAttribute(k_outln, cudaFuncAttributeMaxDynamicSharedMemorySize,
                         OLN_SMEM);

    k_wconv<<<dim3(256, 5), 256>>>(qp, kp, vp, gp, ow);
    k_ln1  <<<BSs, 256>>>(x, l1g, l1b);
    k_qkvg <<<dim3(416, 16), 256>>>();
    k_attn <<<Bb * Hh, 512, ATTN_SMEM>>>(pm, mm);
    k_outln<<<BSs / 32, 256, OLN_SMEM>>>(ob, l2g, l2b, out);
}

// round 12
// speedup vs baseline: 3.1416x; 1.0240x over previous
#include <cuda_runtime.h>
#include <cuda_bf16.h>
#include <cstdint>

#define Bb   128
#define Ss   416
#define Nn   32
#define Mm   384
#define Dd   256
#define Hh   8
#define Ee   32
#define Oo   256
#define BSs  (Bb*Ss)          // 53248
#define NBH  (Bb*Hh*Ss*Ee)    // 13,631,488

// -------- scratch (static device globals; no runtime allocation) ----------
__device__ __nv_bfloat16 g_xh[BSs*Dd], g_xl[BSs*Dd];
__device__ __nv_bfloat16 g_wh[5*256*256], g_wl[5*256*256];  // [proj][n][k]; 4=out_w
__device__ __nv_bfloat16 g_qh[NBH], g_ql[NBH];
__device__ __nv_bfloat16 g_kh[NBH], g_kl[NBH];
__device__ __nv_bfloat16 g_vh[NBH], g_vl[NBH];
__device__ float         g_g [NBH];
__device__ __nv_bfloat16 g_aoh[BSs*Oo], g_aol[BSs*Oo];

__device__ __forceinline__ float warpSum(float v) {
#pragma unroll
    for (int o = 16; o; o >>= 1) v += __shfl_xor_sync(0xffffffffu, v, o);
    return v;
}

// -------- mma.sync helpers --------------------------------------------------
__device__ __forceinline__ uint32_t smem_u32(const void* p) {
    uint32_t a;
    asm("{ .reg .u64 t; cvta.to.shared.u64 t, %1; cvt.u32.u64 %0, t; }"
        : "=r"(a) : "l"(p));
    return a;
}
__device__ __forceinline__ void ldsm4(uint32_t& r0, uint32_t& r1,
                                      uint32_t& r2, uint32_t& r3, uint32_t a) {
    asm volatile("ldmatrix.sync.aligned.m8n8.x4.shared.b16 {%0,%1,%2,%3}, [%4];"
                 : "=r"(r0), "=r"(r1), "=r"(r2), "=r"(r3) : "r"(a));
}
__device__ __forceinline__ void ldsm4t(uint32_t& r0, uint32_t& r1,
                                       uint32_t& r2, uint32_t& r3, uint32_t a) {
    asm volatile("ldmatrix.sync.aligned.m8n8.x4.trans.shared.b16 {%0,%1,%2,%3}, [%4];"
                 : "=r"(r0), "=r"(r1), "=r"(r2), "=r"(r3) : "r"(a));
}
__device__ __forceinline__ void ldsm2(uint32_t& r0, uint32_t& r1, uint32_t a) {
    asm volatile("ldmatrix.sync.aligned.m8n8.x2.shared.b16 {%0,%1}, [%2];"
                 : "=r"(r0), "=r"(r1) : "r"(a));
}
__device__ __forceinline__ void mma16816(float* d, const uint32_t* a,
                                         const uint32_t* b) {
    asm volatile(
        "mma.sync.aligned.m16n8k16.row.col.f32.bf16.bf16.f32 "
        "{%0,%1,%2,%3}, {%4,%5,%6,%7}, {%8,%9}, {%0,%1,%2,%3};"
        : "+f"(d[0]), "+f"(d[1]), "+f"(d[2]), "+f"(d[3])
        : "r"(a[0]), "r"(a[1]), "r"(a[2]), "r"(a[3]), "r"(b[0]), "r"(b[1]));
}
__device__ __forceinline__ void mma1688(float* d, const uint32_t* a, uint32_t b) {
    asm volatile(
        "mma.sync.aligned.m16n8k8.row.col.f32.bf16.bf16.f32 "
        "{%0,%1,%2,%3}, {%4,%5}, {%6}, {%0,%1,%2,%3};"
        : "+f"(d[0]), "+f"(d[1]), "+f"(d[2]), "+f"(d[3])
        : "r"(a[0]), "r"(a[1]), "r"(b));
}
__device__ __forceinline__ void hilo(float v, __nv_bfloat16& h, __nv_bfloat16& l) {
    h = __float2bfloat16(v);
    l = __float2bfloat16(v - __bfloat162float(h));
}
// fast hi/lo pack of a float pair: (x->low half, y->high half)
__device__ __forceinline__ void packhl2(float x, float y,
                                        uint32_t& ph, uint32_t& pl) {
    asm("cvt.rn.bf16x2.f32 %0, %1, %2;" : "=r"(ph) : "f"(y), "f"(x));
    float xh = __uint_as_float(ph << 16);
    float yh = __uint_as_float(ph & 0xFFFF0000u);
    float xl = x - xh;
    float yl = y - yh;
    asm("cvt.rn.bf16x2.f32 %0, %1, %2;" : "=r"(pl) : "f"(yl), "f"(xl));
}
__device__ __forceinline__ float ex2f(float x) {
    float r; asm("ex2.approx.f32 %0, %1;" : "=f"(r) : "f"(x)); return r;
}

// ========== Kernel 0: one-time weight conversion to hi/lo bf16 [n][k] ======
__global__ void k_wconv(const float* __restrict__ qp, const float* __restrict__ kp,
                        const float* __restrict__ vp, const float* __restrict__ gp,
                        const float* __restrict__ ow) {
    int n = blockIdx.x;
    int proj = blockIdx.y;
    int k = threadIdx.x;
    float v;
    if (proj < 4) {
        const float* Wp = (proj == 0) ? qp : (proj == 1) ? kp
                         : (proj == 2) ? vp : gp;
        v = Wp[(n >> 5) * 8192 + k * 32 + (n & 31)];
    } else {
        v = ow[k * 256 + n];
    }
    __nv_bfloat16 h, l;
    hilo(v, h, l);
    size_t idx = (size_t)(proj * 256 + n) * 256 + k;
    g_wh[idx] = h;
    g_wl[idx] = l;
}

// =================== Kernel 1: LayerNorm -> hi/lo bf16 =====================
__global__ void k_ln1(const float* __restrict__ x,
                      const float* __restrict__ gam,
                      const float* __restrict__ bet) {
    int row = blockIdx.x;
    int t = threadIdx.x;
    int w = t >> 5, lane = t & 31;
    __shared__ float red[8];

    float v = x[(size_t)row * Dd + t];
    float s = warpSum(v);
    if (lane == 0) red[w] = s;
    __syncthreads();
    float mu = 0.f;
#pragma unroll
    for (int i = 0; i < 8; i++) mu += red[i];
    mu *= (1.f / 256.f);
    float d = v - mu;
    __syncthreads();
    s = warpSum(d * d);
    if (lane == 0) red[w] = s;
    __syncthreads();
    float var = 0.f;
#pragma unroll
    for (int i = 0; i < 8; i++) var += red[i];
    var *= (1.f / 256.f);
    float r = d * rsqrtf(var + 1e-6f) * gam[t] + bet[t];
    __nv_bfloat16 h, l;
    hilo(r, h, l);
    g_xh[(size_t)row * Dd + t] = h;
    g_xl[(size_t)row * Dd + t] = l;
}

// ==== Kernel 2: QKVG; A staged ONCE per block, loop all 16 n-tiles =========
#define QSCALE 0.2550868099f
#define QK_AHI 0
#define QK_ALO (128*264*2)                 // 67584
#define QK_BHI (2*128*264*2)               // 135168
#define QK_BLO (QK_BHI + 64*264*2)         // 168960
#define QKVG_SMEM (QK_BHI + 2*64*264*2)    // 202752

__global__ void __launch_bounds__(512, 1)
k_qkvg() {
    extern __shared__ char smq[];
    __nv_bfloat16* Ahi = (__nv_bfloat16*)(smq + QK_AHI);
    __nv_bfloat16* Alo = (__nv_bfloat16*)(smq + QK_ALO);
    __nv_bfloat16* Bhi = (__nv_bfloat16*)(smq + QK_BHI);
    __nv_bfloat16* Blo = (__nv_bfloat16*)(smq + QK_BLO);
    uint32_t ahi_b = smem_u32(Ahi), alo_b = smem_u32(Alo);
    uint32_t bhi_b = smem_u32(Bhi), blo_b = smem_u32(Blo);

    int tid = threadIdx.x;
    int wid = tid >> 5, lane = tid & 31;
    int wm = wid >> 1, wn = wid & 1;       // 8 m-slices x 2 n-halves
    int m0 = blockIdx.x * 128;

    // ---- stage A once: 128 x 256 hi/lo, stride 264 ----
#pragma unroll
    for (int it = 0; it < 16; it++) {
        int idx = tid + it * 512;          // 0..8191
        int buf = idx >> 12;
        int rem = idx & 4095;
        int row = rem >> 5, q = rem & 31;
        const __nv_bfloat16* src = buf ? g_xl : g_xh;
        __nv_bfloat16* dst = buf ? Alo : Ahi;
        *(uint4*)&dst[row * 264 + q * 8] =
            *(const uint4*)&src[(size_t)(m0 + row) * 256 + q * 8];
    }

    int a_row = lane & 15;
    int a_kof = (lane >> 4) * 8;
    int b_row = ((lane >> 4) & 1) * 8 + (lane & 7);
    int b_kof = ((lane >> 3) & 1) * 8;
    int fr = lane >> 2, fc = lane & 3;

    for (int nt = 0; nt < 16; nt++) {
        int proj = nt >> 2;
        int nin = (nt & 3) * 64;
        // ---- stage B tile: 64 x 256 hi/lo ----
        __syncthreads();   // previous compute done before overwriting B
#pragma unroll
        for (int it = 0; it < 8; it++) {
            int idx = tid + it * 512;      // 0..4095
            int buf = idx >> 11;
            int rem = idx & 2047;
            int n = rem >> 5, q = rem & 31;
            const __nv_bfloat16* src = buf ? g_wl : g_wh;
            __nv_bfloat16* dst = buf ? Blo : Bhi;
            *(uint4*)&dst[n * 264 + q * 8] =
                *(const uint4*)&src[(size_t)(proj * 256 + nin + n) * 256 + q * 8];
        }
        __syncthreads();

        float acc[4][4];
#pragma unroll
        for (int j = 0; j < 4; j++)
#pragma unroll
            for (int c = 0; c < 4; c++) acc[j][c] = 0.f;

        for (int k0 = 0; k0 < 256; k0 += 32) {
#pragma unroll
            for (int ks = 0; ks < 2; ks++) {
                int kk = k0 + ks * 16;
                uint32_t ah[4], al[4];
                {
                    uint32_t off = (uint32_t)((wm * 16 + a_row) * 264
                                              + kk + a_kof) * 2;
                    ldsm4(ah[0], ah[1], ah[2], ah[3], ahi_b + off);
                    ldsm4(al[0], al[1], al[2], al[3], alo_b + off);
                }
#pragma unroll
                for (int jp = 0; jp < 2; jp++) {
                    uint32_t bh2[4], bl2[4];
                    uint32_t off = (uint32_t)((wn * 32 + jp * 16 + b_row) * 264
                                              + kk + b_kof) * 2;
                    ldsm4(bh2[0], bh2[1], bh2[2], bh2[3], bhi_b + off);
                    ldsm4(bl2[0], bl2[1], bl2[2], bl2[3], blo_b + off);
                    mma16816(acc[jp*2],   ah, &bh2[0]);
                    mma16816(acc[jp*2],   ah, &bl2[0]);
                    mma16816(acc[jp*2],   al, &bh2[0]);
                    mma16816(acc[jp*2+1], ah, &bh2[2]);
                    mma16816(acc[jp*2+1], ah, &bl2[2]);
                    mma16816(acc[jp*2+1], al, &bh2[2]);
                }
            }
        }

        // pre-scale q for log2-domain softmax
        if (proj == 0) {
#pragma unroll
            for (int j = 0; j < 4; j++)
#pragma unroll
                for (int c = 0; c < 4; c++) acc[j][c] *= QSCALE;
        }

        // ---- epilogue -> q/k/v hi/lo bf16, g fp32; layout [B,H,S,E] ----
        int h = (nin + wn * 32) >> 5;
        __nv_bfloat16* Oh = (proj == 0) ? g_qh : (proj == 1) ? g_kh : g_vh;
        __nv_bfloat16* Ol = (proj == 0) ? g_ql : (proj == 1) ? g_kl : g_vl;
        bool isG = (proj == 3);
        int m = m0 + wm * 16 + fr;
        int b1 = m / Ss, s1 = m - b1 * Ss;
        int m2 = m + 8;
        int b2 = m2 / Ss, s2 = m2 - b2 * Ss;
        size_t i1 = (((size_t)(b1 * Hh + h)) * Ss + s1) * Ee;
        size_t i2 = (((size_t)(b2 * Hh + h)) * Ss + s2) * Ee;
#pragma unroll
        for (int j = 0; j < 4; j++) {
            int e = j * 8 + fc * 2;
            if (isG) {
                *(float2*)&g_g[i1 + e] = make_float2(acc[j][0], acc[j][1]);
                *(float2*)&g_g[i2 + e] = make_float2(acc[j][2], acc[j][3]);
            } else {
                uint32_t h1, l1, h2, l2;
                packhl2(acc[j][0], acc[j][1], h1, l1);
                packhl2(acc[j][2], acc[j][3], h2, l2);
                *(uint32_t*)&Oh[i1 + e] = h1;
                *(uint32_t*)&Ol[i1 + e] = l1;
                *(uint32_t*)&Oh[i2 + e] = h2;
                *(uint32_t*)&Ol[i2 + e] = l2;
            }
        }
    }
}

// ==== Kernel 3: attention; 2 groups, Q via LDG, log2-domain softmax ========
#define KHI_OFF   0                       // 416*40*2 = 33280
#define KLO_OFF   33280
#define VH_OFF    66560
#define VL_OFF    99840
#define CSH_OFF   133120                  // 416*4 = 1664
#define RED_OFF   134784                  // 2*32*8*4 = 2048
#define OP_OFF    136832                  // 2*4*32*32*4 = 32768
#define ATTN_SMEM 169600

__global__ void __launch_bounds__(512, 1)
k_attn(const float* __restrict__ pmask, const float* __restrict__ mmask) {
    extern __shared__ char smc[];
    __nv_bfloat16* khi = (__nv_bfloat16*)(smc + KHI_OFF);
    __nv_bfloat16* klo = (__nv_bfloat16*)(smc + KLO_OFF);
    __nv_bfloat16* v_h = (__nv_bfloat16*)(smc + VH_OFF);
    __nv_bfloat16* v_l = (__nv_bfloat16*)(smc + VL_OFF);
    float*         c_sh = (float*)(smc + CSH_OFF);
    float*         red  = (float*)(smc + RED_OFF);
    float*         opart = (float*)(smc + OP_OFF);

    uint32_t khi_b = smem_u32(khi), klo_b = smem_u32(klo);
    uint32_t vh_b = smem_u32(v_h), vl_b = smem_u32(v_l);

    int tid = threadIdx.x;
    int lane = tid & 31;
    int bh = blockIdx.x;
    int h = bh & 7, b = bh >> 3;
    size_t baseBH = (size_t)(b * Hh + h) * Ss;

    for (int i = tid; i < Ss * 4; i += 512) {
        int y = i >> 2, q = i & 3;
        size_t src = (baseBH + y) * Ee + q * 8;
        *(uint4*)&khi[y * 40 + q * 8] = *(const uint4*)&g_kh[src];
        *(uint4*)&klo[y * 40 + q * 8] = *(const uint4*)&g_kl[src];
        *(uint4*)&v_h[y * 40 + q * 8] = *(const uint4*)&g_vh[src];
        *(uint4*)&v_l[y * 40 + q * 8] = *(const uint4*)&g_vl[src];
    }
    for (int i = tid; i < Ss; i += 512) {
        float val = (i < Nn) ? pmask[b * Nn + i] : mmask[b * Mm + (i - Nn)];
        c_sh[i] = (val == -2.0f) ? 0.f : 1.f;
    }
    __syncthreads();

    const float BIGL = 1.0e9f;
    int grp = tid >> 8;
    int wg = (tid >> 5) & 7;
    int mh = (wg >> 2) & 1;
    int nq = wg & 3;
    int nbase = nq * 104;
    int gtid = tid & 255;

    int b_row = ((lane >> 4) & 1) * 8 + (lane & 7);
    int b_kof = ((lane >> 3) & 1) * 8;
    int fr = lane >> 2, fc = lane & 3;
    int lx1 = mh * 16 + fr;
    int lx2 = lx1 + 8;

    float* redg = red + grp * 256;
    float* opg  = opart + grp * 4096;
    int bar_id = grp + 1;

    for (int t = grp; t < 13; t += 2) {
        int x0 = t * 32;

        uint32_t qah[2][4], qal[2][4];
        {
            const __nv_bfloat16* ph = g_qh + (baseBH + x0 + lx1) * 32;
            const __nv_bfloat16* pl = g_ql + (baseBH + x0 + lx1) * 32;
#pragma unroll
            for (int ks = 0; ks < 2; ks++) {
                int kk = ks * 16 + fc * 2;
                qah[ks][0] = *(const uint32_t*)&ph[kk];
                qah[ks][1] = *(const uint32_t*)&ph[256 + kk];
                qah[ks][2] = *(const uint32_t*)&ph[kk + 8];
                qah[ks][3] = *(const uint32_t*)&ph[256 + kk + 8];
                qal[ks][0] = *(const uint32_t*)&pl[kk];
                qal[ks][1] = *(const uint32_t*)&pl[256 + kk];
                qal[ks][2] = *(const uint32_t*)&pl[kk + 8];
                qal[ks][3] = *(const uint32_t*)&pl[256 + kk + 8];
            }
        }

        float acc[13][4];
#pragma unroll
        for (int t2 = 0; t2 < 13; t2++)
#pragma unroll
            for (int c = 0; c < 4; c++) acc[t2][c] = 0.f;

#pragma unroll
        for (int ks = 0; ks < 2; ks++) {
            int kk = ks * 16;
#pragma unroll
            for (int jp = 0; jp < 6; jp++) {
                uint32_t bh2[4], bl2[4];
                uint32_t off = (uint32_t)((nbase + jp * 16 + b_row) * 40
                                          + kk + b_kof) * 2;
                ldsm4(bh2[0], bh2[1], bh2[2], bh2[3], khi_b + off);
                ldsm4(bl2[0], bl2[1], bl2[2], bl2[3], klo_b + off);
                mma16816(acc[jp*2],   qah[ks], &bh2[0]);
                mma16816(acc[jp*2],   qah[ks], &bl2[0]);
                mma16816(acc[jp*2],   qal[ks], &bh2[0]);
                mma16816(acc[jp*2+1], qah[ks], &bh2[2]);
                mma16816(acc[jp*2+1], qah[ks], &bl2[2]);
                mma16816(acc[jp*2+1], qal[ks], &bh2[2]);
            }
            {
                uint32_t bh1[2], bl1[2];
                uint32_t off = (uint32_t)((nbase + 96 + (lane & 7)) * 40 + kk
                                          + 8 * ((lane >> 3) & 1)) * 2;
                ldsm2(bh1[0], bh1[1], khi_b + off);
                ldsm2(bl1[0], bl1[1], klo_b + off);
                mma16816(acc[12], qah[ks], bh1);
                mma16816(acc[12], qah[ks], bl1);
                mma16816(acc[12], qal[ks], bh1);
            }
        }

        bool xIsP = (t == 0);
        float cx1 = c_sh[x0 + lx1];
        float cx2 = c_sh[x0 + lx2];
#pragma unroll
        for (int t2 = 0; t2 < 13; t2++) {
            int ybase = nbase + t2 * 8;
            int yc = ybase + fc * 2;
            bool cross = (xIsP != (ybase < Nn));
            float cy0 = c_sh[yc], cy1 = c_sh[yc + 1];
            float by0 = cross ? fmaf(cy0, BIGL, -BIGL) : -BIGL;
            float by1 = cross ? fmaf(cy1, BIGL, -BIGL) : -BIGL;
            acc[t2][0] += by0;
            acc[t2][1] += by1;
            acc[t2][2] += by0;
            acc[t2][3] += by1;
        }

        float m1 = -3.0e38f, m2 = -3.0e38f;
#pragma unroll
        for (int t2 = 0; t2 < 13; t2++) {
            m1 = fmaxf(m1, fmaxf(acc[t2][0], acc[t2][1]));
            m2 = fmaxf(m2, fmaxf(acc[t2][2], acc[t2][3]));
        }
#pragma unroll
        for (int o = 1; o <= 2; o <<= 1) {
            m1 = fmaxf(m1, __shfl_xor_sync(0xffffffffu, m1, o));
            m2 = fmaxf(m2, __shfl_xor_sync(0xffffffffu, m2, o));
        }
        float s1 = 0.f, s2 = 0.f;
#pragma unroll
        for (int t2 = 0; t2 < 13; t2++) {
            acc[t2][0] = ex2f(acc[t2][0] - m1);
            acc[t2][1] = ex2f(acc[t2][1] - m1);
            acc[t2][2] = ex2f(acc[t2][2] - m2);
            acc[t2][3] = ex2f(acc[t2][3] - m2);
            s1 += acc[t2][0] + acc[t2][1];
            s2 += acc[t2][2] + acc[t2][3];
        }
#pragma unroll
        for (int o = 1; o <= 2; o <<= 1) {
            s1 += __shfl_xor_sync(0xffffffffu, s1, o);
            s2 += __shfl_xor_sync(0xffffffffu, s2, o);
        }
        if (fc == 0) {
            redg[lx1 * 8 + nq * 2]     = m1;
            redg[lx1 * 8 + nq * 2 + 1] = s1;
            redg[lx2 * 8 + nq * 2]     = m2;
            redg[lx2 * 8 + nq * 2 + 1] = s2;
        }
        asm volatile("bar.sync %0, %1;" :: "r"(bar_id), "r"(256) : "memory");
        float f1, f2;
        {
            float M1 = -3.0e38f, M2 = -3.0e38f;
#pragma unroll
            for (int q = 0; q < 4; q++) {
                M1 = fmaxf(M1, redg[lx1 * 8 + q * 2]);
                M2 = fmaxf(M2, redg[lx2 * 8 + q * 2]);
            }
            float S1 = 0.f, S2 = 0.f;
#pragma unroll
            for (int q = 0; q < 4; q++) {
                S1 += redg[lx1 * 8 + q * 2 + 1] * ex2f(redg[lx1 * 8 + q * 2] - M1);
                S2 += redg[lx2 * 8 + q * 2 + 1] * ex2f(redg[lx2 * 8 + q * 2] - M2);
            }
            f1 = cx1 * ex2f(m1 - M1) / S1;
            f2 = cx2 * ex2f(m2 - M2) / S2;
        }

        {
            float o[4][4];
#pragma unroll
            for (int eg = 0; eg < 4; eg++)
#pragma unroll
                for (int c = 0; c < 4; c++) o[eg][c] = 0.f;

#pragma unroll
            for (int g = 0; g < 3; g++) {
                uint32_t Ah0[4], Al0[4], Ah1[4], Al1[4];
                {
                    int ta = 4 * g, tb = 4 * g + 1;
                    packhl2(acc[ta][0] * f1, acc[ta][1] * f1, Ah0[0], Al0[0]);
                    packhl2(acc[ta][2] * f2, acc[ta][3] * f2, Ah0[1], Al0[1]);
                    packhl2(acc[tb][0] * f1, acc[tb][1] * f1, Ah0[2], Al0[2]);
                    packhl2(acc[tb][2] * f2, acc[tb][3] * f2, Ah0[3], Al0[3]);
                    int tc = 4 * g + 2, td = 4 * g + 3;
                    packhl2(acc[tc][0] * f1, acc[tc][1] * f1, Ah1[0], Al1[0]);
                    packhl2(acc[tc][2] * f2, acc[tc][3] * f2, Ah1[1], Al1[1]);
                    packhl2(acc[td][0] * f1, acc[td][1] * f1, Ah1[2], Al1[2]);
                    packhl2(acc[td][2] * f2, acc[td][3] * f2, Ah1[3], Al1[3]);
                }
#pragma unroll
                for (int eg = 0; eg < 4; eg++) {
                    uint32_t bh4[4], bl4[4];
                    uint32_t offB = (uint32_t)((nbase + g * 32 + lane) * 40
                                               + eg * 8) * 2;
                    ldsm4t(bh4[0], bh4[1], bh4[2], bh4[3], vh_b + offB);
                    ldsm4t(bl4[0], bl4[1], bl4[2], bl4[3], vl_b + offB);
                    mma16816(o[eg], Ah0, &bh4[0]);
                    mma16816(o[eg], Ah0, &bl4[0]);
                    mma16816(o[eg], Al0, &bh4[0]);
                    mma16816(o[eg], Ah1, &bh4[2]);
                    mma16816(o[eg], Ah1, &bl4[2]);
                    mma16816(o[eg], Al1, &bh4[2]);
                }
            }
            {
                uint32_t Ath[2], Atl[2];
                packhl2(acc[12][0] * f1, acc[12][1] * f1, Ath[0], Atl[0]);
                packhl2(acc[12][2] * f2, acc[12][3] * f2, Ath[1], Atl[1]);
                uint32_t bh4[4], bl4[4];
                uint32_t offT = (uint32_t)((nbase + 96 + (lane & 7)) * 40
                                           + (lane >> 3) * 8) * 2;
                ldsm4t(bh4[0], bh4[1], bh4[2], bh4[3], vh_b + offT);
                ldsm4t(bl4[0], bl4[1], bl4[2], bl4[3], vl_b + offT);
#pragma unroll
                for (int eg = 0; eg < 4; eg++) {
                    mma1688(o[eg], Ath, bh4[eg]);
                    mma1688(o[eg], Ath, bl4[eg]);
                    mma1688(o[eg], Atl, bh4[eg]);
                }
            }
            float* op = opg + nq * 1024;
#pragma unroll
            for (int eg = 0; eg < 4; eg++) {
                int e = eg * 8 + fc * 2;
                *(float2*)&op[lx1 * 32 + e] = make_float2(o[eg][0], o[eg][1]);
                *(float2*)&op[lx2 * 32 + e] = make_float2(o[eg][2], o[eg][3]);
            }
        }
        asm volatile("bar.sync %0, %1;" :: "r"(bar_id), "r"(256) : "memory");

#pragma unroll
        for (int it = 0; it < 2; it++) {
            int idx = gtid + it * 256;
            int row = idx >> 4;
            int e = (idx & 15) * 2;
            const float* op = opg + row * 32 + e;
            float sum0 = op[0] + op[1024] + op[2048] + op[3072];
            float sum1 = op[1] + op[1025] + op[2049] + op[3073];
            int xs_ = x0 + row;
            float2 gv = *(const float2*)&g_g[(baseBH + xs_) * Ee + e];
            float sg0 = 1.f / (1.f + __expf(-gv.x));
            float sg1 = 1.f / (1.f + __expf(-gv.y));
            float o0 = sum0 * sg0;
            float o1 = sum1 * sg1;
            uint32_t oh, ol;
            packhl2(o0, o1, oh, ol);
            size_t di = ((size_t)b * Ss + xs_) * Oo + h * Ee + e;
            *(uint32_t*)&g_aoh[di] = oh;
            *(uint32_t*)&g_aol[di] = ol;
        }
    }
}

// ==== Kernel 4: output projection (HMMA bf16x3) + LN2; 64 rows/block =======
#define OAHI_OFF 0                            // 64*40*2 = 5120
#define OALO_OFF 5120
#define OBHI_OFF 10240                        // 256*40*2 = 20480
#define OBLO_OFF 30720
#define OYS_OFF  51200                        // 64*264*4 = 67584
#define OMU_OFF  118784                       // 256
#define ORS_OFF  119040                       // 256
#define OLN_SMEM 119296

__global__ void __launch_bounds__(512, 1)
k_outln(const float* __restrict__ bias, const float* __restrict__ g2,
        const float* __restrict__ b2, float* __restrict__ out) {
    extern __shared__ char smo[];
    __nv_bfloat16* Ahi = (__nv_bfloat16*)(smo + OAHI_OFF);
    __nv_bfloat16* Alo = (__nv_bfloat16*)(smo + OALO_OFF);
    __nv_bfloat16* Bhi = (__nv_bfloat16*)(smo + OBHI_OFF);
    __nv_bfloat16* Blo = (__nv_bfloat16*)(smo + OBLO_OFF);
    float* ys  = (float*)(smo + OYS_OFF);
    float* mus = (float*)(smo + OMU_OFF);
    float* rss = (float*)(smo + ORS_OFF);

    uint32_t ahi_b = smem_u32(Ahi), alo_b = smem_u32(Alo);
    uint32_t bhi_b = smem_u32(Bhi), blo_b = smem_u32(Blo);

    int tid = threadIdx.x;
    int wid = tid >> 5, lane = tid & 31;
    int mh = wid & 3, nq = wid >> 2;          // 4 m-slices x 4 n-quarters
    int r0 = blockIdx.x * 64;

    int a_row = lane & 15;
    int a_kof = (lane >> 4) * 8;
    int b_row = ((lane >> 4) & 1) * 8 + (lane & 7);
    int b_kof = ((lane >> 3) & 1) * 8;
    int fr = lane >> 2, fc = lane & 3;

    float acc[8][4];
#pragma unroll
    for (int j = 0; j < 8; j++)
#pragma unroll
        for (int c = 0; c < 4; c++) acc[j][c] = 0.f;

    for (int k0 = 0; k0 < 256; k0 += 32) {
        // stage A 64x32 hi/lo
        {
            int i = tid & 255;
            int row = i >> 2, q = i & 3;
            size_t src = (size_t)(r0 + row) * 256 + k0 + q * 8;
            if (tid < 256)
                *(uint4*)&Ahi[row * 40 + q * 8] = *(const uint4*)&g_aoh[src];
            else
                *(uint4*)&Alo[row * 40 + q * 8] = *(const uint4*)&g_aol[src];
        }
        // stage B 256x32 hi/lo
#pragma unroll
        for (int it = 0; it < 4; it++) {
            int idx = tid + it * 512;     // 0..2047
            int buf = idx >> 10;
            int rem = idx & 1023;
            int n = rem >> 2, q = rem & 3;
            size_t src = (size_t)(4 * 256 + n) * 256 + k0 + q * 8;
            const __nv_bfloat16* s = buf ? g_wl : g_wh;
            __nv_bfloat16* d = buf ? Blo : Bhi;
            *(uint4*)&d[n * 40 + q * 8] = *(const uint4*)&s[src];
        }
        __syncthreads();

#pragma unroll
        for (int ks = 0; ks < 2; ks++) {
            int kk = ks * 16;
            uint32_t ah[4], al[4];
            {
                uint32_t off = (uint32_t)((mh * 16 + a_row) * 40 + kk + a_kof) * 2;
                ldsm4(ah[0], ah[1], ah[2], ah[3], ahi_b + off);
                ldsm4(al[0], al[1], al[2], al[3], alo_b + off);
            }
#pragma unroll
            for (int jp = 0; jp < 4; jp++) {
                uint32_t bh2[4], bl2[4];
                uint32_t off = (uint32_t)((nq * 64 + jp * 16 + b_row) * 40
                                          + kk + b_kof) * 2;
                ldsm4(bh2[0], bh2[1], bh2[2], bh2[3], bhi_b + off);
                ldsm4(bl2[0], bl2[1], bl2[2], bl2[3], blo_b + off);
                mma16816(acc[jp*2],   ah, &bh2[0]);
                mma16816(acc[jp*2],   ah, &bl2[0]);
                mma16816(acc[jp*2],   al, &bh2[0]);
                mma16816(acc[jp*2+1], ah, &bh2[2]);
                mma16816(acc[jp*2+1], ah, &bl2[2]);
                mma16816(acc[jp*2+1], al, &bh2[2]);
            }
        }
        __syncthreads();
    }

    int lx1 = mh * 16 + fr;
    int lx2 = lx1 + 8;
#pragma unroll
    for (int j = 0; j < 8; j++) {
        int n = nq * 64 + j * 8 + fc * 2;
        float b0 = bias[n], b1 = bias[n + 1];
        ys[lx1 * 264 + n]     = acc[j][0] + b0;
        ys[lx1 * 264 + n + 1] = acc[j][1] + b1;
        ys[lx2 * 264 + n]     = acc[j][2] + b0;
        ys[lx2 * 264 + n + 1] = acc[j][3] + b1;
    }
    __syncthreads();

#pragma unroll
    for (int rr = 0; rr < 4; rr++) {
        int xr = wid + rr * 16;
        const float* row = ys + xr * 264;
        float s = 0.f;
#pragma unroll
        for (int j = 0; j < 8; j++) s += row[lane + 32 * j];
        s = warpSum(s);
        float mu = s * (1.f / 256.f);
        float vs = 0.f;
#pragma unroll
        for (int j = 0; j < 8; j++) {
            float d = row[lane + 32 * j] - mu;
            vs += d * d;
        }
        vs = warpSum(vs);
        if (lane == 0) { mus[xr] = mu; rss[xr] = rsqrtf(vs * (1.f / 256.f) + 1e-6f); }
    }
    __syncthreads();

    int cc = tid & 255;
    int rh = tid >> 8;
    float gt = g2[cc], bt = b2[cc];
#pragma unroll 4
    for (int r = rh * 32; r < rh * 32 + 32; r++) {
        out[(size_t)(r0 + r) * 256 + cc] =
            (ys[r * 264 + cc] - mus[r]) * rss[r] * gt + bt;
    }
}

// ===========================================================================
extern "C" void kernel_launch(void* const* d_in, const int* in_sizes, int n_in,
                              void* d_out, int out_size) {
    const float* x   = (const float*)d_in[0];
    const float* pm  = (const float*)d_in[1];
    const float* mm  = (const float*)d_in[2];
    const float* qp  = (const float*)d_in[3];
    const float* kp  = (const float*)d_in[4];
    const float* vp  = (const float*)d_in[5];
    const float* gp  = (const float*)d_in[6];
    const float* ow  = (const float*)d_in[7];
    const float* ob  = (const float*)d_in[8];
    const float* l1g = (const float*)d_in[9];
    const float* l1b = (const float*)d_in[10];
    const float* l2g = (const float*)d_in[11];
    const float* l2b = (const float*)d_in[12];
    float* out = (float*)d_out;

    cudaFuncSetAttribute(k_qkvg, cudaFuncAttributeMaxDynamicSharedMemorySize,
                         QKVG_SMEM);
    cudaFuncSetAttribute(k_attn, cudaFuncAttributeMaxDynamicSharedMemorySize,
                         ATTN_SMEM);
    cudaFuncSetAttribute(k_outln, cudaFuncAttributeMaxDynamicSharedMemorySize,
                         OLN_SMEM);

    k_wconv<<<dim3(256, 5), 256>>>(qp, kp, vp, gp, ow);
    k_ln1  <<<BSs, 256>>>(x, l1g, l1b);
    k_qkvg <<<416, 512, QKVG_SMEM>>>();
    k_attn <<<Bb * Hh, 512, ATTN_SMEM>>>(pm, mm);
    k_outln<<<BSs / 64, 512, OLN_SMEM>>>(ob, l2g, l2b, out);
}

// round 13
// speedup vs baseline: 3.4159x; 1.0873x over previous
#include <cuda_runtime.h>
#include <cuda_bf16.h>
#include <cstdint>

#define Bb   128
#define Ss   416
#define Nn   32
#define Mm   384
#define Dd   256
#define Hh   8
#define Ee   32
#define Oo   256
#define BSs  (Bb*Ss)          // 53248
#define NBH  (Bb*Hh*Ss*Ee)    // 13,631,488

// -------- scratch (static device globals; no runtime allocation) ----------
__device__ __nv_bfloat16 g_wh[5*256*256], g_wl[5*256*256];  // [proj][n][k]; 4=out_w
__device__ __nv_bfloat16 g_qh[NBH], g_ql[NBH];
__device__ __nv_bfloat16 g_kh[NBH], g_kl[NBH];
__device__ __nv_bfloat16 g_vh[NBH], g_vl[NBH];
__device__ float         g_g [NBH];
__device__ __nv_bfloat16 g_aoh[BSs*Oo], g_aol[BSs*Oo];

__device__ __forceinline__ float warpSum(float v) {
#pragma unroll
    for (int o = 16; o; o >>= 1) v += __shfl_xor_sync(0xffffffffu, v, o);
    return v;
}

// -------- mma.sync / async helpers ------------------------------------------
__device__ __forceinline__ uint32_t smem_u32(const void* p) {
    uint32_t a;
    asm("{ .reg .u64 t; cvta.to.shared.u64 t, %1; cvt.u32.u64 %0, t; }"
        : "=r"(a) : "l"(p));
    return a;
}
__device__ __forceinline__ void ldsm4(uint32_t& r0, uint32_t& r1,
                                      uint32_t& r2, uint32_t& r3, uint32_t a) {
    asm volatile("ldmatrix.sync.aligned.m8n8.x4.shared.b16 {%0,%1,%2,%3}, [%4];"
                 : "=r"(r0), "=r"(r1), "=r"(r2), "=r"(r3) : "r"(a));
}
__device__ __forceinline__ void ldsm4t(uint32_t& r0, uint32_t& r1,
                                       uint32_t& r2, uint32_t& r3, uint32_t a) {
    asm volatile("ldmatrix.sync.aligned.m8n8.x4.trans.shared.b16 {%0,%1,%2,%3}, [%4];"
                 : "=r"(r0), "=r"(r1), "=r"(r2), "=r"(r3) : "r"(a));
}
__device__ __forceinline__ void ldsm2(uint32_t& r0, uint32_t& r1, uint32_t a) {
    asm volatile("ldmatrix.sync.aligned.m8n8.x2.shared.b16 {%0,%1}, [%2];"
                 : "=r"(r0), "=r"(r1) : "r"(a));
}
__device__ __forceinline__ void mma16816(float* d, const uint32_t* a,
                                         const uint32_t* b) {
    asm volatile(
        "mma.sync.aligned.m16n8k16.row.col.f32.bf16.bf16.f32 "
        "{%0,%1,%2,%3}, {%4,%5,%6,%7}, {%8,%9}, {%0,%1,%2,%3};"
        : "+f"(d[0]), "+f"(d[1]), "+f"(d[2]), "+f"(d[3])
        : "r"(a[0]), "r"(a[1]), "r"(a[2]), "r"(a[3]), "r"(b[0]), "r"(b[1]));
}
__device__ __forceinline__ void mma1688(float* d, const uint32_t* a, uint32_t b) {
    asm volatile(
        "mma.sync.aligned.m16n8k8.row.col.f32.bf16.bf16.f32 "
        "{%0,%1,%2,%3}, {%4,%5}, {%6}, {%0,%1,%2,%3};"
        : "+f"(d[0]), "+f"(d[1]), "+f"(d[2]), "+f"(d[3])
        : "r"(a[0]), "r"(a[1]), "r"(b));
}
__device__ __forceinline__ void hilo(float v, __nv_bfloat16& h, __nv_bfloat16& l) {
    h = __float2bfloat16(v);
    l = __float2bfloat16(v - __bfloat162float(h));
}
__device__ __forceinline__ void packhl2(float x, float y,
                                        uint32_t& ph, uint32_t& pl) {
    asm("cvt.rn.bf16x2.f32 %0, %1, %2;" : "=r"(ph) : "f"(y), "f"(x));
    float xh = __uint_as_float(ph << 16);
    float yh = __uint_as_float(ph & 0xFFFF0000u);
    float xl = x - xh;
    float yl = y - yh;
    asm("cvt.rn.bf16x2.f32 %0, %1, %2;" : "=r"(pl) : "f"(yl), "f"(xl));
}
__device__ __forceinline__ float ex2f(float x) {
    float r; asm("ex2.approx.f32 %0, %1;" : "=f"(r) : "f"(x)); return r;
}
__device__ __forceinline__ void cpasync16(uint32_t dst, const void* src) {
    asm volatile("cp.async.cg.shared.global [%0], [%1], 16;"
                 :: "r"(dst), "l"(src) : "memory");
}
#define CP_COMMIT() asm volatile("cp.async.commit_group;" ::: "memory")
#define CP_WAIT1()  asm volatile("cp.async.wait_group 1;" ::: "memory")
#define CP_WAIT0()  asm volatile("cp.async.wait_group 0;" ::: "memory")

// ========== Kernel 0: one-time weight conversion to hi/lo bf16 [n][k] ======
__global__ void k_wconv(const float* __restrict__ qp, const float* __restrict__ kp,
                        const float* __restrict__ vp, const float* __restrict__ gp,
                        const float* __restrict__ ow) {
    int n = blockIdx.x;
    int proj = blockIdx.y;
    int k = threadIdx.x;
    float v;
    if (proj < 4) {
        const float* Wp = (proj == 0) ? qp : (proj == 1) ? kp
                         : (proj == 2) ? vp : gp;
        v = Wp[(n >> 5) * 8192 + k * 32 + (n & 31)];
    } else {
        v = ow[k * 256 + n];
    }
    __nv_bfloat16 h, l;
    hilo(v, h, l);
    size_t idx = (size_t)(proj * 256 + n) * 256 + k;
    g_wh[idx] = h;
    g_wl[idx] = l;
}

// ==== Kernel 2: QKVG with fused LN1; A staged once; cp.async B pipeline ====
#define QSCALE 0.2550868099f
#define QK_AHI 0
#define QK_ALO (128*264*2)                 // 67584
#define QK_B   (2*128*264*2)               // 135168; stage stride 33792 (hi|lo)
#define QKVG_SMEM (QK_B + 2*33792)         // 202752

__global__ void __launch_bounds__(512, 1)
k_qkvg(const float* __restrict__ x, const float* __restrict__ gam,
       const float* __restrict__ bet) {
    extern __shared__ char smq[];
    __nv_bfloat16* Ahi = (__nv_bfloat16*)(smq + QK_AHI);
    __nv_bfloat16* Alo = (__nv_bfloat16*)(smq + QK_ALO);
    uint32_t ahi_b = smem_u32(Ahi), alo_b = smem_u32(Alo);
    uint32_t bbase = smem_u32(smq + QK_B);

    int tid = threadIdx.x;
    int wid = tid >> 5, lane = tid & 31;
    int wm = wid >> 1, wn = wid & 1;       // 8 m-slices x 2 n-halves (of 32)
    int m0 = blockIdx.x * 128;

    // ---- prefetch B tile 0 (overlaps LN staging below) ----
    {
        int nt = 0;
        int proj = nt >> 3, nin = (nt & 7) * 32;
#pragma unroll
        for (int it = 0; it < 4; it++) {
            int idx = tid + it * 512;        // 0..2047
            int buf = idx >> 10;
            int rem = idx & 1023;
            int n = rem >> 5, q = rem & 31;
            const __nv_bfloat16* src = buf ? g_wl : g_wh;
            cpasync16(bbase + buf * 16896 + (uint32_t)(n * 264 + q * 8) * 2,
                      &src[(size_t)(proj * 256 + nin + n) * 256 + q * 8]);
        }
        CP_COMMIT();
    }

    // ---- stage A with fused LayerNorm: warp w handles rows w*8..w*8+7 ----
    {
        float4 gm0 = *(const float4*)&gam[lane * 8];
        float4 gm1 = *(const float4*)&gam[lane * 8 + 4];
        float4 bt0 = *(const float4*)&bet[lane * 8];
        float4 bt1 = *(const float4*)&bet[lane * 8 + 4];
#pragma unroll
        for (int r = 0; r < 8; r++) {
            int row = wid * 8 + r;
            const float* xr = x + (size_t)(m0 + row) * 256 + lane * 8;
            float4 v0 = *(const float4*)xr;
            float4 v1 = *(const float4*)(xr + 4);
            float s = v0.x + v0.y + v0.z + v0.w + v1.x + v1.y + v1.z + v1.w;
            s = warpSum(s);
            float mu = s * (1.f / 256.f);
            float d[8] = {v0.x - mu, v0.y - mu, v0.z - mu, v0.w - mu,
                          v1.x - mu, v1.y - mu, v1.z - mu, v1.w - mu};
            float vs = 0.f;
#pragma unroll
            for (int i = 0; i < 8; i++) vs += d[i] * d[i];
            vs = warpSum(vs);
            float rs = rsqrtf(vs * (1.f / 256.f) + 1e-6f);
            float o[8];
            o[0] = d[0] * rs * gm0.x + bt0.x;
            o[1] = d[1] * rs * gm0.y + bt0.y;
            o[2] = d[2] * rs * gm0.z + bt0.z;
            o[3] = d[3] * rs * gm0.w + bt0.w;
            o[4] = d[4] * rs * gm1.x + bt1.x;
            o[5] = d[5] * rs * gm1.y + bt1.y;
            o[6] = d[6] * rs * gm1.z + bt1.z;
            o[7] = d[7] * rs * gm1.w + bt1.w;
            uint32_t ph[4], pl[4];
#pragma unroll
            for (int i = 0; i < 4; i++) packhl2(o[i*2], o[i*2+1], ph[i], pl[i]);
            *(uint4*)&Ahi[row * 264 + lane * 8] = *(uint4*)ph;
            *(uint4*)&Alo[row * 264 + lane * 8] = *(uint4*)pl;
        }
    }

    int a_row = lane & 15;
    int a_kof = (lane >> 4) * 8;
    int b_row = ((lane >> 4) & 1) * 8 + (lane & 7);
    int b_kof = ((lane >> 3) & 1) * 8;
    int fr = lane >> 2, fc = lane & 3;

    for (int nt = 0; nt < 32; nt++) {
        // prefetch next B tile
        if (nt < 31) {
            int nn = nt + 1;
            int proj = nn >> 3, nin = (nn & 7) * 32;
            uint32_t sb = bbase + ((nn & 1) ? 33792u : 0u);
#pragma unroll
            for (int it = 0; it < 4; it++) {
                int idx = tid + it * 512;
                int buf = idx >> 10;
                int rem = idx & 1023;
                int n = rem >> 5, q = rem & 31;
                const __nv_bfloat16* src = buf ? g_wl : g_wh;
                cpasync16(sb + buf * 16896 + (uint32_t)(n * 264 + q * 8) * 2,
                          &src[(size_t)(proj * 256 + nin + n) * 256 + q * 8]);
            }
            CP_COMMIT();
            CP_WAIT1();
        } else {
            CP_WAIT0();
        }
        __syncthreads();

        int proj = nt >> 3;
        int nin = (nt & 7) * 32;
        uint32_t bhi_b = bbase + ((nt & 1) ? 33792u : 0u);
        uint32_t blo_b = bhi_b + 16896u;

        float acc[2][4];
#pragma unroll
        for (int j = 0; j < 2; j++)
#pragma unroll
            for (int c = 0; c < 4; c++) acc[j][c] = 0.f;

#pragma unroll 2
        for (int k0 = 0; k0 < 256; k0 += 32) {
#pragma unroll
            for (int ks = 0; ks < 2; ks++) {
                int kk = k0 + ks * 16;
                uint32_t ah[4], al[4];
                {
                    uint32_t off = (uint32_t)((wm * 16 + a_row) * 264
                                              + kk + a_kof) * 2;
                    ldsm4(ah[0], ah[1], ah[2], ah[3], ahi_b + off);
                    ldsm4(al[0], al[1], al[2], al[3], alo_b + off);
                }
                uint32_t bh2[4], bl2[4];
                {
                    uint32_t off = (uint32_t)((wn * 16 + b_row) * 264
                                              + kk + b_kof) * 2;
                    ldsm4(bh2[0], bh2[1], bh2[2], bh2[3], bhi_b + off);
                    ldsm4(bl2[0], bl2[1], bl2[2], bl2[3], blo_b + off);
                }
                mma16816(acc[0], ah, &bh2[0]);
                mma16816(acc[0], ah, &bl2[0]);
                mma16816(acc[0], al, &bh2[0]);
                mma16816(acc[1], ah, &bh2[2]);
                mma16816(acc[1], ah, &bl2[2]);
                mma16816(acc[1], al, &bh2[2]);
            }
        }

        if (proj == 0) {
#pragma unroll
            for (int j = 0; j < 2; j++)
#pragma unroll
                for (int c = 0; c < 4; c++) acc[j][c] *= QSCALE;
        }

        // ---- epilogue ----
        int nglob = nin + wn * 16;
        int h = nglob >> 5;
        int ebase = nglob & 31;
        __nv_bfloat16* Oh = (proj == 0) ? g_qh : (proj == 1) ? g_kh : g_vh;
        __nv_bfloat16* Ol = (proj == 0) ? g_ql : (proj == 1) ? g_kl : g_vl;
        bool isG = (proj == 3);
        int m = m0 + wm * 16 + fr;
        int b1 = m / Ss, s1 = m - b1 * Ss;
        int m2 = m + 8;
        int b2 = m2 / Ss, s2 = m2 - b2 * Ss;
        size_t i1 = (((size_t)(b1 * Hh + h)) * Ss + s1) * Ee;
        size_t i2 = (((size_t)(b2 * Hh + h)) * Ss + s2) * Ee;
#pragma unroll
        for (int j = 0; j < 2; j++) {
            int e = ebase + j * 8 + fc * 2;
            if (isG) {
                *(float2*)&g_g[i1 + e] = make_float2(acc[j][0], acc[j][1]);
                *(float2*)&g_g[i2 + e] = make_float2(acc[j][2], acc[j][3]);
            } else {
                uint32_t h1, l1, h2, l2;
                packhl2(acc[j][0], acc[j][1], h1, l1);
                packhl2(acc[j][2], acc[j][3], h2, l2);
                *(uint32_t*)&Oh[i1 + e] = h1;
                *(uint32_t*)&Ol[i1 + e] = l1;
                *(uint32_t*)&Oh[i2 + e] = h2;
                *(uint32_t*)&Ol[i2 + e] = l2;
            }
        }
        __syncthreads();
    }
}

// ==== Kernel 3: attention; 2 groups, Q via LDG, log2-domain softmax ========
#define KHI_OFF   0
#define KLO_OFF   33280
#define VH_OFF    66560
#define VL_OFF    99840
#define CSH_OFF   133120
#define RED_OFF   134784
#define OP_OFF    136832
#define ATTN_SMEM 169600

__global__ void __launch_bounds__(512, 1)
k_attn(const float* __restrict__ pmask, const float* __restrict__ mmask) {
    extern __shared__ char smc[];
    __nv_bfloat16* khi = (__nv_bfloat16*)(smc + KHI_OFF);
    __nv_bfloat16* klo = (__nv_bfloat16*)(smc + KLO_OFF);
    __nv_bfloat16* v_h = (__nv_bfloat16*)(smc + VH_OFF);
    __nv_bfloat16* v_l = (__nv_bfloat16*)(smc + VL_OFF);
    float*         c_sh = (float*)(smc + CSH_OFF);
    float*         red  = (float*)(smc + RED_OFF);
    float*         opart = (float*)(smc + OP_OFF);

    uint32_t khi_b = smem_u32(khi), klo_b = smem_u32(klo);
    uint32_t vh_b = smem_u32(v_h), vl_b = smem_u32(v_l);

    int tid = threadIdx.x;
    int lane = tid & 31;
    int bh = blockIdx.x;
    int h = bh & 7, b = bh >> 3;
    size_t baseBH = (size_t)(b * Hh + h) * Ss;

    for (int i = tid; i < Ss * 4; i += 512) {
        int y = i >> 2, q = i & 3;
        size_t src = (baseBH + y) * Ee + q * 8;
        *(uint4*)&khi[y * 40 + q * 8] = *(const uint4*)&g_kh[src];
        *(uint4*)&klo[y * 40 + q * 8] = *(const uint4*)&g_kl[src];
        *(uint4*)&v_h[y * 40 + q * 8] = *(const uint4*)&g_vh[src];
        *(uint4*)&v_l[y * 40 + q * 8] = *(const uint4*)&g_vl[src];
    }
    for (int i = tid; i < Ss; i += 512) {
        float val = (i < Nn) ? pmask[b * Nn + i] : mmask[b * Mm + (i - Nn)];
        c_sh[i] = (val == -2.0f) ? 0.f : 1.f;
    }
    __syncthreads();

    const float BIGL = 1.0e9f;
    int grp = tid >> 8;
    int wg = (tid >> 5) & 7;
    int mh = (wg >> 2) & 1;
    int nq = wg & 3;
    int nbase = nq * 104;
    int gtid = tid & 255;

    int b_row = ((lane >> 4) & 1) * 8 + (lane & 7);
    int b_kof = ((lane >> 3) & 1) * 8;
    int fr = lane >> 2, fc = lane & 3;
    int lx1 = mh * 16 + fr;
    int lx2 = lx1 + 8;

    float* redg = red + grp * 256;
    float* opg  = opart + grp * 4096;
    int bar_id = grp + 1;

    for (int t = grp; t < 13; t += 2) {
        int x0 = t * 32;

        uint32_t qah[2][4], qal[2][4];
        {
            const __nv_bfloat16* ph = g_qh + (baseBH + x0 + lx1) * 32;
            const __nv_bfloat16* pl = g_ql + (baseBH + x0 + lx1) * 32;
#pragma unroll
            for (int ks = 0; ks < 2; ks++) {
                int kk = ks * 16 + fc * 2;
                qah[ks][0] = *(const uint32_t*)&ph[kk];
                qah[ks][1] = *(const uint32_t*)&ph[256 + kk];
                qah[ks][2] = *(const uint32_t*)&ph[kk + 8];
                qah[ks][3] = *(const uint32_t*)&ph[256 + kk + 8];
                qal[ks][0] = *(const uint32_t*)&pl[kk];
                qal[ks][1] = *(const uint32_t*)&pl[256 + kk];
                qal[ks][2] = *(const uint32_t*)&pl[kk + 8];
                qal[ks][3] = *(const uint32_t*)&pl[256 + kk + 8];
            }
        }

        float acc[13][4];
#pragma unroll
        for (int t2 = 0; t2 < 13; t2++)
#pragma unroll
            for (int c = 0; c < 4; c++) acc[t2][c] = 0.f;

#pragma unroll
        for (int ks = 0; ks < 2; ks++) {
            int kk = ks * 16;
#pragma unroll
            for (int jp = 0; jp < 6; jp++) {
                uint32_t bh2[4], bl2[4];
                uint32_t off = (uint32_t)((nbase + jp * 16 + b_row) * 40
                                          + kk + b_kof) * 2;
                ldsm4(bh2[0], bh2[1], bh2[2], bh2[3], khi_b + off);
                ldsm4(bl2[0], bl2[1], bl2[2], bl2[3], klo_b + off);
                mma16816(acc[jp*2],   qah[ks], &bh2[0]);
                mma16816(acc[jp*2],   qah[ks], &bl2[0]);
                mma16816(acc[jp*2],   qal[ks], &bh2[0]);
                mma16816(acc[jp*2+1], qah[ks], &bh2[2]);
                mma16816(acc[jp*2+1], qah[ks], &bl2[2]);
                mma16816(acc[jp*2+1], qal[ks], &bh2[2]);
            }
            {
                uint32_t bh1[2], bl1[2];
                uint32_t off = (uint32_t)((nbase + 96 + (lane & 7)) * 40 + kk
                                          + 8 * ((lane >> 3) & 1)) * 2;
                ldsm2(bh1[0], bh1[1], khi_b + off);
                ldsm2(bl1[0], bl1[1], klo_b + off);
                mma16816(acc[12], qah[ks], bh1);
                mma16816(acc[12], qah[ks], bl1);
                mma16816(acc[12], qal[ks], bh1);
            }
        }

        bool xIsP = (t == 0);
        float cx1 = c_sh[x0 + lx1];
        float cx2 = c_sh[x0 + lx2];
#pragma unroll
        for (int t2 = 0; t2 < 13; t2++) {
            int ybase = nbase + t2 * 8;
            int yc = ybase + fc * 2;
            bool cross = (xIsP != (ybase < Nn));
            float cy0 = c_sh[yc], cy1 = c_sh[yc + 1];
            float by0 = cross ? fmaf(cy0, BIGL, -BIGL) : -BIGL;
            float by1 = cross ? fmaf(cy1, BIGL, -BIGL) : -BIGL;
            acc[t2][0] += by0;
            acc[t2][1] += by1;
            acc[t2][2] += by0;
            acc[t2][3] += by1;
        }

        float m1 = -3.0e38f, m2 = -3.0e38f;
#pragma unroll
        for (int t2 = 0; t2 < 13; t2++) {
            m1 = fmaxf(m1, fmaxf(acc[t2][0], acc[t2][1]));
            m2 = fmaxf(m2, fmaxf(acc[t2][2], acc[t2][3]));
        }
#pragma unroll
        for (int o = 1; o <= 2; o <<= 1) {
            m1 = fmaxf(m1, __shfl_xor_sync(0xffffffffu, m1, o));
            m2 = fmaxf(m2, __shfl_xor_sync(0xffffffffu, m2, o));
        }
        float s1 = 0.f, s2 = 0.f;
#pragma unroll
        for (int t2 = 0; t2 < 13; t2++) {
            acc[t2][0] = ex2f(acc[t2][0] - m1);
            acc[t2][1] = ex2f(acc[t2][1] - m1);
            acc[t2][2] = ex2f(acc[t2][2] - m2);
            acc[t2][3] = ex2f(acc[t2][3] - m2);
            s1 += acc[t2][0] + acc[t2][1];
            s2 += acc[t2][2] + acc[t2][3];
        }
#pragma unroll
        for (int o = 1; o <= 2; o <<= 1) {
            s1 += __shfl_xor_sync(0xffffffffu, s1, o);
            s2 += __shfl_xor_sync(0xffffffffu, s2, o);
        }
        if (fc == 0) {
            redg[lx1 * 8 + nq * 2]     = m1;
            redg[lx1 * 8 + nq * 2 + 1] = s1;
            redg[lx2 * 8 + nq * 2]     = m2;
            redg[lx2 * 8 + nq * 2 + 1] = s2;
        }
        asm volatile("bar.sync %0, %1;" :: "r"(bar_id), "r"(256) : "memory");
        float f1, f2;
        {
            float M1 = -3.0e38f, M2 = -3.0e38f;
#pragma unroll
            for (int q = 0; q < 4; q++) {
                M1 = fmaxf(M1, redg[lx1 * 8 + q * 2]);
                M2 = fmaxf(M2, redg[lx2 * 8 + q * 2]);
            }
            float S1 = 0.f, S2 = 0.f;
#pragma unroll
            for (int q = 0; q < 4; q++) {
                S1 += redg[lx1 * 8 + q * 2 + 1] * ex2f(redg[lx1 * 8 + q * 2] - M1);
                S2 += redg[lx2 * 8 + q * 2 + 1] * ex2f(redg[lx2 * 8 + q * 2] - M2);
            }
            f1 = cx1 * ex2f(m1 - M1) / S1;
            f2 = cx2 * ex2f(m2 - M2) / S2;
        }

        {
            float o[4][4];
#pragma unroll
            for (int eg = 0; eg < 4; eg++)
#pragma unroll
                for (int c = 0; c < 4; c++) o[eg][c] = 0.f;

#pragma unroll
            for (int g = 0; g < 3; g++) {
                uint32_t Ah0[4], Al0[4], Ah1[4], Al1[4];
                {
                    int ta = 4 * g, tb = 4 * g + 1;
                    packhl2(acc[ta][0] * f1, acc[ta][1] * f1, Ah0[0], Al0[0]);
                    packhl2(acc[ta][2] * f2, acc[ta][3] * f2, Ah0[1], Al0[1]);
                    packhl2(acc[tb][0] * f1, acc[tb][1] * f1, Ah0[2], Al0[2]);
                    packhl2(acc[tb][2] * f2, acc[tb][3] * f2, Ah0[3], Al0[3]);
                    int tc = 4 * g + 2, td = 4 * g + 3;
                    packhl2(acc[tc][0] * f1, acc[tc][1] * f1, Ah1[0], Al1[0]);
                    packhl2(acc[tc][2] * f2, acc[tc][3] * f2, Ah1[1], Al1[1]);
                    packhl2(acc[td][0] * f1, acc[td][1] * f1, Ah1[2], Al1[2]);
                    packhl2(acc[td][2] * f2, acc[td][3] * f2, Ah1[3], Al1[3]);
                }
#pragma unroll
                for (int eg = 0; eg < 4; eg++) {
                    uint32_t bh4[4], bl4[4];
                    uint32_t offB = (uint32_t)((nbase + g * 32 + lane) * 40
                                               + eg * 8) * 2;
                    ldsm4t(bh4[0], bh4[1], bh4[2], bh4[3], vh_b + offB);
                    ldsm4t(bl4[0], bl4[1], bl4[2], bl4[3], vl_b + offB);
                    mma16816(o[eg], Ah0, &bh4[0]);
                    mma16816(o[eg], Ah0, &bl4[0]);
                    mma16816(o[eg], Al0, &bh4[0]);
                    mma16816(o[eg], Ah1, &bh4[2]);
                    mma16816(o[eg], Ah1, &bl4[2]);
                    mma16816(o[eg], Al1, &bh4[2]);
                }
            }
            {
                uint32_t Ath[2], Atl[2];
                packhl2(acc[12][0] * f1, acc[12][1] * f1, Ath[0], Atl[0]);
                packhl2(acc[12][2] * f2, acc[12][3] * f2, Ath[1], Atl[1]);
                uint32_t bh4[4], bl4[4];
                uint32_t offT = (uint32_t)((nbase + 96 + (lane & 7)) * 40
                                           + (lane >> 3) * 8) * 2;
                ldsm4t(bh4[0], bh4[1], bh4[2], bh4[3], vh_b + offT);
                ldsm4t(bl4[0], bl4[1], bl4[2], bl4[3], vl_b + offT);
#pragma unroll
                for (int eg = 0; eg < 4; eg++) {
                    mma1688(o[eg], Ath, bh4[eg]);
                    mma1688(o[eg], Ath, bl4[eg]);
                    mma1688(o[eg], Atl, bh4[eg]);
                }
            }
            float* op = opg + nq * 1024;
#pragma unroll
            for (int eg = 0; eg < 4; eg++) {
                int e = eg * 8 + fc * 2;
                *(float2*)&op[lx1 * 32 + e] = make_float2(o[eg][0], o[eg][1]);
                *(float2*)&op[lx2 * 32 + e] = make_float2(o[eg][2], o[eg][3]);
            }
        }
        asm volatile("bar.sync %0, %1;" :: "r"(bar_id), "r"(256) : "memory");

#pragma unroll
        for (int it = 0; it < 2; it++) {
            int idx = gtid + it * 256;
            int row = idx >> 4;
            int e = (idx & 15) * 2;
            const float* op = opg + row * 32 + e;
            float sum0 = op[0] + op[1024] + op[2048] + op[3072];
            float sum1 = op[1] + op[1025] + op[2049] + op[3073];
            int xs_ = x0 + row;
            float2 gv = *(const float2*)&g_g[(baseBH + xs_) * Ee + e];
            float sg0 = 1.f / (1.f + __expf(-gv.x));
            float sg1 = 1.f / (1.f + __expf(-gv.y));
            float o0 = sum0 * sg0;
            float o1 = sum1 * sg1;
            uint32_t oh, ol;
            packhl2(o0, o1, oh, ol);
            size_t di = ((size_t)b * Ss + xs_) * Oo + h * Ee + e;
            *(uint32_t*)&g_aoh[di] = oh;
            *(uint32_t*)&g_aol[di] = ol;
        }
    }
}

// ==== Kernel 4: output proj + LN2; cp.async double-buffered A and B ========
#define OA_OFF  0                             // 2 stages x 10240 (hi|lo 5120)
#define OB_OFF  20480                         // 2 stages x 40960 (hi|lo 20480)
#define OYS_OFF 102400                        // 64*264*4 = 67584
#define OMU_OFF 169984
#define ORS_OFF 170240
#define OLN_SMEM 170496

__global__ void __launch_bounds__(512, 1)
k_outln(const float* __restrict__ bias, const float* __restrict__ g2,
        const float* __restrict__ b2, float* __restrict__ out) {
    extern __shared__ char smo[];
    float* ys  = (float*)(smo + OYS_OFF);
    float* mus = (float*)(smo + OMU_OFF);
    float* rss = (float*)(smo + ORS_OFF);
    uint32_t oa_b = smem_u32(smo + OA_OFF);
    uint32_t ob_b = smem_u32(smo + OB_OFF);

    int tid = threadIdx.x;
    int wid = tid >> 5, lane = tid & 31;
    int mh = wid & 3, nq = wid >> 2;
    int r0 = blockIdx.x * 64;

    int a_row = lane & 15;
    int a_kof = (lane >> 4) * 8;
    int b_row = ((lane >> 4) & 1) * 8 + (lane & 7);
    int b_kof = ((lane >> 3) & 1) * 8;
    int fr = lane >> 2, fc = lane & 3;

    // prefetch stage 0 (k0 = 0)
    auto prefetch = [&](int ki, int st) {
        int k0 = ki * 32;
        uint32_t sa = oa_b + st * 10240;
        {
            int idx = tid;                    // 0..511
            int buf = idx >> 8;
            int rem = idx & 255;
            int row = rem >> 2, q = rem & 3;
            const __nv_bfloat16* src = buf ? g_aol : g_aoh;
            cpasync16(sa + buf * 5120 + (uint32_t)(row * 40 + q * 8) * 2,
                      &src[(size_t)(r0 + row) * 256 + k0 + q * 8]);
        }
        uint32_t sb = ob_b + st * 40960;
#pragma unroll
        for (int it = 0; it < 4; it++) {
            int idx = tid + it * 512;         // 0..2047
            int buf = idx >> 10;
            int rem = idx & 1023;
            int n = rem >> 2, q = rem & 3;
            const __nv_bfloat16* src = buf ? g_wl : g_wh;
            cpasync16(sb + buf * 20480 + (uint32_t)(n * 40 + q * 8) * 2,
                      &src[(size_t)(4 * 256 + n) * 256 + k0 + q * 8]);
        }
        CP_COMMIT();
    };
    prefetch(0, 0);

    float acc[8][4];
#pragma unroll
    for (int j = 0; j < 8; j++)
#pragma unroll
        for (int c = 0; c < 4; c++) acc[j][c] = 0.f;

    for (int ki = 0; ki < 8; ki++) {
        if (ki < 7) { prefetch(ki + 1, (ki + 1) & 1); CP_WAIT1(); }
        else        { CP_WAIT0(); }
        __syncthreads();

        uint32_t ahi_b = oa_b + (ki & 1) * 10240;
        uint32_t alo_b = ahi_b + 5120;
        uint32_t bhi_b = ob_b + (ki & 1) * 40960;
        uint32_t blo_b = bhi_b + 20480;

#pragma unroll
        for (int ks = 0; ks < 2; ks++) {
            int kk = ks * 16;
            uint32_t ah[4], al[4];
            {
                uint32_t off = (uint32_t)((mh * 16 + a_row) * 40 + kk + a_kof) * 2;
                ldsm4(ah[0], ah[1], ah[2], ah[3], ahi_b + off);
                ldsm4(al[0], al[1], al[2], al[3], alo_b + off);
            }
#pragma unroll
            for (int jp = 0; jp < 4; jp++) {
                uint32_t bh2[4], bl2[4];
                uint32_t off = (uint32_t)((nq * 64 + jp * 16 + b_row) * 40
                                          + kk + b_kof) * 2;
                ldsm4(bh2[0], bh2[1], bh2[2], bh2[3], bhi_b + off);
                ldsm4(bl2[0], bl2[1], bl2[2], bl2[3], blo_b + off);
                mma16816(acc[jp*2],   ah, &bh2[0]);
                mma16816(acc[jp*2],   ah, &bl2[0]);
                mma16816(acc[jp*2],   al, &bh2[0]);
                mma16816(acc[jp*2+1], ah, &bh2[2]);
                mma16816(acc[jp*2+1], ah, &bl2[2]);
                mma16816(acc[jp*2+1], al, &bh2[2]);
            }
        }
        __syncthreads();
    }

    int lx1 = mh * 16 + fr;
    int lx2 = lx1 + 8;
#pragma unroll
    for (int j = 0; j < 8; j++) {
        int n = nq * 64 + j * 8 + fc * 2;
        float b0 = bias[n], b1 = bias[n + 1];
        ys[lx1 * 264 + n]     = acc[j][0] + b0;
        ys[lx1 * 264 + n + 1] = acc[j][1] + b1;
        ys[lx2 * 264 + n]     = acc[j][2] + b0;
        ys[lx2 * 264 + n + 1] = acc[j][3] + b1;
    }
    __syncthreads();

#pragma unroll
    for (int rr = 0; rr < 4; rr++) {
        int xr = wid + rr * 16;
        const float* row = ys + xr * 264;
        float s = 0.f;
#pragma unroll
        for (int j = 0; j < 8; j++) s += row[lane + 32 * j];
        s = warpSum(s);
        float mu = s * (1.f / 256.f);
        float vs = 0.f;
#pragma unroll
        for (int j = 0; j < 8; j++) {
            float d = row[lane + 32 * j] - mu;
            vs += d * d;
        }
        vs = warpSum(vs);
        if (lane == 0) { mus[xr] = mu; rss[xr] = rsqrtf(vs * (1.f / 256.f) + 1e-6f); }
    }
    __syncthreads();

    int cc = tid & 255;
    int rh = tid >> 8;
    float gt = g2[cc], bt = b2[cc];
#pragma unroll 4
    for (int r = rh * 32; r < rh * 32 + 32; r++) {
        out[(size_t)(r0 + r) * 256 + cc] =
            (ys[r * 264 + cc] - mus[r]) * rss[r] * gt + bt;
    }
}

// ===========================================================================
extern "C" void kernel_launch(void* const* d_in, const int* in_sizes, int n_in,
                              void* d_out, int out_size) {
    const float* x   = (const float*)d_in[0];
    const float* pm  = (const float*)d_in[1];
    const float* mm  = (const float*)d_in[2];
    const float* qp  = (const float*)d_in[3];
    const float* kp  = (const float*)d_in[4];
    const float* vp  = (const float*)d_in[5];
    const float* gp  = (const float*)d_in[6];
    const float* ow  = (const float*)d_in[7];
    const float* ob  = (const float*)d_in[8];
    const float* l1g = (const float*)d_in[9];
    const float* l1b = (const float*)d_in[10];
    const float* l2g = (const float*)d_in[11];
    const float* l2b = (const float*)d_in[12];
    float* out = (float*)d_out;

    cudaFuncSetAttribute(k_qkvg, cudaFuncAttributeMaxDynamicSharedMemorySize,
                         QKVG_SMEM);
    cudaFuncSetAttribute(k_attn, cudaFuncAttributeMaxDynamicSharedMemorySize,
                         ATTN_SMEM);
    cudaFuncSetAttribute(k_outln, cudaFuncAttributeMaxDynamicSharedMemorySize,
                         OLN_SMEM);

    k_wconv<<<dim3(256, 5), 256>>>(qp, kp, vp, gp, ow);
    k_qkvg <<<416, 512, QKVG_SMEM>>>(x, l1g, l1b);
    k_attn <<<Bb * Hh, 512, ATTN_SMEM>>>(pm, mm);
    k_outln<<<BSs / 64, 512, OLN_SMEM>>>(ob, l2g, l2b, out);
}

// round 14
// speedup vs baseline: 3.6017x; 1.0544x over previous
#include <cuda_runtime.h>
#include <cuda_bf16.h>
#include <cstdint>

#define Bb   128
#define Ss   416
#define Nn   32
#define Mm   384
#define Dd   256
#define Hh   8
#define Ee   32
#define Oo   256
#define BSs  (Bb*Ss)          // 53248
#define NBH  (Bb*Hh*Ss*Ee)    // 13,631,488

// -------- scratch (static device globals; no runtime allocation) ----------
// fragment-packed weights: [proj(5)][n8t(32)][kc(16)][lane(32)] x 16B
__device__ uint4 g_wf[5*32*16*32];
__device__ __nv_bfloat16 g_qh[NBH], g_ql[NBH];
__device__ __nv_bfloat16 g_kh[NBH], g_kl[NBH];
__device__ __nv_bfloat16 g_vh[NBH], g_vl[NBH];
__device__ float         g_g [NBH];
// fragment-packed attention output: [m8t(6656)][kc(16)][lane(32)] x 16B
__device__ uint4 g_aof[6656*16*32];

__device__ __forceinline__ float warpSum(float v) {
#pragma unroll
    for (int o = 16; o; o >>= 1) v += __shfl_xor_sync(0xffffffffu, v, o);
    return v;
}

// -------- mma.sync helpers --------------------------------------------------
__device__ __forceinline__ uint32_t smem_u32(const void* p) {
    uint32_t a;
    asm("{ .reg .u64 t; cvta.to.shared.u64 t, %1; cvt.u32.u64 %0, t; }"
        : "=r"(a) : "l"(p));
    return a;
}
__device__ __forceinline__ void ldsm4(uint32_t& r0, uint32_t& r1,
                                      uint32_t& r2, uint32_t& r3, uint32_t a) {
    asm volatile("ldmatrix.sync.aligned.m8n8.x4.shared.b16 {%0,%1,%2,%3}, [%4];"
                 : "=r"(r0), "=r"(r1), "=r"(r2), "=r"(r3) : "r"(a));
}
__device__ __forceinline__ void ldsm4t(uint32_t& r0, uint32_t& r1,
                                       uint32_t& r2, uint32_t& r3, uint32_t a) {
    asm volatile("ldmatrix.sync.aligned.m8n8.x4.trans.shared.b16 {%0,%1,%2,%3}, [%4];"
                 : "=r"(r0), "=r"(r1), "=r"(r2), "=r"(r3) : "r"(a));
}
__device__ __forceinline__ void ldsm2(uint32_t& r0, uint32_t& r1, uint32_t a) {
    asm volatile("ldmatrix.sync.aligned.m8n8.x2.shared.b16 {%0,%1}, [%2];"
                 : "=r"(r0), "=r"(r1) : "r"(a));
}
__device__ __forceinline__ void mma16816(float* d, const uint32_t* a,
                                         const uint32_t* b) {
    asm volatile(
        "mma.sync.aligned.m16n8k16.row.col.f32.bf16.bf16.f32 "
        "{%0,%1,%2,%3}, {%4,%5,%6,%7}, {%8,%9}, {%0,%1,%2,%3};"
        : "+f"(d[0]), "+f"(d[1]), "+f"(d[2]), "+f"(d[3])
        : "r"(a[0]), "r"(a[1]), "r"(a[2]), "r"(a[3]), "r"(b[0]), "r"(b[1]));
}
__device__ __forceinline__ void mma1688(float* d, const uint32_t* a, uint32_t b) {
    asm volatile(
        "mma.sync.aligned.m16n8k8.row.col.f32.bf16.bf16.f32 "
        "{%0,%1,%2,%3}, {%4,%5}, {%6}, {%0,%1,%2,%3};"
        : "+f"(d[0]), "+f"(d[1]), "+f"(d[2]), "+f"(d[3])
        : "r"(a[0]), "r"(a[1]), "r"(b));
}
__device__ __forceinline__ void packhl2(float x, float y,
                                        uint32_t& ph, uint32_t& pl) {
    asm("cvt.rn.bf16x2.f32 %0, %1, %2;" : "=r"(ph) : "f"(y), "f"(x));
    float xh = __uint_as_float(ph << 16);
    float yh = __uint_as_float(ph & 0xFFFF0000u);
    float xl = x - xh;
    float yl = y - yh;
    asm("cvt.rn.bf16x2.f32 %0, %1, %2;" : "=r"(pl) : "f"(yl), "f"(xl));
}
__device__ __forceinline__ float ex2f(float x) {
    float r; asm("ex2.approx.f32 %0, %1;" : "=f"(r) : "f"(x)); return r;
}

// ========== Kernel 0: weights -> fragment-packed hi/lo (g_wf) ==============
__global__ void k_wconv(const float* __restrict__ qp, const float* __restrict__ kp,
                        const float* __restrict__ vp, const float* __restrict__ gp,
                        const float* __restrict__ ow) {
    int n8t = blockIdx.x;      // 0..31
    int proj = blockIdx.y;     // 0..4
    int tid = threadIdx.x;     // 512
    int kc = tid >> 5, lane = tid & 31;
    int n = n8t * 8 + (lane >> 2);
    int k0 = kc * 16 + (lane & 3) * 2;
    float v0, v1, v8, v9;
    if (proj < 4) {
        const float* Wp = (proj == 0) ? qp : (proj == 1) ? kp
                         : (proj == 2) ? vp : gp;
        int base = (n >> 5) * 8192 + (n & 31);
        v0 = Wp[base + k0 * 32];
        v1 = Wp[base + (k0 + 1) * 32];
        v8 = Wp[base + (k0 + 8) * 32];
        v9 = Wp[base + (k0 + 9) * 32];
    } else {
        v0 = ow[k0 * 256 + n];
        v1 = ow[(k0 + 1) * 256 + n];
        v8 = ow[(k0 + 8) * 256 + n];
        v9 = ow[(k0 + 9) * 256 + n];
    }
    uint32_t ph0, pl0, ph1, pl1;
    packhl2(v0, v1, ph0, pl0);
    packhl2(v8, v9, ph1, pl1);
    g_wf[((proj * 32 + n8t) * 16 + kc) * 32 + lane] =
        make_uint4(ph0, ph1, pl0, pl1);
}

// ==== Kernel 2: QKVG; fused LN1 A-staging; B via fragment LDG.128 ==========
#define QSCALE 0.2550868099f
#define QK_AHI 0
#define QK_ALO (128*264*2)                 // 67584
#define QKVG_SMEM (2*128*264*2)            // 135168

__global__ void __launch_bounds__(512, 1)
k_qkvg(const float* __restrict__ x, const float* __restrict__ gam,
       const float* __restrict__ bet) {
    extern __shared__ char smq[];
    __nv_bfloat16* Ahi = (__nv_bfloat16*)(smq + QK_AHI);
    __nv_bfloat16* Alo = (__nv_bfloat16*)(smq + QK_ALO);
    uint32_t ahi_b = smem_u32(Ahi), alo_b = smem_u32(Alo);

    int tid = threadIdx.x;
    int wid = tid >> 5, lane = tid & 31;
    int wm = wid & 3, wn = wid >> 2;       // 4 m-slices (32 rows) x 4 n-slices (32)
    int m0 = blockIdx.x * 128;

    // ---- stage A with fused LayerNorm: warp w handles rows w*8..w*8+7 ----
    {
        float4 gm0 = *(const float4*)&gam[lane * 8];
        float4 gm1 = *(const float4*)&gam[lane * 8 + 4];
        float4 bt0 = *(const float4*)&bet[lane * 8];
        float4 bt1 = *(const float4*)&bet[lane * 8 + 4];
#pragma unroll
        for (int r = 0; r < 8; r++) {
            int row = wid * 8 + r;
            const float* xr = x + (size_t)(m0 + row) * 256 + lane * 8;
            float4 v0 = *(const float4*)xr;
            float4 v1 = *(const float4*)(xr + 4);
            float s = v0.x + v0.y + v0.z + v0.w + v1.x + v1.y + v1.z + v1.w;
            s = warpSum(s);
            float mu = s * (1.f / 256.f);
            float d[8] = {v0.x - mu, v0.y - mu, v0.z - mu, v0.w - mu,
                          v1.x - mu, v1.y - mu, v1.z - mu, v1.w - mu};
            float vs = 0.f;
#pragma unroll
            for (int i = 0; i < 8; i++) vs += d[i] * d[i];
            vs = warpSum(vs);
            float rs = rsqrtf(vs * (1.f / 256.f) + 1e-6f);
            float o[8];
            o[0] = d[0] * rs * gm0.x + bt0.x;
            o[1] = d[1] * rs * gm0.y + bt0.y;
            o[2] = d[2] * rs * gm0.z + bt0.z;
            o[3] = d[3] * rs * gm0.w + bt0.w;
            o[4] = d[4] * rs * gm1.x + bt1.x;
            o[5] = d[5] * rs * gm1.y + bt1.y;
            o[6] = d[6] * rs * gm1.z + bt1.z;
            o[7] = d[7] * rs * gm1.w + bt1.w;
            uint32_t ph[4], pl[4];
#pragma unroll
            for (int i = 0; i < 4; i++) packhl2(o[i*2], o[i*2+1], ph[i], pl[i]);
            *(uint4*)&Ahi[row * 264 + lane * 8] = *(uint4*)ph;
            *(uint4*)&Alo[row * 264 + lane * 8] = *(uint4*)pl;
        }
    }
    __syncthreads();   // the ONLY block barrier

    int a_row = lane & 15;
    int a_kof = (lane >> 4) * 8;
    int fr = lane >> 2, fc = lane & 3;

    for (int nt = 0; nt < 8; nt++) {
        int proj = nt >> 1;
        int nin = (nt & 1) * 128;
        int n8b = proj * 32 + (nt & 1) * 16 + wn * 4;

        float acc[2][4][4];
#pragma unroll
        for (int mt = 0; mt < 2; mt++)
#pragma unroll
            for (int j = 0; j < 4; j++)
#pragma unroll
                for (int c = 0; c < 4; c++) acc[mt][j][c] = 0.f;

#pragma unroll 2
        for (int kc = 0; kc < 16; kc++) {
            uint4 bf[4];
#pragma unroll
            for (int j = 0; j < 4; j++)
                bf[j] = g_wf[((n8b + j) * 16 + kc) * 32 + lane];
            uint32_t ah[2][4], al[2][4];
#pragma unroll
            for (int mt = 0; mt < 2; mt++) {
                uint32_t off = (uint32_t)((wm * 32 + mt * 16 + a_row) * 264
                                          + kc * 16 + a_kof) * 2;
                ldsm4(ah[mt][0], ah[mt][1], ah[mt][2], ah[mt][3], ahi_b + off);
                ldsm4(al[mt][0], al[mt][1], al[mt][2], al[mt][3], alo_b + off);
            }
#pragma unroll
            for (int mt = 0; mt < 2; mt++)
#pragma unroll
                for (int j = 0; j < 4; j++) {
                    uint32_t bh[2] = {bf[j].x, bf[j].y};
                    uint32_t bl[2] = {bf[j].z, bf[j].w};
                    mma16816(acc[mt][j], ah[mt], bh);
                    mma16816(acc[mt][j], ah[mt], bl);
                    mma16816(acc[mt][j], al[mt], bh);
                }
        }

        if (proj == 0) {
#pragma unroll
            for (int mt = 0; mt < 2; mt++)
#pragma unroll
                for (int j = 0; j < 4; j++)
#pragma unroll
                    for (int c = 0; c < 4; c++) acc[mt][j][c] *= QSCALE;
        }

        __nv_bfloat16* Oh = (proj == 0) ? g_qh : (proj == 1) ? g_kh : g_vh;
        __nv_bfloat16* Ol = (proj == 0) ? g_ql : (proj == 1) ? g_kl : g_vl;
        bool isG = (proj == 3);
#pragma unroll
        for (int mt = 0; mt < 2; mt++) {
            int m = m0 + wm * 32 + mt * 16 + fr;
            int b1 = m / Ss, s1 = m - b1 * Ss;
            int m2 = m + 8;
            int b2 = m2 / Ss, s2 = m2 - b2 * Ss;
#pragma unroll
            for (int j = 0; j < 4; j++) {
                int n = nin + wn * 32 + j * 8 + fc * 2;
                int h = n >> 5, e = n & 31;
                size_t i1 = (((size_t)(b1 * Hh + h)) * Ss + s1) * Ee + e;
                size_t i2 = (((size_t)(b2 * Hh + h)) * Ss + s2) * Ee + e;
                if (isG) {
                    *(float2*)&g_g[i1] = make_float2(acc[mt][j][0], acc[mt][j][1]);
                    *(float2*)&g_g[i2] = make_float2(acc[mt][j][2], acc[mt][j][3]);
                } else {
                    uint32_t h1, l1, h2, l2;
                    packhl2(acc[mt][j][0], acc[mt][j][1], h1, l1);
                    packhl2(acc[mt][j][2], acc[mt][j][3], h2, l2);
                    *(uint32_t*)&Oh[i1] = h1;
                    *(uint32_t*)&Ol[i1] = l1;
                    *(uint32_t*)&Oh[i2] = h2;
                    *(uint32_t*)&Ol[i2] = l2;
                }
            }
        }
    }
}

// ==== Kernel 3: attention; 2 groups, Q via LDG, log2-domain softmax ========
#define KHI_OFF   0
#define KLO_OFF   33280
#define VH_OFF    66560
#define VL_OFF    99840
#define CSH_OFF   133120
#define RED_OFF   134784
#define OP_OFF    136832
#define ATTN_SMEM 169600

__global__ void __launch_bounds__(512, 1)
k_attn(const float* __restrict__ pmask, const float* __restrict__ mmask) {
    extern __shared__ char smc[];
    __nv_bfloat16* khi = (__nv_bfloat16*)(smc + KHI_OFF);
    __nv_bfloat16* klo = (__nv_bfloat16*)(smc + KLO_OFF);
    __nv_bfloat16* v_h = (__nv_bfloat16*)(smc + VH_OFF);
    __nv_bfloat16* v_l = (__nv_bfloat16*)(smc + VL_OFF);
    float*         c_sh = (float*)(smc + CSH_OFF);
    float*         red  = (float*)(smc + RED_OFF);
    float*         opart = (float*)(smc + OP_OFF);

    uint32_t khi_b = smem_u32(khi), klo_b = smem_u32(klo);
    uint32_t vh_b = smem_u32(v_h), vl_b = smem_u32(v_l);

    int tid = threadIdx.x;
    int lane = tid & 31;
    int bh = blockIdx.x;
    int h = bh & 7, b = bh >> 3;
    size_t baseBH = (size_t)(b * Hh + h) * Ss;

    for (int i = tid; i < Ss * 4; i += 512) {
        int y = i >> 2, q = i & 3;
        size_t src = (baseBH + y) * Ee + q * 8;
        *(uint4*)&khi[y * 40 + q * 8] = *(const uint4*)&g_kh[src];
        *(uint4*)&klo[y * 40 + q * 8] = *(const uint4*)&g_kl[src];
        *(uint4*)&v_h[y * 40 + q * 8] = *(const uint4*)&g_vh[src];
        *(uint4*)&v_l[y * 40 + q * 8] = *(const uint4*)&g_vl[src];
    }
    for (int i = tid; i < Ss; i += 512) {
        float val = (i < Nn) ? pmask[b * Nn + i] : mmask[b * Mm + (i - Nn)];
        c_sh[i] = (val == -2.0f) ? 0.f : 1.f;
    }
    __syncthreads();

    const float BIGL = 1.0e9f;
    int grp = tid >> 8;
    int wg = (tid >> 5) & 7;
    int mh = (wg >> 2) & 1;
    int nq = wg & 3;
    int nbase = nq * 104;
    int gtid = tid & 255;

    int b_row = ((lane >> 4) & 1) * 8 + (lane & 7);
    int b_kof = ((lane >> 3) & 1) * 8;
    int fr = lane >> 2, fc = lane & 3;
    int lx1 = mh * 16 + fr;
    int lx2 = lx1 + 8;

    float* redg = red + grp * 256;
    float* opg  = opart + grp * 4096;
    int bar_id = grp + 1;

    for (int t = grp; t < 13; t += 2) {
        int x0 = t * 32;

        uint32_t qah[2][4], qal[2][4];
        {
            const __nv_bfloat16* ph = g_qh + (baseBH + x0 + lx1) * 32;
            const __nv_bfloat16* pl = g_ql + (baseBH + x0 + lx1) * 32;
#pragma unroll
            for (int ks = 0; ks < 2; ks++) {
                int kk = ks * 16 + fc * 2;
                qah[ks][0] = *(const uint32_t*)&ph[kk];
                qah[ks][1] = *(const uint32_t*)&ph[256 + kk];
                qah[ks][2] = *(const uint32_t*)&ph[kk + 8];
                qah[ks][3] = *(const uint32_t*)&ph[256 + kk + 8];
                qal[ks][0] = *(const uint32_t*)&pl[kk];
                qal[ks][1] = *(const uint32_t*)&pl[256 + kk];
                qal[ks][2] = *(const uint32_t*)&pl[kk + 8];
                qal[ks][3] = *(const uint32_t*)&pl[256 + kk + 8];
            }
        }

        float acc[13][4];
#pragma unroll
        for (int t2 = 0; t2 < 13; t2++)
#pragma unroll
            for (int c = 0; c < 4; c++) acc[t2][c] = 0.f;

#pragma unroll
        for (int ks = 0; ks < 2; ks++) {
            int kk = ks * 16;
#pragma unroll
            for (int jp = 0; jp < 6; jp++) {
                uint32_t bh2[4], bl2[4];
                uint32_t off = (uint32_t)((nbase + jp * 16 + b_row) * 40
                                          + kk + b_kof) * 2;
                ldsm4(bh2[0], bh2[1], bh2[2], bh2[3], khi_b + off);
                ldsm4(bl2[0], bl2[1], bl2[2], bl2[3], klo_b + off);
                mma16816(acc[jp*2],   qah[ks], &bh2[0]);
                mma16816(acc[jp*2],   qah[ks], &bl2[0]);
                mma16816(acc[jp*2],   qal[ks], &bh2[0]);
                mma16816(acc[jp*2+1], qah[ks], &bh2[2]);
                mma16816(acc[jp*2+1], qah[ks], &bl2[2]);
                mma16816(acc[jp*2+1], qal[ks], &bh2[2]);
            }
            {
                uint32_t bh1[2], bl1[2];
                uint32_t off = (uint32_t)((nbase + 96 + (lane & 7)) * 40 + kk
                                          + 8 * ((lane >> 3) & 1)) * 2;
                ldsm2(bh1[0], bh1[1], khi_b + off);
                ldsm2(bl1[0], bl1[1], klo_b + off);
                mma16816(acc[12], qah[ks], bh1);
                mma16816(acc[12], qah[ks], bl1);
                mma16816(acc[12], qal[ks], bh1);
            }
        }

        bool xIsP = (t == 0);
        float cx1 = c_sh[x0 + lx1];
        float cx2 = c_sh[x0 + lx2];
#pragma unroll
        for (int t2 = 0; t2 < 13; t2++) {
            int ybase = nbase + t2 * 8;
            int yc = ybase + fc * 2;
            bool cross = (xIsP != (ybase < Nn));
            float cy0 = c_sh[yc], cy1 = c_sh[yc + 1];
            float by0 = cross ? fmaf(cy0, BIGL, -BIGL) : -BIGL;
            float by1 = cross ? fmaf(cy1, BIGL, -BIGL) : -BIGL;
            acc[t2][0] += by0;
            acc[t2][1] += by1;
            acc[t2][2] += by0;
            acc[t2][3] += by1;
        }

        float m1 = -3.0e38f, m2 = -3.0e38f;
#pragma unroll
        for (int t2 = 0; t2 < 13; t2++) {
            m1 = fmaxf(m1, fmaxf(acc[t2][0], acc[t2][1]));
            m2 = fmaxf(m2, fmaxf(acc[t2][2], acc[t2][3]));
        }
#pragma unroll
        for (int o = 1; o <= 2; o <<= 1) {
            m1 = fmaxf(m1, __shfl_xor_sync(0xffffffffu, m1, o));
            m2 = fmaxf(m2, __shfl_xor_sync(0xffffffffu, m2, o));
        }
        float s1 = 0.f, s2 = 0.f;
#pragma unroll
        for (int t2 = 0; t2 < 13; t2++) {
            acc[t2][0] = ex2f(acc[t2][0] - m1);
            acc[t2][1] = ex2f(acc[t2][1] - m1);
            acc[t2][2] = ex2f(acc[t2][2] - m2);
            acc[t2][3] = ex2f(acc[t2][3] - m2);
            s1 += acc[t2][0] + acc[t2][1];
            s2 += acc[t2][2] + acc[t2][3];
        }
#pragma unroll
        for (int o = 1; o <= 2; o <<= 1) {
            s1 += __shfl_xor_sync(0xffffffffu, s1, o);
            s2 += __shfl_xor_sync(0xffffffffu, s2, o);
        }
        if (fc == 0) {
            redg[lx1 * 8 + nq * 2]     = m1;
            redg[lx1 * 8 + nq * 2 + 1] = s1;
            redg[lx2 * 8 + nq * 2]     = m2;
            redg[lx2 * 8 + nq * 2 + 1] = s2;
        }
        asm volatile("bar.sync %0, %1;" :: "r"(bar_id), "r"(256) : "memory");
        float f1, f2;
        {
            float M1 = -3.0e38f, M2 = -3.0e38f;
#pragma unroll
            for (int q = 0; q < 4; q++) {
                M1 = fmaxf(M1, redg[lx1 * 8 + q * 2]);
                M2 = fmaxf(M2, redg[lx2 * 8 + q * 2]);
            }
            float S1 = 0.f, S2 = 0.f;
#pragma unroll
            for (int q = 0; q < 4; q++) {
                S1 += redg[lx1 * 8 + q * 2 + 1] * ex2f(redg[lx1 * 8 + q * 2] - M1);
                S2 += redg[lx2 * 8 + q * 2 + 1] * ex2f(redg[lx2 * 8 + q * 2] - M2);
            }
            f1 = cx1 * ex2f(m1 - M1) / S1;
            f2 = cx2 * ex2f(m2 - M2) / S2;
        }

        {
            float o[4][4];
#pragma unroll
            for (int eg = 0; eg < 4; eg++)
#pragma unroll
                for (int c = 0; c < 4; c++) o[eg][c] = 0.f;

#pragma unroll
            for (int g = 0; g < 3; g++) {
                uint32_t Ah0[4], Al0[4], Ah1[4], Al1[4];
                {
                    int ta = 4 * g, tb = 4 * g + 1;
                    packhl2(acc[ta][0] * f1, acc[ta][1] * f1, Ah0[0], Al0[0]);
                    packhl2(acc[ta][2] * f2, acc[ta][3] * f2, Ah0[1], Al0[1]);
                    packhl2(acc[tb][0] * f1, acc[tb][1] * f1, Ah0[2], Al0[2]);
                    packhl2(acc[tb][2] * f2, acc[tb][3] * f2, Ah0[3], Al0[3]);
                    int tc = 4 * g + 2, td = 4 * g + 3;
                    packhl2(acc[tc][0] * f1, acc[tc][1] * f1, Ah1[0], Al1[0]);
                    packhl2(acc[tc][2] * f2, acc[tc][3] * f2, Ah1[1], Al1[1]);
                    packhl2(acc[td][0] * f1, acc[td][1] * f1, Ah1[2], Al1[2]);
                    packhl2(acc[td][2] * f2, acc[td][3] * f2, Ah1[3], Al1[3]);
                }
#pragma unroll
                for (int eg = 0; eg < 4; eg++) {
                    uint32_t bh4[4], bl4[4];
                    uint32_t offB = (uint32_t)((nbase + g * 32 + lane) * 40
                                               + eg * 8) * 2;
                    ldsm4t(bh4[0], bh4[1], bh4[2], bh4[3], vh_b + offB);
                    ldsm4t(bl4[0], bl4[1], bl4[2], bl4[3], vl_b + offB);
                    mma16816(o[eg], Ah0, &bh4[0]);
                    mma16816(o[eg], Ah0, &bl4[0]);
                    mma16816(o[eg], Al0, &bh4[0]);
                    mma16816(o[eg], Ah1, &bh4[2]);
                    mma16816(o[eg], Ah1, &bl4[2]);
                    mma16816(o[eg], Al1, &bh4[2]);
                }
            }
            {
                uint32_t Ath[2], Atl[2];
                packhl2(acc[12][0] * f1, acc[12][1] * f1, Ath[0], Atl[0]);
                packhl2(acc[12][2] * f2, acc[12][3] * f2, Ath[1], Atl[1]);
                uint32_t bh4[4], bl4[4];
                uint32_t offT = (uint32_t)((nbase + 96 + (lane & 7)) * 40
                                           + (lane >> 3) * 8) * 2;
                ldsm4t(bh4[0], bh4[1], bh4[2], bh4[3], vh_b + offT);
                ldsm4t(bl4[0], bl4[1], bl4[2], bl4[3], vl_b + offT);
#pragma unroll
                for (int eg = 0; eg < 4; eg++) {
                    mma1688(o[eg], Ath, bh4[eg]);
                    mma1688(o[eg], Ath, bl4[eg]);
                    mma1688(o[eg], Atl, bh4[eg]);
                }
            }
            float* op = opg + nq * 1024;
#pragma unroll
            for (int eg = 0; eg < 4; eg++) {
                int e = eg * 8 + fc * 2;
                *(float2*)&op[lx1 * 32 + e] = make_float2(o[eg][0], o[eg][1]);
                *(float2*)&op[lx2 * 32 + e] = make_float2(o[eg][2], o[eg][3]);
            }
        }
        asm volatile("bar.sync %0, %1;" :: "r"(bar_id), "r"(256) : "memory");

        // ---- reduce over nq + gate + store (fragment-packed g_aof) ----
#pragma unroll
        for (int it = 0; it < 2; it++) {
            int idx = gtid + it * 256;
            int row = idx >> 4;
            int e = (idx & 15) * 2;
            const float* op = opg + row * 32 + e;
            float sum0 = op[0] + op[1024] + op[2048] + op[3072];
            float sum1 = op[1] + op[1025] + op[2049] + op[3073];
            int xs_ = x0 + row;
            float2 gv = *(const float2*)&g_g[(baseBH + xs_) * Ee + e];
            float sg0 = 1.f / (1.f + __expf(-gv.x));
            float sg1 = 1.f / (1.f + __expf(-gv.y));
            float o0 = sum0 * sg0;
            float o1 = sum1 * sg1;
            uint32_t oh, ol;
            packhl2(o0, o1, oh, ol);
            // fragment-packed indices
            int grow = b * Ss + xs_;
            int m8t = grow >> 3;
            int kglob = h * 32 + e;
            int kc = kglob >> 4;
            int p = (kglob & 15) >> 1;
            int lane2 = (grow & 7) * 4 + (p & 3);
            int slot = p >> 2;
            uint32_t* dst = (uint32_t*)g_aof
                          + ((size_t)(m8t * 16 + kc) * 32 + lane2) * 4;
            dst[slot]     = oh;
            dst[slot + 2] = ol;
        }
    }
}

// ==== Kernel 4: output proj + LN2; A and B fragments via LDG.128 ===========
#define OYS_OFF 0                             // 64*264*4 = 67584
#define OMU_OFF 67584
#define ORS_OFF 67840
#define OLN_SMEM 68096

__global__ void __launch_bounds__(512)
k_outln(const float* __restrict__ bias, const float* __restrict__ g2,
        const float* __restrict__ b2, float* __restrict__ out) {
    extern __shared__ char smo[];
    float* ys  = (float*)(smo + OYS_OFF);
    float* mus = (float*)(smo + OMU_OFF);
    float* rss = (float*)(smo + ORS_OFF);

    int tid = threadIdx.x;
    int wid = tid >> 5, lane = tid & 31;
    int mh = wid & 3, nq = wid >> 2;          // 4 m-slices(16) x 4 n-quarters(64)
    int r0 = blockIdx.x * 64;
    int fr = lane >> 2, fc = lane & 3;
    int t0 = (r0 >> 3) + mh * 2;

    float acc[8][4];
#pragma unroll
    for (int j = 0; j < 8; j++)
#pragma unroll
        for (int c = 0; c < 4; c++) acc[j][c] = 0.f;

#pragma unroll 2
    for (int kc = 0; kc < 16; kc++) {
        uint4 ea = g_aof[((size_t)(t0 * 16 + kc)) * 32 + lane];
        uint4 eb = g_aof[((size_t)((t0 + 1) * 16 + kc)) * 32 + lane];
        uint32_t Ahf[4] = {ea.x, eb.x, ea.y, eb.y};
        uint32_t Alf[4] = {ea.z, eb.z, ea.w, eb.w};
#pragma unroll
        for (int jp = 0; jp < 8; jp++) {
            uint4 bf = g_wf[((4 * 32 + nq * 8 + jp) * 16 + kc) * 32 + lane];
            uint32_t bh[2] = {bf.x, bf.y};
            uint32_t bl[2] = {bf.z, bf.w};
            mma16816(acc[jp], Ahf, bh);
            mma16816(acc[jp], Ahf, bl);
            mma16816(acc[jp], Alf, bh);
        }
    }

    int lx1 = mh * 16 + fr;
    int lx2 = lx1 + 8;
#pragma unroll
    for (int j = 0; j < 8; j++) {
        int n = nq * 64 + j * 8 + fc * 2;
        float b0 = bias[n], b1 = bias[n + 1];
        ys[lx1 * 264 + n]     = acc[j][0] + b0;
        ys[lx1 * 264 + n + 1] = acc[j][1] + b1;
        ys[lx2 * 264 + n]     = acc[j][2] + b0;
        ys[lx2 * 264 + n + 1] = acc[j][3] + b1;
    }
    __syncthreads();

#pragma unroll
    for (int rr = 0; rr < 4; rr++) {
        int xr = wid + rr * 16;
        const float* row = ys + xr * 264;
        float s = 0.f;
#pragma unroll
        for (int j = 0; j < 8; j++) s += row[lane + 32 * j];
        s = warpSum(s);
        float mu = s * (1.f / 256.f);
        float vs = 0.f;
#pragma unroll
        for (int j = 0; j < 8; j++) {
            float d = row[lane + 32 * j] - mu;
            vs += d * d;
        }
        vs = warpSum(vs);
        if (lane == 0) { mus[xr] = mu; rss[xr] = rsqrtf(vs * (1.f / 256.f) + 1e-6f); }
    }
    __syncthreads();

    int cc = tid & 255;
    int rh = tid >> 8;
    float gt = g2[cc], bt = b2[cc];
#pragma unroll 4
    for (int r = rh * 32; r < rh * 32 + 32; r++) {
        out[(size_t)(r0 + r) * 256 + cc] =
            (ys[r * 264 + cc] - mus[r]) * rss[r] * gt + bt;
    }
}

// ===========================================================================
extern "C" void kernel_launch(void* const* d_in, const int* in_sizes, int n_in,
                              void* d_out, int out_size) {
    const float* x   = (const float*)d_in[0];
    const float* pm  = (const float*)d_in[1];
    const float* mm  = (const float*)d_in[2];
    const float* qp  = (const float*)d_in[3];
    const float* kp  = (const float*)d_in[4];
    const float* vp  = (const float*)d_in[5];
    const float* gp  = (const float*)d_in[6];
    const float* ow  = (const float*)d_in[7];
    const float* ob  = (const float*)d_in[8];
    const float* l1g = (const float*)d_in[9];
    const float* l1b = (const float*)d_in[10];
    const float* l2g = (const float*)d_in[11];
    const float* l2b = (const float*)d_in[12];
    float* out = (float*)d_out;

    cudaFuncSetAttribute(k_qkvg, cudaFuncAttributeMaxDynamicSharedMemorySize,
                         QKVG_SMEM);
    cudaFuncSetAttribute(k_attn, cudaFuncAttributeMaxDynamicSharedMemorySize,
                         ATTN_SMEM);
    cudaFuncSetAttribute(k_outln, cudaFuncAttributeMaxDynamicSharedMemorySize,
                         OLN_SMEM);

    k_wconv<<<dim3(32, 5), 512>>>(qp, kp, vp, gp, ow);
    k_qkvg <<<416, 512, QKVG_SMEM>>>(x, l1g, l1b);
    k_attn <<<Bb * Hh, 512, ATTN_SMEM>>>(pm, mm);
    k_outln<<<BSs / 64, 512, OLN_SMEM>>>(ob, l2g, l2b, out);
}